// round 2
// baseline (speedup 1.0000x reference)
#include <cuda_runtime.h>
#include <math.h>

#define NN 10000
#define NE 160000

// ---- scratch (static device globals; no allocation) ----
__device__ float g_deg[NN];
__device__ float g_dis[NN];
__device__ float g_w[NE];
__device__ float g_X3[NN * 768];      // packed [tx0|tx1|tx2], max 3*256 per node
__device__ float g_actA[NN * 512];
__device__ float g_actB[NN * 512];

// ---------------- small kernels ----------------
__global__ void k_zero(float* p, int n) {
    int i = blockIdx.x * blockDim.x + threadIdx.x;
    if (i < n) p[i] = 0.f;
}

__global__ void k_deg(const int* __restrict__ ei, float* __restrict__ deg) {
    int e = blockIdx.x * blockDim.x + threadIdx.x;
    if (e < NE) atomicAdd(&deg[ei[e]], 1.f);
}

__global__ void k_dis(const float* __restrict__ deg, float* __restrict__ dis) {
    int i = blockIdx.x * blockDim.x + threadIdx.x;
    if (i < NN) {
        float d = deg[i];
        dis[i] = (d > 0.f) ? rsqrtf(d) : 0.f;
    }
}

__global__ void k_w(const int* __restrict__ ei, const float* __restrict__ dis,
                    float* __restrict__ w) {
    int e = blockIdx.x * blockDim.x + threadIdx.x;
    if (e < NE) {
        int r = ei[e];
        int c = ei[NE + e];
        w[e] = -dis[r] * dis[c];
    }
}

// pack: X3[n] = [ x(n) | 0 | -x(n) ]  (slot1 filled by prop1, slot2 becomes 2*prop(tx1)-x)
__global__ void k_pack(const float* __restrict__ x, float* __restrict__ X3,
                       int Fin, int total) {
    int i = blockIdx.x * blockDim.x + threadIdx.x;
    if (i < total) {
        int n = i / Fin;
        int f = i - n * Fin;
        float v = x[i];
        float* row = X3 + (size_t)n * 3 * Fin;
        row[f] = v;
        row[Fin + f] = 0.f;
        row[2 * Fin + f] = -v;
    }
}

// prop1: tx1[col] += w[e] * x[row]   (into X3 slot 1)
__global__ void k_prop1(const int* __restrict__ ei, const float* __restrict__ w,
                        const float* __restrict__ x, float* __restrict__ X3, int Fin) {
    long long i = (long long)blockIdx.x * blockDim.x + threadIdx.x;
    long long tot = (long long)NE * Fin;
    if (i < tot) {
        int e = (int)(i / Fin);
        int f = (int)(i - (long long)e * Fin);
        int r = ei[e];
        int c = ei[NE + e];
        atomicAdd(&X3[(size_t)c * 3 * Fin + Fin + f], w[e] * x[(size_t)r * Fin + f]);
    }
}

// prop2: tx2[col] += 2 * w[e] * tx1[row]  (into X3 slot 2; already init'd to -x)
__global__ void k_prop2(const int* __restrict__ ei, const float* __restrict__ w,
                        float* __restrict__ X3, int Fin) {
    long long i = (long long)blockIdx.x * blockDim.x + threadIdx.x;
    long long tot = (long long)NE * Fin;
    if (i < tot) {
        int e = (int)(i / Fin);
        int f = (int)(i - (long long)e * Fin);
        int r = ei[e];
        int c = ei[NE + e];
        atomicAdd(&X3[(size_t)c * 3 * Fin + 2 * Fin + f],
                  2.f * w[e] * X3[(size_t)r * 3 * Fin + Fin + f]);
    }
}

// ---------------- GEMM: C[M,N](ldc) = A[M,K] @ B[K,N] + bias, optional relu ----------
// BM=BN=64, BK=16, 256 threads, 4x4 per thread.
__global__ void k_gemm(const float* __restrict__ A, const float* __restrict__ B,
                       const float* __restrict__ bias, float* __restrict__ C,
                       int M, int K, int N, int ldc, int relu) {
    __shared__ float As[16][68];   // padded to kill 64-stride bank conflicts on store
    __shared__ float Bs[16][64];

    int bm = blockIdx.y * 64;
    int bn = blockIdx.x * 64;
    int tid = threadIdx.x;
    int ty = tid >> 4;   // 0..15
    int tx = tid & 15;   // 0..15

    float acc[4][4];
#pragma unroll
    for (int i = 0; i < 4; i++)
#pragma unroll
        for (int j = 0; j < 4; j++) acc[i][j] = 0.f;

    for (int k0 = 0; k0 < K; k0 += 16) {
        // load A tile 64x16 (row-major global) -> As[k][m]
#pragma unroll
        for (int l = 0; l < 4; l++) {
            int lin = tid + l * 256;
            int i = lin >> 4;   // 0..63 (m)
            int j = lin & 15;   // 0..15 (k)
            int gm = bm + i;
            As[j][i] = (gm < M) ? A[(size_t)gm * K + k0 + j] : 0.f;
        }
        // load B tile 16x64 -> Bs[k][n]
#pragma unroll
        for (int l = 0; l < 4; l++) {
            int lin = tid + l * 256;
            int i = lin >> 6;   // 0..15 (k)
            int j = lin & 63;   // 0..63 (n)
            Bs[i][j] = B[(size_t)(k0 + i) * N + bn + j];
        }
        __syncthreads();

#pragma unroll
        for (int k = 0; k < 16; k++) {
            float a0 = As[k][ty * 4 + 0];
            float a1 = As[k][ty * 4 + 1];
            float a2 = As[k][ty * 4 + 2];
            float a3 = As[k][ty * 4 + 3];
            float b0 = Bs[k][tx * 4 + 0];
            float b1 = Bs[k][tx * 4 + 1];
            float b2 = Bs[k][tx * 4 + 2];
            float b3 = Bs[k][tx * 4 + 3];
            acc[0][0] += a0 * b0; acc[0][1] += a0 * b1; acc[0][2] += a0 * b2; acc[0][3] += a0 * b3;
            acc[1][0] += a1 * b0; acc[1][1] += a1 * b1; acc[1][2] += a1 * b2; acc[1][3] += a1 * b3;
            acc[2][0] += a2 * b0; acc[2][1] += a2 * b1; acc[2][2] += a2 * b2; acc[2][3] += a2 * b3;
            acc[3][0] += a3 * b0; acc[3][1] += a3 * b1; acc[3][2] += a3 * b2; acc[3][3] += a3 * b3;
        }
        __syncthreads();
    }

#pragma unroll
    for (int i = 0; i < 4; i++) {
        int gm = bm + ty * 4 + i;
        if (gm < M) {
#pragma unroll
            for (int j = 0; j < 4; j++) {
                int gn = bn + tx * 4 + j;
                float v = acc[i][j] + bias[gn];
                if (relu) v = fmaxf(v, 0.f);
                C[(size_t)gm * ldc + gn] = v;
            }
        }
    }
}

// ---------------- host orchestration ----------------
static void run_layer(const int* ei, const float* wbuf, float* X3,
                      const float* x, int Fin, int Fout,
                      const float* W, const float* b, float* y) {
    int totp = NN * Fin;
    k_pack<<<(totp + 255) / 256, 256>>>(x, X3, Fin, totp);
    long long tote = (long long)NE * Fin;
    int blks = (int)((tote + 255) / 256);
    k_prop1<<<blks, 256>>>(ei, wbuf, x, X3, Fin);
    k_prop2<<<blks, 256>>>(ei, wbuf, X3, Fin);
    dim3 grid(Fout / 64, (NN + 63) / 64);
    k_gemm<<<grid, 256>>>(X3, W, b, y, NN, 3 * Fin, Fout, Fout, 1);
}

extern "C" void kernel_launch(void* const* d_in, const int* in_sizes, int n_in,
                              void* d_out, int out_size) {
    const float* v      = (const float*)d_in[0];
    const int* ei       = (const int*)d_in[1];   // int32: JAX x64 disabled canonicalizes int64->int32
    const float* W1 = (const float*)d_in[2];
    const float* b1 = (const float*)d_in[3];
    const float* W2 = (const float*)d_in[4];
    const float* b2 = (const float*)d_in[5];
    const float* W3 = (const float*)d_in[6];
    const float* b3 = (const float*)d_in[7];
    const float* Wmu  = (const float*)d_in[8];
    const float* bmu  = (const float*)d_in[9];
    const float* Wstd = (const float*)d_in[10];
    const float* bstd = (const float*)d_in[11];
    float* out = (float*)d_out;

    float *deg, *dis, *wbuf, *X3, *actA, *actB;
    cudaGetSymbolAddress((void**)&deg,  g_deg);
    cudaGetSymbolAddress((void**)&dis,  g_dis);
    cudaGetSymbolAddress((void**)&wbuf, g_w);
    cudaGetSymbolAddress((void**)&X3,   g_X3);
    cudaGetSymbolAddress((void**)&actA, g_actA);
    cudaGetSymbolAddress((void**)&actB, g_actB);

    // normalization weights
    k_zero<<<(NN + 255) / 256, 256>>>(deg, NN);
    k_deg<<<(NE + 255) / 256, 256>>>(ei, deg);
    k_dis<<<(NN + 255) / 256, 256>>>(deg, dis);
    k_w<<<(NE + 255) / 256, 256>>>(ei, dis, wbuf);

    // 3 ChebConv(K=3) + ReLU layers
    run_layer(ei, wbuf, X3, v,    128, 128, W1, b1, actA);
    run_layer(ei, wbuf, X3, actA, 128, 256, W2, b2, actB);
    run_layer(ei, wbuf, X3, actB, 256, 512, W3, b3, actA);

    // heads: mu then std, concatenated in d_out
    dim3 ghead(256 / 64, (NN + 63) / 64);
    k_gemm<<<ghead, 256>>>(actA, Wmu,  bmu,  out,                    NN, 512, 256, 256, 0);
    k_gemm<<<ghead, 256>>>(actA, Wstd, bstd, out + (size_t)NN * 256, NN, 512, 256, 256, 0);

    (void)in_sizes; (void)n_in; (void)out_size;
}

// round 4
// speedup vs baseline: 1.0807x; 1.0807x over previous
#include <cuda_runtime.h>
#include <cuda_bf16.h>
#include <math.h>
#include <stdint.h>

#define NN 10000
#define NE 160000

// ---- scratch (static device globals; no allocation) ----
__device__ float g_deg[NN];
__device__ float g_dis[NN];
__device__ float g_w[NE];
__device__ float g_X3[NN * 768];              // packed [tx0|tx1|tx2] fp32
__device__ float g_actA[NN * 512];
__device__ float g_actB[NN * 512];
__device__ __nv_bfloat16 g_Abig[NN * 2304];   // [hi|lo|hi] split, K''max = 2304
__device__ __nv_bfloat16 g_Bbig[512 * 2304];  // transposed+split weights [N, K'']

__device__ __forceinline__ uint32_t smem_u32(const void* p) {
    uint32_t a;
    asm("{ .reg .u64 t; cvta.to.shared.u64 t, %1; cvt.u32.u64 %0, t; }" : "=r"(a) : "l"(p));
    return a;
}

// =============== small kernels ===============
__global__ void k_zero(float* p, int n) {
    int i = blockIdx.x * blockDim.x + threadIdx.x;
    if (i < n) p[i] = 0.f;
}
__global__ void k_deg(const int* __restrict__ ei, float* __restrict__ deg) {
    int e = blockIdx.x * blockDim.x + threadIdx.x;
    if (e < NE) atomicAdd(&deg[ei[e]], 1.f);
}
__global__ void k_dis(const float* __restrict__ deg, float* __restrict__ dis) {
    int i = blockIdx.x * blockDim.x + threadIdx.x;
    if (i < NN) {
        float d = deg[i];
        dis[i] = (d > 0.f) ? rsqrtf(d) : 0.f;
    }
}
__global__ void k_w(const int* __restrict__ ei, const float* __restrict__ dis,
                    float* __restrict__ w) {
    int e = blockIdx.x * blockDim.x + threadIdx.x;
    if (e < NE) w[e] = -dis[ei[e]] * dis[ei[NE + e]];
}

// pack: X3[n] = [ x(n) | 0 | -x(n) ]
__global__ void k_pack(const float* __restrict__ x, float* __restrict__ X3,
                       int Fin, int total) {
    int i = blockIdx.x * blockDim.x + threadIdx.x;
    if (i < total) {
        int n = i / Fin;
        int f = i - n * Fin;
        float v = x[i];
        float* row = X3 + (size_t)n * 3 * Fin;
        row[f] = v;
        row[Fin + f] = 0.f;
        row[2 * Fin + f] = -v;
    }
}
__global__ void k_prop1(const int* __restrict__ ei, const float* __restrict__ w,
                        const float* __restrict__ x, float* __restrict__ X3, int Fin) {
    long long i = (long long)blockIdx.x * blockDim.x + threadIdx.x;
    long long tot = (long long)NE * Fin;
    if (i < tot) {
        int e = (int)(i / Fin);
        int f = (int)(i - (long long)e * Fin);
        int r = ei[e];
        int c = ei[NE + e];
        atomicAdd(&X3[(size_t)c * 3 * Fin + Fin + f], w[e] * x[(size_t)r * Fin + f]);
    }
}
__global__ void k_prop2(const int* __restrict__ ei, const float* __restrict__ w,
                        float* __restrict__ X3, int Fin) {
    long long i = (long long)blockIdx.x * blockDim.x + threadIdx.x;
    long long tot = (long long)NE * Fin;
    if (i < tot) {
        int e = (int)(i / Fin);
        int f = (int)(i - (long long)e * Fin);
        int r = ei[e];
        int c = ei[NE + e];
        atomicAdd(&X3[(size_t)c * 3 * Fin + 2 * Fin + f],
                  2.f * w[e] * X3[(size_t)r * 3 * Fin + Fin + f]);
    }
}

// =============== bf16 split conversions ===============
__global__ void k_aconv(const float* __restrict__ X, __nv_bfloat16* __restrict__ A, int K) {
    long long i = (long long)blockIdx.x * blockDim.x + threadIdx.x;
    long long tot = (long long)NN * K;
    if (i < tot) {
        int n = (int)(i / K);
        int k = (int)(i - (long long)n * K);
        float x = X[i];
        __nv_bfloat16 hi = __float2bfloat16(x);
        __nv_bfloat16 lo = __float2bfloat16(x - __bfloat162float(hi));
        __nv_bfloat16* row = A + (size_t)n * 3 * K;
        row[k] = hi;
        row[K + k] = lo;
        row[2 * K + k] = hi;
    }
}
__global__ void k_wconv(const float* __restrict__ W, __nv_bfloat16* __restrict__ B,
                        int K, int N) {
    int i = blockIdx.x * blockDim.x + threadIdx.x;
    if (i < K * N) {
        int k = i / N;
        int n = i - k * N;
        float x = W[i];
        __nv_bfloat16 hi = __float2bfloat16(x);
        __nv_bfloat16 lo = __float2bfloat16(x - __bfloat162float(hi));
        __nv_bfloat16* row = B + (size_t)n * 3 * K;
        row[k] = hi;
        row[K + k] = hi;
        row[2 * K + k] = lo;
    }
}

// =============== mma.sync bf16 GEMM: C[M,N] = A[M,K''] @ B[N,K'']^T + bias ========
// CTA 128x128, BK=32, 256 threads (8 warps, 2x4), warp tile 64x32.
#define LDT 40   // padded smem stride in bf16 elems (80B rows -> conflict-free)

__device__ __forceinline__ void ldm_x4(uint32_t& r0, uint32_t& r1, uint32_t& r2, uint32_t& r3,
                                       uint32_t a) {
    asm volatile("ldmatrix.sync.aligned.m8n8.x4.shared.b16 {%0,%1,%2,%3}, [%4];"
                 : "=r"(r0), "=r"(r1), "=r"(r2), "=r"(r3) : "r"(a));
}
__device__ __forceinline__ void ldm_x2(uint32_t& r0, uint32_t& r1, uint32_t a) {
    asm volatile("ldmatrix.sync.aligned.m8n8.x2.shared.b16 {%0,%1}, [%2];"
                 : "=r"(r0), "=r"(r1) : "r"(a));
}
__device__ __forceinline__ void mma_bf16(float* c, const uint32_t* a, const uint32_t* b) {
    asm volatile(
        "mma.sync.aligned.m16n8k16.row.col.f32.bf16.bf16.f32 "
        "{%0,%1,%2,%3}, {%4,%5,%6,%7}, {%8,%9}, {%0,%1,%2,%3};"
        : "+f"(c[0]), "+f"(c[1]), "+f"(c[2]), "+f"(c[3])
        : "r"(a[0]), "r"(a[1]), "r"(a[2]), "r"(a[3]), "r"(b[0]), "r"(b[1]));
}
__device__ __forceinline__ void cp16(uint32_t dst, const void* src, int pred16) {
    asm volatile("cp.async.ca.shared.global [%0], [%1], 16, %2;"
                 :: "r"(dst), "l"(src), "r"(pred16) : "memory");
}

__global__ __launch_bounds__(256, 1) void k_mgemm(
    const __nv_bfloat16* __restrict__ A, const __nv_bfloat16* __restrict__ B,
    const float* __restrict__ bias, float* __restrict__ C,
    int M, int Kbig, int ldc, int relu)
{
    __shared__ __align__(16) __nv_bfloat16 sA[2][128 * LDT];
    __shared__ __align__(16) __nv_bfloat16 sB[2][128 * LDT];

    const int tid = threadIdx.x;
    const int wid = tid >> 5;
    const int lane = tid & 31;
    const int bm = blockIdx.y * 128;
    const int bn = blockIdx.x * 128;
    const int warp_m = (wid & 1) * 64;
    const int warp_n = (wid >> 1) * 32;

    float acc[4][4][4];
#pragma unroll
    for (int i = 0; i < 4; i++)
#pragma unroll
        for (int j = 0; j < 4; j++)
#pragma unroll
            for (int q = 0; q < 4; q++) acc[i][j][q] = 0.f;

    const uint32_t sA_base[2] = { smem_u32(sA[0]), smem_u32(sA[1]) };
    const uint32_t sB_base[2] = { smem_u32(sB[0]), smem_u32(sB[1]) };
    const int niter = Kbig >> 5;   // /32

    // loader indices: 512 16B-chunks per tile, 2 per thread
    const int lr = tid >> 1;            // row 0..127
    const int lc0 = (tid & 1) * 2;      // chunk 0/2  -> +1 for second

    auto issue = [&](int stage, int k0) {
#pragma unroll
        for (int h = 0; h < 2; h++) {
            int c = lc0 + h;             // 0..3 -> col = c*8 elems
            int gm = bm + lr;
            cp16(sA_base[stage] + (lr * LDT + c * 8) * 2,
                 A + (size_t)gm * Kbig + k0 + c * 8, gm < M ? 16 : 0);
            cp16(sB_base[stage] + (lr * LDT + c * 8) * 2,
                 B + (size_t)(bn + lr) * Kbig + k0 + c * 8, 16);
        }
        asm volatile("cp.async.commit_group;" ::: "memory");
    };

    issue(0, 0);
    for (int it = 0; it < niter; it++) {
        const int stage = it & 1;
        if (it + 1 < niter) {
            issue(stage ^ 1, (it + 1) << 5);
            asm volatile("cp.async.wait_group 1;" ::: "memory");
        } else {
            asm volatile("cp.async.wait_group 0;" ::: "memory");
        }
        __syncthreads();

#pragma unroll
        for (int ks = 0; ks < 2; ks++) {
            uint32_t af[4][4];
            uint32_t bf[4][2];
#pragma unroll
            for (int mf = 0; mf < 4; mf++) {
                uint32_t addr = sA_base[stage] +
                    ((warp_m + mf * 16 + (lane & 15)) * LDT + ks * 16 + (lane >> 4) * 8) * 2;
                ldm_x4(af[mf][0], af[mf][1], af[mf][2], af[mf][3], addr);
            }
#pragma unroll
            for (int nf = 0; nf < 4; nf++) {
                uint32_t addr = sB_base[stage] +
                    ((warp_n + nf * 8 + (lane & 7)) * LDT + ks * 16 + ((lane >> 3) & 1) * 8) * 2;
                ldm_x2(bf[nf][0], bf[nf][1], addr);
            }
#pragma unroll
            for (int mf = 0; mf < 4; mf++)
#pragma unroll
                for (int nf = 0; nf < 4; nf++)
                    mma_bf16(acc[mf][nf], af[mf], bf[nf]);
        }
        __syncthreads();   // protect stage before it gets re-issued next iter
    }

    // epilogue
#pragma unroll
    for (int mf = 0; mf < 4; mf++) {
#pragma unroll
        for (int nf = 0; nf < 4; nf++) {
            int row0 = bm + warp_m + mf * 16 + (lane >> 2);
            int col0 = bn + warp_n + nf * 8 + (lane & 3) * 2;
#pragma unroll
            for (int h = 0; h < 2; h++) {
                int row = row0 + h * 8;
                if (row < M) {
                    float v0 = acc[mf][nf][h * 2 + 0] + bias[col0];
                    float v1 = acc[mf][nf][h * 2 + 1] + bias[col0 + 1];
                    if (relu) { v0 = fmaxf(v0, 0.f); v1 = fmaxf(v1, 0.f); }
                    *(float2*)(C + (size_t)row * ldc + col0) = make_float2(v0, v1);
                }
            }
        }
    }
}

// =============== host orchestration ===============
static void run_gemm(const __nv_bfloat16* A, const float* W, __nv_bfloat16* Bbig,
                     const float* bias, float* C, int K, int N, int relu) {
    k_wconv<<<(K * N + 255) / 256, 256>>>(W, Bbig, K, N);
    dim3 grid(N / 128, (NN + 127) / 128);
    k_mgemm<<<grid, 256>>>(A, Bbig, bias, C, NN, 3 * K, N, relu);
}

static void run_layer(const int* ei, const float* wbuf, float* X3,
                      __nv_bfloat16* Abig, __nv_bfloat16* Bbig,
                      const float* x, int Fin, int Fout,
                      const float* W, const float* b, float* y) {
    int totp = NN * Fin;
    k_pack<<<(totp + 255) / 256, 256>>>(x, X3, Fin, totp);
    long long tote = (long long)NE * Fin;
    int blks = (int)((tote + 255) / 256);
    k_prop1<<<blks, 256>>>(ei, wbuf, x, X3, Fin);
    k_prop2<<<blks, 256>>>(ei, wbuf, X3, Fin);
    long long tota = (long long)NN * 3 * Fin;
    k_aconv<<<(int)((tota + 255) / 256), 256>>>(X3, Abig, 3 * Fin);
    run_gemm(Abig, W, Bbig, b, y, 3 * Fin, Fout, 1);
}

extern "C" void kernel_launch(void* const* d_in, const int* in_sizes, int n_in,
                              void* d_out, int out_size) {
    const float* v    = (const float*)d_in[0];
    const int* ei     = (const int*)d_in[1];
    const float* W1   = (const float*)d_in[2];
    const float* b1   = (const float*)d_in[3];
    const float* W2   = (const float*)d_in[4];
    const float* b2   = (const float*)d_in[5];
    const float* W3   = (const float*)d_in[6];
    const float* b3   = (const float*)d_in[7];
    const float* Wmu  = (const float*)d_in[8];
    const float* bmu  = (const float*)d_in[9];
    const float* Wstd = (const float*)d_in[10];
    const float* bstd = (const float*)d_in[11];
    float* out = (float*)d_out;

    float *deg, *dis, *wbuf, *X3, *actA, *actB;
    __nv_bfloat16 *Abig, *Bbig;
    cudaGetSymbolAddress((void**)&deg,  g_deg);
    cudaGetSymbolAddress((void**)&dis,  g_dis);
    cudaGetSymbolAddress((void**)&wbuf, g_w);
    cudaGetSymbolAddress((void**)&X3,   g_X3);
    cudaGetSymbolAddress((void**)&actA, g_actA);
    cudaGetSymbolAddress((void**)&actB, g_actB);
    cudaGetSymbolAddress((void**)&Abig, g_Abig);
    cudaGetSymbolAddress((void**)&Bbig, g_Bbig);

    // normalization weights
    k_zero<<<(NN + 255) / 256, 256>>>(deg, NN);
    k_deg<<<(NE + 255) / 256, 256>>>(ei, deg);
    k_dis<<<(NN + 255) / 256, 256>>>(deg, dis);
    k_w<<<(NE + 255) / 256, 256>>>(ei, dis, wbuf);

    // 3 ChebConv(K=3) + ReLU layers
    run_layer(ei, wbuf, X3, Abig, Bbig, v,    128, 128, W1, b1, actA);
    run_layer(ei, wbuf, X3, Abig, Bbig, actA, 128, 256, W2, b2, actB);
    run_layer(ei, wbuf, X3, Abig, Bbig, actB, 256, 512, W3, b3, actA);

    // heads: convert actA once (K=512), then two GEMMs
    long long tota = (long long)NN * 512;
    k_aconv<<<(int)((tota + 255) / 256), 256>>>(actA, Abig, 512);
    run_gemm(Abig, Wmu,  Bbig, bmu,  out,                    512, 256, 0);
    run_gemm(Abig, Wstd, Bbig, bstd, out + (size_t)NN * 256, 512, 256, 0);

    (void)in_sizes; (void)n_in; (void)out_size;
}

// round 5
// speedup vs baseline: 1.7272x; 1.5982x over previous
#include <cuda_runtime.h>
#include <cuda_bf16.h>
#include <math.h>
#include <stdint.h>

#define NN 10000
#define NE 160000

// ---- scratch (static device globals; no allocation) ----
__device__ float g_deg[NN];
__device__ float g_dis[NN];
__device__ float g_w[NE];
__device__ int   g_cnt[NN];        // in-degree (by col) for CSR
__device__ int   g_rowptr[NN + 1];
__device__ int   g_cursor[NN];
__device__ int   g_csr_src[NE];
__device__ float g_csr_w[NE];
__device__ float g_X3[NN * 768];              // packed [tx0|tx1|tx2] fp32
__device__ float g_actA[NN * 512];
__device__ float g_actB[NN * 512];
__device__ __nv_bfloat16 g_Abig[NN * 2304];   // [hi|lo|hi] split, K''max = 2304
__device__ __nv_bfloat16 g_Bbig[512 * 2304];  // transposed+split weights [N, K'']

__device__ __forceinline__ uint32_t smem_u32(const void* p) {
    uint32_t a;
    asm("{ .reg .u64 t; cvta.to.shared.u64 t, %1; cvt.u32.u64 %0, t; }" : "=r"(a) : "l"(p));
    return a;
}

// =============== graph preprocessing ===============
__global__ void k_zero2(float* deg, int* cnt, int n) {
    int i = blockIdx.x * blockDim.x + threadIdx.x;
    if (i < n) { deg[i] = 0.f; cnt[i] = 0; }
}
// out-degree on row (normalization) + in-degree on col (CSR)
__global__ void k_counts(const int* __restrict__ ei, float* __restrict__ deg,
                         int* __restrict__ cnt) {
    int e = blockIdx.x * blockDim.x + threadIdx.x;
    if (e < NE) {
        atomicAdd(&deg[ei[e]], 1.f);
        atomicAdd(&cnt[ei[NE + e]], 1);
    }
}
__global__ void k_dis(const float* __restrict__ deg, float* __restrict__ dis) {
    int i = blockIdx.x * blockDim.x + threadIdx.x;
    if (i < NN) {
        float d = deg[i];
        dis[i] = (d > 0.f) ? rsqrtf(d) : 0.f;
    }
}
__global__ void k_w(const int* __restrict__ ei, const float* __restrict__ dis,
                    float* __restrict__ w) {
    int e = blockIdx.x * blockDim.x + threadIdx.x;
    if (e < NE) w[e] = -dis[ei[e]] * dis[ei[NE + e]];
}
// single-block prefix sum over NN counts -> rowptr, and seed cursor
__global__ void k_scan(const int* __restrict__ cnt, int* __restrict__ rowptr,
                       int* __restrict__ cursor) {
    __shared__ int sh[1024];
    __shared__ int carry;
    int tid = threadIdx.x;
    if (tid == 0) { carry = 0; rowptr[0] = 0; }
    __syncthreads();
    for (int base = 0; base < NN; base += 1024) {
        int i = base + tid;
        int v = (i < NN) ? cnt[i] : 0;
        sh[tid] = v;
        __syncthreads();
        for (int off = 1; off < 1024; off <<= 1) {
            int t = (tid >= off) ? sh[tid - off] : 0;
            __syncthreads();
            sh[tid] += t;
            __syncthreads();
        }
        if (i < NN) {
            int inc = carry + sh[tid];
            rowptr[i + 1] = inc;
            cursor[i] = inc - v;   // exclusive = start offset
        }
        __syncthreads();
        if (tid == 1023) carry += sh[1023];
        __syncthreads();
    }
}
__global__ void k_scatter(const int* __restrict__ ei, const float* __restrict__ w,
                          int* __restrict__ cursor, int* __restrict__ csr_src,
                          float* __restrict__ csr_w) {
    int e = blockIdx.x * blockDim.x + threadIdx.x;
    if (e < NE) {
        int c = ei[NE + e];
        int p = atomicAdd(&cursor[c], 1);
        csr_src[p] = ei[e];
        csr_w[p] = w[e];
    }
}

// =============== CSR gather props (no atomics) ===============
// prop1: X3[n][slot1] = sum w*x[src];  X3[n][slot0] = x[n]
__global__ __launch_bounds__(128) void k_gprop1(
    const int* __restrict__ rowptr, const int* __restrict__ csr_src,
    const float* __restrict__ csr_w, const float* __restrict__ x,
    float* __restrict__ X3, int Fin)
{
    __shared__ int   ssrc[128];
    __shared__ float sw[128];
    int n = blockIdx.x;
    int f = blockIdx.y * 128 + threadIdx.x;
    int s = rowptr[n], e = rowptr[n + 1];
    float acc = 0.f;
    for (int j0 = s; j0 < e; j0 += 128) {
        int j = j0 + threadIdx.x;
        if (j < e) { ssrc[threadIdx.x] = csr_src[j]; sw[threadIdx.x] = csr_w[j]; }
        __syncthreads();
        int m = min(128, e - j0);
        for (int t = 0; t < m; t++)
            acc += sw[t] * x[(size_t)ssrc[t] * Fin + f];
        __syncthreads();
    }
    float* row = X3 + (size_t)n * 3 * Fin;
    row[Fin + f] = acc;
    row[f] = x[(size_t)n * Fin + f];
}
// prop2: X3[n][slot2] = 2*sum w*tx1[src] - x[n]
__global__ __launch_bounds__(128) void k_gprop2(
    const int* __restrict__ rowptr, const int* __restrict__ csr_src,
    const float* __restrict__ csr_w, const float* __restrict__ x,
    float* __restrict__ X3, int Fin)
{
    __shared__ int   ssrc[128];
    __shared__ float sw[128];
    int n = blockIdx.x;
    int f = blockIdx.y * 128 + threadIdx.x;
    int s = rowptr[n], e = rowptr[n + 1];
    float acc = 0.f;
    for (int j0 = s; j0 < e; j0 += 128) {
        int j = j0 + threadIdx.x;
        if (j < e) { ssrc[threadIdx.x] = csr_src[j]; sw[threadIdx.x] = csr_w[j]; }
        __syncthreads();
        int m = min(128, e - j0);
        for (int t = 0; t < m; t++)
            acc += sw[t] * X3[(size_t)ssrc[t] * 3 * Fin + Fin + f];
        __syncthreads();
    }
    X3[(size_t)n * 3 * Fin + 2 * Fin + f] = 2.f * acc - x[(size_t)n * Fin + f];
}

// =============== bf16 split conversions ===============
__global__ void k_aconv(const float* __restrict__ X, __nv_bfloat16* __restrict__ A, int K) {
    long long i = (long long)blockIdx.x * blockDim.x + threadIdx.x;
    long long tot = (long long)NN * K;
    if (i < tot) {
        int n = (int)(i / K);
        int k = (int)(i - (long long)n * K);
        float x = X[i];
        __nv_bfloat16 hi = __float2bfloat16(x);
        __nv_bfloat16 lo = __float2bfloat16(x - __bfloat162float(hi));
        __nv_bfloat16* row = A + (size_t)n * 3 * K;
        row[k] = hi;
        row[K + k] = lo;
        row[2 * K + k] = hi;
    }
}
__global__ void k_wconv(const float* __restrict__ W, __nv_bfloat16* __restrict__ B,
                        int K, int N) {
    int i = blockIdx.x * blockDim.x + threadIdx.x;
    if (i < K * N) {
        int k = i / N;
        int n = i - k * N;
        float x = W[i];
        __nv_bfloat16 hi = __float2bfloat16(x);
        __nv_bfloat16 lo = __float2bfloat16(x - __bfloat162float(hi));
        __nv_bfloat16* row = B + (size_t)n * 3 * K;
        row[k] = hi;
        row[K + k] = hi;
        row[2 * K + k] = lo;
    }
}

// =============== mma.sync bf16 GEMM: C[M,N] = A[M,K''] @ B[N,K'']^T + bias ========
#define LDT 40   // padded smem stride in bf16 elems (80B rows -> conflict-free)

__device__ __forceinline__ void ldm_x4(uint32_t& r0, uint32_t& r1, uint32_t& r2, uint32_t& r3,
                                       uint32_t a) {
    asm volatile("ldmatrix.sync.aligned.m8n8.x4.shared.b16 {%0,%1,%2,%3}, [%4];"
                 : "=r"(r0), "=r"(r1), "=r"(r2), "=r"(r3) : "r"(a));
}
__device__ __forceinline__ void ldm_x2(uint32_t& r0, uint32_t& r1, uint32_t a) {
    asm volatile("ldmatrix.sync.aligned.m8n8.x2.shared.b16 {%0,%1}, [%2];"
                 : "=r"(r0), "=r"(r1) : "r"(a));
}
__device__ __forceinline__ void mma_bf16(float* c, const uint32_t* a, const uint32_t* b) {
    asm volatile(
        "mma.sync.aligned.m16n8k16.row.col.f32.bf16.bf16.f32 "
        "{%0,%1,%2,%3}, {%4,%5,%6,%7}, {%8,%9}, {%0,%1,%2,%3};"
        : "+f"(c[0]), "+f"(c[1]), "+f"(c[2]), "+f"(c[3])
        : "r"(a[0]), "r"(a[1]), "r"(a[2]), "r"(a[3]), "r"(b[0]), "r"(b[1]));
}
__device__ __forceinline__ void cp16(uint32_t dst, const void* src, int pred16) {
    asm volatile("cp.async.ca.shared.global [%0], [%1], 16, %2;"
                 :: "r"(dst), "l"(src), "r"(pred16) : "memory");
}

__global__ __launch_bounds__(256, 1) void k_mgemm(
    const __nv_bfloat16* __restrict__ A, const __nv_bfloat16* __restrict__ B,
    const float* __restrict__ bias, float* __restrict__ C,
    int M, int Kbig, int ldc, int relu)
{
    __shared__ __align__(16) __nv_bfloat16 sA[2][128 * LDT];
    __shared__ __align__(16) __nv_bfloat16 sB[2][128 * LDT];

    const int tid = threadIdx.x;
    const int wid = tid >> 5;
    const int lane = tid & 31;
    const int bm = blockIdx.y * 128;
    const int bn = blockIdx.x * 128;
    const int warp_m = (wid & 1) * 64;
    const int warp_n = (wid >> 1) * 32;

    float acc[4][4][4];
#pragma unroll
    for (int i = 0; i < 4; i++)
#pragma unroll
        for (int j = 0; j < 4; j++)
#pragma unroll
            for (int q = 0; q < 4; q++) acc[i][j][q] = 0.f;

    const uint32_t sA_base[2] = { smem_u32(sA[0]), smem_u32(sA[1]) };
    const uint32_t sB_base[2] = { smem_u32(sB[0]), smem_u32(sB[1]) };
    const int niter = Kbig >> 5;   // /32

    const int lr = tid >> 1;
    const int lc0 = (tid & 1) * 2;

    auto issue = [&](int stage, int k0) {
#pragma unroll
        for (int h = 0; h < 2; h++) {
            int c = lc0 + h;
            int gm = bm + lr;
            cp16(sA_base[stage] + (lr * LDT + c * 8) * 2,
                 A + (size_t)gm * Kbig + k0 + c * 8, gm < M ? 16 : 0);
            cp16(sB_base[stage] + (lr * LDT + c * 8) * 2,
                 B + (size_t)(bn + lr) * Kbig + k0 + c * 8, 16);
        }
        asm volatile("cp.async.commit_group;" ::: "memory");
    };

    issue(0, 0);
    for (int it = 0; it < niter; it++) {
        const int stage = it & 1;
        if (it + 1 < niter) {
            issue(stage ^ 1, (it + 1) << 5);
            asm volatile("cp.async.wait_group 1;" ::: "memory");
        } else {
            asm volatile("cp.async.wait_group 0;" ::: "memory");
        }
        __syncthreads();

#pragma unroll
        for (int ks = 0; ks < 2; ks++) {
            uint32_t af[4][4];
            uint32_t bf[4][2];
#pragma unroll
            for (int mf = 0; mf < 4; mf++) {
                uint32_t addr = sA_base[stage] +
                    ((warp_m + mf * 16 + (lane & 15)) * LDT + ks * 16 + (lane >> 4) * 8) * 2;
                ldm_x4(af[mf][0], af[mf][1], af[mf][2], af[mf][3], addr);
            }
#pragma unroll
            for (int nf = 0; nf < 4; nf++) {
                uint32_t addr = sB_base[stage] +
                    ((warp_n + nf * 8 + (lane & 7)) * LDT + ks * 16 + ((lane >> 3) & 1) * 8) * 2;
                ldm_x2(bf[nf][0], bf[nf][1], addr);
            }
#pragma unroll
            for (int mf = 0; mf < 4; mf++)
#pragma unroll
                for (int nf = 0; nf < 4; nf++)
                    mma_bf16(acc[mf][nf], af[mf], bf[nf]);
        }
        __syncthreads();
    }

#pragma unroll
    for (int mf = 0; mf < 4; mf++) {
#pragma unroll
        for (int nf = 0; nf < 4; nf++) {
            int row0 = bm + warp_m + mf * 16 + (lane >> 2);
            int col0 = bn + warp_n + nf * 8 + (lane & 3) * 2;
#pragma unroll
            for (int h = 0; h < 2; h++) {
                int row = row0 + h * 8;
                if (row < M) {
                    float v0 = acc[mf][nf][h * 2 + 0] + bias[col0];
                    float v1 = acc[mf][nf][h * 2 + 1] + bias[col0 + 1];
                    if (relu) { v0 = fmaxf(v0, 0.f); v1 = fmaxf(v1, 0.f); }
                    *(float2*)(C + (size_t)row * ldc + col0) = make_float2(v0, v1);
                }
            }
        }
    }
}

// =============== host orchestration ===============
static void run_gemm(const __nv_bfloat16* A, const float* W, __nv_bfloat16* Bbig,
                     const float* bias, float* C, int K, int N, int relu) {
    k_wconv<<<(K * N + 255) / 256, 256>>>(W, Bbig, K, N);
    dim3 grid(N / 128, (NN + 127) / 128);
    k_mgemm<<<grid, 256>>>(A, Bbig, bias, C, NN, 3 * K, N, relu);
}

static void run_layer(const int* rowptr, const int* csr_src, const float* csr_w,
                      float* X3, __nv_bfloat16* Abig, __nv_bfloat16* Bbig,
                      const float* x, int Fin, int Fout,
                      const float* W, const float* b, float* y) {
    dim3 pg(NN, Fin / 128);
    k_gprop1<<<pg, 128>>>(rowptr, csr_src, csr_w, x, X3, Fin);
    k_gprop2<<<pg, 128>>>(rowptr, csr_src, csr_w, x, X3, Fin);
    long long tota = (long long)NN * 3 * Fin;
    k_aconv<<<(int)((tota + 255) / 256), 256>>>(X3, Abig, 3 * Fin);
    run_gemm(Abig, W, Bbig, b, y, 3 * Fin, Fout, 1);
}

extern "C" void kernel_launch(void* const* d_in, const int* in_sizes, int n_in,
                              void* d_out, int out_size) {
    const float* v    = (const float*)d_in[0];
    const int* ei     = (const int*)d_in[1];
    const float* W1   = (const float*)d_in[2];
    const float* b1   = (const float*)d_in[3];
    const float* W2   = (const float*)d_in[4];
    const float* b2   = (const float*)d_in[5];
    const float* W3   = (const float*)d_in[6];
    const float* b3   = (const float*)d_in[7];
    const float* Wmu  = (const float*)d_in[8];
    const float* bmu  = (const float*)d_in[9];
    const float* Wstd = (const float*)d_in[10];
    const float* bstd = (const float*)d_in[11];
    float* out = (float*)d_out;

    float *deg, *dis, *wbuf, *X3, *actA, *actB, *csr_w;
    int *cnt, *rowptr, *cursor, *csr_src;
    __nv_bfloat16 *Abig, *Bbig;
    cudaGetSymbolAddress((void**)&deg,     g_deg);
    cudaGetSymbolAddress((void**)&dis,     g_dis);
    cudaGetSymbolAddress((void**)&wbuf,    g_w);
    cudaGetSymbolAddress((void**)&cnt,     g_cnt);
    cudaGetSymbolAddress((void**)&rowptr,  g_rowptr);
    cudaGetSymbolAddress((void**)&cursor,  g_cursor);
    cudaGetSymbolAddress((void**)&csr_src, g_csr_src);
    cudaGetSymbolAddress((void**)&csr_w,   g_csr_w);
    cudaGetSymbolAddress((void**)&X3,      g_X3);
    cudaGetSymbolAddress((void**)&actA,    g_actA);
    cudaGetSymbolAddress((void**)&actB,    g_actB);
    cudaGetSymbolAddress((void**)&Abig,    g_Abig);
    cudaGetSymbolAddress((void**)&Bbig,    g_Bbig);

    // graph preprocessing: normalization + CSR by destination
    k_zero2<<<(NN + 255) / 256, 256>>>(deg, cnt, NN);
    k_counts<<<(NE + 255) / 256, 256>>>(ei, deg, cnt);
    k_dis<<<(NN + 255) / 256, 256>>>(deg, dis);
    k_w<<<(NE + 255) / 256, 256>>>(ei, dis, wbuf);
    k_scan<<<1, 1024>>>(cnt, rowptr, cursor);
    k_scatter<<<(NE + 255) / 256, 256>>>(ei, wbuf, cursor, csr_src, csr_w);

    // 3 ChebConv(K=3) + ReLU layers
    run_layer(rowptr, csr_src, csr_w, X3, Abig, Bbig, v,    128, 128, W1, b1, actA);
    run_layer(rowptr, csr_src, csr_w, X3, Abig, Bbig, actA, 128, 256, W2, b2, actB);
    run_layer(rowptr, csr_src, csr_w, X3, Abig, Bbig, actB, 256, 512, W3, b3, actA);

    // heads: convert actA once (K=512), then two GEMMs
    long long tota = (long long)NN * 512;
    k_aconv<<<(int)((tota + 255) / 256), 256>>>(actA, Abig, 512);
    run_gemm(Abig, Wmu,  Bbig, bmu,  out,                    512, 256, 0);
    run_gemm(Abig, Wstd, Bbig, bstd, out + (size_t)NN * 256, 512, 256, 0);

    (void)in_sizes; (void)n_in; (void)out_size;
}

// round 7
// speedup vs baseline: 2.0185x; 1.1686x over previous
#include <cuda_runtime.h>
#include <cuda_bf16.h>
#include <math.h>
#include <stdint.h>

#define NN 10000
#define NE 160000

// ---- scratch (static device globals; no allocation) ----
__device__ float g_deg[NN];
__device__ float g_dis[NN];
__device__ float g_w[NE];
__device__ int   g_cnt[NN];
__device__ int   g_rowptr[NN + 1];
__device__ int   g_cursor[NN];
__device__ int   g_csr_src[NE];
__device__ float g_csr_w[NE];
__device__ float g_tx1[NN * 256];             // fp32 tx1 (prop2 input), max Fin=256
__device__ float g_actA[NN * 512];
__device__ float g_actB[NN * 512];
__device__ __nv_bfloat16 g_Abig[NN * 2304];   // split rows, K''max = 9*256 = 2304
__device__ __nv_bfloat16 g_Bbig[512 * 2304];  // transposed+split weights [N, K'']

__device__ __forceinline__ uint32_t smem_u32(const void* p) {
    uint32_t a;
    asm("{ .reg .u64 t; cvta.to.shared.u64 t, %1; cvt.u32.u64 %0, t; }" : "=r"(a) : "l"(p));
    return a;
}

// =============== graph preprocessing ===============
__global__ void k_zero2(float* deg, int* cnt, int n) {
    int i = blockIdx.x * blockDim.x + threadIdx.x;
    if (i < n) { deg[i] = 0.f; cnt[i] = 0; }
}
__global__ void k_counts(const int* __restrict__ ei, float* __restrict__ deg,
                         int* __restrict__ cnt) {
    int e = blockIdx.x * blockDim.x + threadIdx.x;
    if (e < NE) {
        atomicAdd(&deg[ei[e]], 1.f);
        atomicAdd(&cnt[ei[NE + e]], 1);
    }
}
__global__ void k_dis(const float* __restrict__ deg, float* __restrict__ dis) {
    int i = blockIdx.x * blockDim.x + threadIdx.x;
    if (i < NN) {
        float d = deg[i];
        dis[i] = (d > 0.f) ? rsqrtf(d) : 0.f;
    }
}
__global__ void k_w(const int* __restrict__ ei, const float* __restrict__ dis,
                    float* __restrict__ w) {
    int e = blockIdx.x * blockDim.x + threadIdx.x;
    if (e < NE) w[e] = -dis[ei[e]] * dis[ei[NE + e]];
}
__global__ void k_scan(const int* __restrict__ cnt, int* __restrict__ rowptr,
                       int* __restrict__ cursor) {
    __shared__ int sh[1024];
    __shared__ int carry;
    int tid = threadIdx.x;
    if (tid == 0) { carry = 0; rowptr[0] = 0; }
    __syncthreads();
    for (int base = 0; base < NN; base += 1024) {
        int i = base + tid;
        int v = (i < NN) ? cnt[i] : 0;
        sh[tid] = v;
        __syncthreads();
        for (int off = 1; off < 1024; off <<= 1) {
            int t = (tid >= off) ? sh[tid - off] : 0;
            __syncthreads();
            sh[tid] += t;
            __syncthreads();
        }
        if (i < NN) {
            int inc = carry + sh[tid];
            rowptr[i + 1] = inc;
            cursor[i] = inc - v;
        }
        __syncthreads();
        if (tid == 1023) carry += sh[1023];
        __syncthreads();
    }
}
__global__ void k_scatter(const int* __restrict__ ei, const float* __restrict__ w,
                          int* __restrict__ cursor, int* __restrict__ csr_src,
                          float* __restrict__ csr_w) {
    int e = blockIdx.x * blockDim.x + threadIdx.x;
    if (e < NE) {
        int c = ei[NE + e];
        int p = atomicAdd(&cursor[c], 1);
        csr_src[p] = ei[e];
        csr_w[p] = w[e];
    }
}

// =============== CSR gather props, fused bf16-split A writes ===============
// Abig row layout (len 9*Fin): [hi(tx0)|hi(tx1)|hi(tx2) | lo(tx0)|lo(tx1)|lo(tx2) | hi(...)]
__device__ __forceinline__ void split_write(__nv_bfloat16* row, int Fin, int pos, float v) {
    __nv_bfloat16 hi = __float2bfloat16(v);
    __nv_bfloat16 lo = __float2bfloat16(v - __bfloat162float(hi));
    row[pos] = hi;
    row[3 * Fin + pos] = lo;
    row[6 * Fin + pos] = hi;
}

// prop1: tx1 = sum w*x[src]; writes tx0,tx1 splits + tx1 fp32
__global__ __launch_bounds__(128) void k_gprop1(
    const int* __restrict__ rowptr, const int* __restrict__ csr_src,
    const float* __restrict__ csr_w, const float* __restrict__ x,
    float* __restrict__ tx1, __nv_bfloat16* __restrict__ Abig, int Fin)
{
    __shared__ int   ssrc[128];
    __shared__ float sw[128];
    int n = blockIdx.x;
    int f = blockIdx.y * 128 + threadIdx.x;
    int s = rowptr[n], e = rowptr[n + 1];
    float acc = 0.f;
    for (int j0 = s; j0 < e; j0 += 128) {
        int j = j0 + threadIdx.x;
        if (j < e) { ssrc[threadIdx.x] = csr_src[j]; sw[threadIdx.x] = csr_w[j]; }
        __syncthreads();
        int m = min(128, e - j0);
        for (int t = 0; t < m; t++)
            acc += sw[t] * x[(size_t)ssrc[t] * Fin + f];
        __syncthreads();
    }
    float x0 = x[(size_t)n * Fin + f];
    __nv_bfloat16* row = Abig + (size_t)n * 9 * Fin;
    split_write(row, Fin, f, x0);
    split_write(row, Fin, Fin + f, acc);
    tx1[(size_t)n * Fin + f] = acc;
}
// prop2: tx2 = 2*sum w*tx1[src] - x; writes tx2 split
__global__ __launch_bounds__(128) void k_gprop2(
    const int* __restrict__ rowptr, const int* __restrict__ csr_src,
    const float* __restrict__ csr_w, const float* __restrict__ x,
    const float* __restrict__ tx1, __nv_bfloat16* __restrict__ Abig, int Fin)
{
    __shared__ int   ssrc[128];
    __shared__ float sw[128];
    int n = blockIdx.x;
    int f = blockIdx.y * 128 + threadIdx.x;
    int s = rowptr[n], e = rowptr[n + 1];
    float acc = 0.f;
    for (int j0 = s; j0 < e; j0 += 128) {
        int j = j0 + threadIdx.x;
        if (j < e) { ssrc[threadIdx.x] = csr_src[j]; sw[threadIdx.x] = csr_w[j]; }
        __syncthreads();
        int m = min(128, e - j0);
        for (int t = 0; t < m; t++)
            acc += sw[t] * tx1[(size_t)ssrc[t] * Fin + f];
        __syncthreads();
    }
    float t2 = 2.f * acc - x[(size_t)n * Fin + f];
    __nv_bfloat16* row = Abig + (size_t)n * 9 * Fin;
    split_write(row, Fin, 2 * Fin + f, t2);
}

// =============== bf16 split conversions ===============
// A: X [NN, K] -> rows of 3K: [hi | lo | hi]
__global__ void k_aconv(const float* __restrict__ X, __nv_bfloat16* __restrict__ A, int K) {
    long long i = (long long)blockIdx.x * blockDim.x + threadIdx.x;
    long long tot = (long long)NN * K;
    if (i < tot) {
        int n = (int)(i / K);
        int k = (int)(i - (long long)n * K);
        float x = X[i];
        __nv_bfloat16 hi = __float2bfloat16(x);
        __nv_bfloat16 lo = __float2bfloat16(x - __bfloat162float(hi));
        __nv_bfloat16* row = A + (size_t)n * 3 * K;
        row[k] = hi;
        row[K + k] = lo;
        row[2 * K + k] = hi;
    }
}
// B: W [K, N] -> rows of 3K per output-col n: [hi | hi | lo]
__global__ void k_wconv(const float* __restrict__ W, __nv_bfloat16* __restrict__ B,
                        int K, int N) {
    int i = blockIdx.x * blockDim.x + threadIdx.x;
    if (i < K * N) {
        int k = i / N;
        int n = i - k * N;
        float x = W[i];
        __nv_bfloat16 hi = __float2bfloat16(x);
        __nv_bfloat16 lo = __float2bfloat16(x - __bfloat162float(hi));
        __nv_bfloat16* row = B + (size_t)n * 3 * K;
        row[k] = hi;
        row[K + k] = hi;
        row[2 * K + k] = lo;
    }
}

// =============== mma.sync bf16 GEMM, 4-stage cp.async pipeline ===============
#define LDT 40           // padded smem stride (80B rows: 16B-aligned, conflict-free)
#define NSTAGE 4
#define TILE_ELEMS (128 * LDT)

__device__ __forceinline__ void ldm_x4(uint32_t& r0, uint32_t& r1, uint32_t& r2, uint32_t& r3,
                                       uint32_t a) {
    asm volatile("ldmatrix.sync.aligned.m8n8.x4.shared.b16 {%0,%1,%2,%3}, [%4];"
                 : "=r"(r0), "=r"(r1), "=r"(r2), "=r"(r3) : "r"(a));
}
__device__ __forceinline__ void ldm_x2(uint32_t& r0, uint32_t& r1, uint32_t a) {
    asm volatile("ldmatrix.sync.aligned.m8n8.x2.shared.b16 {%0,%1}, [%2];"
                 : "=r"(r0), "=r"(r1) : "r"(a));
}
__device__ __forceinline__ void mma_bf16(float* c, const uint32_t* a, const uint32_t* b) {
    asm volatile(
        "mma.sync.aligned.m16n8k16.row.col.f32.bf16.bf16.f32 "
        "{%0,%1,%2,%3}, {%4,%5,%6,%7}, {%8,%9}, {%0,%1,%2,%3};"
        : "+f"(c[0]), "+f"(c[1]), "+f"(c[2]), "+f"(c[3])
        : "r"(a[0]), "r"(a[1]), "r"(a[2]), "r"(a[3]), "r"(b[0]), "r"(b[1]));
}
__device__ __forceinline__ void cp16(uint32_t dst, const void* src, int pred16) {
    asm volatile("cp.async.cg.shared.global [%0], [%1], 16, %2;"
                 :: "r"(dst), "l"(src), "r"(pred16) : "memory");
}

// C cols < split -> C0[row*ldc+col] (+bias0), else C1[row*ldc+col-split] (+bias1)
__global__ __launch_bounds__(256) void k_mgemm(
    const __nv_bfloat16* __restrict__ A, const __nv_bfloat16* __restrict__ B,
    const float* __restrict__ bias0, const float* __restrict__ bias1,
    float* __restrict__ C0, float* __restrict__ C1,
    int M, int Kbig, int ldc, int relu, int split)
{
    extern __shared__ __align__(16) __nv_bfloat16 smp[];
    __nv_bfloat16* sAp = smp;
    __nv_bfloat16* sBp = smp + NSTAGE * TILE_ELEMS;

    const int tid = threadIdx.x;
    const int wid = tid >> 5;
    const int lane = tid & 31;
    const int bm = blockIdx.y * 128;
    const int bn = blockIdx.x * 128;
    const int warp_m = (wid & 1) * 64;
    const int warp_n = (wid >> 1) * 32;

    float acc[4][4][4];
#pragma unroll
    for (int i = 0; i < 4; i++)
#pragma unroll
        for (int j = 0; j < 4; j++)
#pragma unroll
            for (int q = 0; q < 4; q++) acc[i][j][q] = 0.f;

    uint32_t sA_u[NSTAGE], sB_u[NSTAGE];
#pragma unroll
    for (int s = 0; s < NSTAGE; s++) {
        sA_u[s] = smem_u32(sAp + s * TILE_ELEMS);
        sB_u[s] = smem_u32(sBp + s * TILE_ELEMS);
    }
    const int niter = Kbig >> 5;

    const int lr = tid >> 1;
    const int lc0 = (tid & 1) * 2;

    auto issue = [&](int stage, int k0) {
#pragma unroll
        for (int h = 0; h < 2; h++) {
            int c = lc0 + h;
            int gm = bm + lr;
            cp16(sA_u[stage] + (lr * LDT + c * 8) * 2,
                 A + (size_t)gm * Kbig + k0 + c * 8, gm < M ? 16 : 0);
            cp16(sB_u[stage] + (lr * LDT + c * 8) * 2,
                 B + (size_t)(bn + lr) * Kbig + k0 + c * 8, 16);
        }
        asm volatile("cp.async.commit_group;" ::: "memory");
    };

    // prologue: 3 stages in flight (niter >= 3 always here: min Kbig = 1152)
    issue(0, 0);
    issue(1, 32);
    issue(2, 64);

    for (int it = 0; it < niter; it++) {
        const int stage = it & (NSTAGE - 1);
        const int ahead = niter - 1 - it;
        if (ahead >= 2)      asm volatile("cp.async.wait_group 2;" ::: "memory");
        else if (ahead == 1) asm volatile("cp.async.wait_group 1;" ::: "memory");
        else                 asm volatile("cp.async.wait_group 0;" ::: "memory");
        __syncthreads();

        if (it + 3 < niter) issue((it + 3) & (NSTAGE - 1), (it + 3) << 5);

#pragma unroll
        for (int ks = 0; ks < 2; ks++) {
            uint32_t af[4][4];
            uint32_t bf[4][2];
#pragma unroll
            for (int mf = 0; mf < 4; mf++) {
                uint32_t addr = sA_u[stage] +
                    ((warp_m + mf * 16 + (lane & 15)) * LDT + ks * 16 + (lane >> 4) * 8) * 2;
                ldm_x4(af[mf][0], af[mf][1], af[mf][2], af[mf][3], addr);
            }
#pragma unroll
            for (int nf = 0; nf < 4; nf++) {
                uint32_t addr = sB_u[stage] +
                    ((warp_n + nf * 8 + (lane & 7)) * LDT + ks * 16 + ((lane >> 3) & 1) * 8) * 2;
                ldm_x2(bf[nf][0], bf[nf][1], addr);
            }
#pragma unroll
            for (int mf = 0; mf < 4; mf++)
#pragma unroll
                for (int nf = 0; nf < 4; nf++)
                    mma_bf16(acc[mf][nf], af[mf], bf[nf]);
        }
    }

    // epilogue with optional split output
#pragma unroll
    for (int mf = 0; mf < 4; mf++) {
#pragma unroll
        for (int nf = 0; nf < 4; nf++) {
            int row0 = bm + warp_m + mf * 16 + (lane >> 2);
            int col0 = bn + warp_n + nf * 8 + (lane & 3) * 2;
            bool second = col0 >= split;
            const float* bs = second ? bias1 : bias0;
            float* dst = second ? C1 : C0;
            int cc = second ? col0 - split : col0;
#pragma unroll
            for (int h = 0; h < 2; h++) {
                int row = row0 + h * 8;
                if (row < M) {
                    float v0 = acc[mf][nf][h * 2 + 0] + bs[cc];
                    float v1 = acc[mf][nf][h * 2 + 1] + bs[cc + 1];
                    if (relu) { v0 = fmaxf(v0, 0.f); v1 = fmaxf(v1, 0.f); }
                    *(float2*)(dst + (size_t)row * ldc + cc) = make_float2(v0, v1);
                }
            }
        }
    }
}

// =============== host orchestration ===============
#define SMEM_BYTES (2 * NSTAGE * TILE_ELEMS * 2)

static void launch_gemm(const __nv_bfloat16* A, const __nv_bfloat16* B,
                        const float* bias0, const float* bias1,
                        float* C0, float* C1, int Kbig, int N, int ldc,
                        int relu, int split) {
    dim3 grid(N / 128, (NN + 127) / 128);
    k_mgemm<<<grid, 256, SMEM_BYTES>>>(A, B, bias0, bias1, C0, C1, NN, Kbig, ldc, relu, split);
}

static void run_layer(const int* rowptr, const int* csr_src, const float* csr_w,
                      float* tx1, __nv_bfloat16* Abig, __nv_bfloat16* Bbig,
                      const float* x, int Fin, int Fout,
                      const float* W, const float* b, float* y) {
    dim3 pg(NN, Fin / 128);
    k_gprop1<<<pg, 128>>>(rowptr, csr_src, csr_w, x, tx1, Abig, Fin);
    k_gprop2<<<pg, 128>>>(rowptr, csr_src, csr_w, x, tx1, Abig, Fin);
    k_wconv<<<(3 * Fin * Fout + 255) / 256, 256>>>(W, Bbig, 3 * Fin, Fout);
    launch_gemm(Abig, Bbig, b, b, y, y, 9 * Fin, Fout, Fout, 1, Fout);
}

extern "C" void kernel_launch(void* const* d_in, const int* in_sizes, int n_in,
                              void* d_out, int out_size) {
    const float* v    = (const float*)d_in[0];
    const int* ei     = (const int*)d_in[1];
    const float* W1   = (const float*)d_in[2];
    const float* b1   = (const float*)d_in[3];
    const float* W2   = (const float*)d_in[4];
    const float* b2   = (const float*)d_in[5];
    const float* W3   = (const float*)d_in[6];
    const float* b3   = (const float*)d_in[7];
    const float* Wmu  = (const float*)d_in[8];
    const float* bmu  = (const float*)d_in[9];
    const float* Wstd = (const float*)d_in[10];
    const float* bstd = (const float*)d_in[11];
    float* out = (float*)d_out;

    static bool attr_done = false;
    if (!attr_done) {
        cudaFuncSetAttribute(k_mgemm, cudaFuncAttributeMaxDynamicSharedMemorySize, SMEM_BYTES);
        attr_done = true;
    }

    float *deg, *dis, *wbuf, *tx1, *actA, *actB, *csr_w;
    int *cnt, *rowptr, *cursor, *csr_src;
    __nv_bfloat16 *Abig, *Bbig;
    cudaGetSymbolAddress((void**)&deg,     g_deg);
    cudaGetSymbolAddress((void**)&dis,     g_dis);
    cudaGetSymbolAddress((void**)&wbuf,    g_w);
    cudaGetSymbolAddress((void**)&cnt,     g_cnt);
    cudaGetSymbolAddress((void**)&rowptr,  g_rowptr);
    cudaGetSymbolAddress((void**)&cursor,  g_cursor);
    cudaGetSymbolAddress((void**)&csr_src, g_csr_src);
    cudaGetSymbolAddress((void**)&csr_w,   g_csr_w);
    cudaGetSymbolAddress((void**)&tx1,     g_tx1);
    cudaGetSymbolAddress((void**)&actA,    g_actA);
    cudaGetSymbolAddress((void**)&actB,    g_actB);
    cudaGetSymbolAddress((void**)&Abig,    g_Abig);
    cudaGetSymbolAddress((void**)&Bbig,    g_Bbig);

    // graph preprocessing
    k_zero2<<<(NN + 255) / 256, 256>>>(deg, cnt, NN);
    k_counts<<<(NE + 255) / 256, 256>>>(ei, deg, cnt);
    k_dis<<<(NN + 255) / 256, 256>>>(deg, dis);
    k_w<<<(NE + 255) / 256, 256>>>(ei, dis, wbuf);
    k_scan<<<1, 1024>>>(cnt, rowptr, cursor);
    k_scatter<<<(NE + 255) / 256, 256>>>(ei, wbuf, cursor, csr_src, csr_w);

    // 3 ChebConv(K=3) + ReLU layers
    run_layer(rowptr, csr_src, csr_w, tx1, Abig, Bbig, v,    128, 128, W1, b1, actA);
    run_layer(rowptr, csr_src, csr_w, tx1, Abig, Bbig, actA, 128, 256, W2, b2, actB);
    run_layer(rowptr, csr_src, csr_w, tx1, Abig, Bbig, actB, 256, 512, W3, b3, actA);

    // fused heads: one N=512 GEMM (A shared), split output mu|std. K''=3*512=1536.
    long long tota = (long long)NN * 512;
    k_aconv<<<(int)((tota + 255) / 256), 256>>>(actA, Abig, 512);
    k_wconv<<<(512 * 256 + 255) / 256, 256>>>(Wmu,  Bbig, 512, 256);
    k_wconv<<<(512 * 256 + 255) / 256, 256>>>(Wstd, Bbig + (size_t)256 * 1536, 512, 256);
    launch_gemm(Abig, Bbig, bmu, bstd, out, out + (size_t)NN * 256,
                1536, 512, 256, 0, 256);

    (void)in_sizes; (void)n_in; (void)out_size;
}

// round 8
// speedup vs baseline: 2.3757x; 1.1770x over previous
#include <cuda_runtime.h>
#include <cuda_bf16.h>
#include <math.h>
#include <stdint.h>

#define NN 10000
#define NE 160000

// ---- scratch (static device globals; no allocation) ----
__device__ float g_deg[NN];
__device__ float g_dis[NN];
__device__ float g_w[NE];
__device__ int   g_cnt[NN];
__device__ int   g_rowptr[NN + 1];
__device__ int   g_cursor[NN];
__device__ int   g_csr_src[NE];
__device__ float g_csr_w[NE];
__device__ float g_tx1[NN * 256];             // fp32 tx1 (prop2 input), max Fin=256
__device__ float g_actA[NN * 512];
__device__ float g_actB[NN * 512];
__device__ __nv_bfloat16 g_Abig[NN * 2304];   // split rows, K''max = 9*256 = 2304
__device__ __nv_bfloat16 g_Bbig[512 * 2304];  // transposed+split weights [N, K'']

__device__ __forceinline__ uint32_t smem_u32(const void* p) {
    uint32_t a;
    asm("{ .reg .u64 t; cvta.to.shared.u64 t, %1; cvt.u32.u64 %0, t; }" : "=r"(a) : "l"(p));
    return a;
}
__device__ __forceinline__ uint32_t pack_bf16x2(float a, float b) {
    __nv_bfloat162 t = __floats2bfloat162_rn(a, b);   // .x=a (low addr), .y=b
    return *(uint32_t*)&t;
}

// =============== graph preprocessing ===============
__global__ void k_zero2(float* deg, int* cnt, int n) {
    int i = blockIdx.x * blockDim.x + threadIdx.x;
    if (i < n) { deg[i] = 0.f; cnt[i] = 0; }
}
__global__ void k_counts(const int* __restrict__ ei, float* __restrict__ deg,
                         int* __restrict__ cnt) {
    int e = blockIdx.x * blockDim.x + threadIdx.x;
    if (e < NE) {
        atomicAdd(&deg[ei[e]], 1.f);
        atomicAdd(&cnt[ei[NE + e]], 1);
    }
}
__global__ void k_dis(const float* __restrict__ deg, float* __restrict__ dis) {
    int i = blockIdx.x * blockDim.x + threadIdx.x;
    if (i < NN) {
        float d = deg[i];
        dis[i] = (d > 0.f) ? rsqrtf(d) : 0.f;
    }
}
__global__ void k_w(const int* __restrict__ ei, const float* __restrict__ dis,
                    float* __restrict__ w) {
    int e = blockIdx.x * blockDim.x + threadIdx.x;
    if (e < NE) w[e] = -dis[ei[e]] * dis[ei[NE + e]];
}
__global__ void k_scan(const int* __restrict__ cnt, int* __restrict__ rowptr,
                       int* __restrict__ cursor) {
    __shared__ int sh[1024];
    __shared__ int carry;
    int tid = threadIdx.x;
    if (tid == 0) { carry = 0; rowptr[0] = 0; }
    __syncthreads();
    for (int base = 0; base < NN; base += 1024) {
        int i = base + tid;
        int v = (i < NN) ? cnt[i] : 0;
        sh[tid] = v;
        __syncthreads();
        for (int off = 1; off < 1024; off <<= 1) {
            int t = (tid >= off) ? sh[tid - off] : 0;
            __syncthreads();
            sh[tid] += t;
            __syncthreads();
        }
        if (i < NN) {
            int inc = carry + sh[tid];
            rowptr[i + 1] = inc;
            cursor[i] = inc - v;
        }
        __syncthreads();
        if (tid == 1023) carry += sh[1023];
        __syncthreads();
    }
}
__global__ void k_scatter(const int* __restrict__ ei, const float* __restrict__ w,
                          int* __restrict__ cursor, int* __restrict__ csr_src,
                          float* __restrict__ csr_w) {
    int e = blockIdx.x * blockDim.x + threadIdx.x;
    if (e < NE) {
        int c = ei[NE + e];
        int p = atomicAdd(&cursor[c], 1);
        csr_src[p] = ei[e];
        csr_w[p] = w[e];
    }
}

// =============== warp-per-node CSR gather props, fused bf16-split writes ===============
// Abig row layout (len 9*Fin): [hi(tx0)|hi(tx1)|hi(tx2) | lo(tx0..2) | hi(tx0..2)]
__device__ __forceinline__ void split_write4(__nv_bfloat16* row, int Fin, int pos, float4 v) {
    float hx = __bfloat162float(__float2bfloat16(v.x));
    float hy = __bfloat162float(__float2bfloat16(v.y));
    float hz = __bfloat162float(__float2bfloat16(v.z));
    float hw = __bfloat162float(__float2bfloat16(v.w));
    uint2 hi = make_uint2(pack_bf16x2(v.x, v.y), pack_bf16x2(v.z, v.w));
    uint2 lo = make_uint2(pack_bf16x2(v.x - hx, v.y - hy), pack_bf16x2(v.z - hz, v.w - hw));
    *(uint2*)(row + pos) = hi;
    *(uint2*)(row + 3 * Fin + pos) = lo;
    *(uint2*)(row + 6 * Fin + pos) = hi;
}

// prop1: tx1 = sum w*x[src]; writes tx0,tx1 splits + tx1 fp32. warp-per-node.
__global__ __launch_bounds__(128) void k_gprop1(
    const int* __restrict__ rowptr, const int* __restrict__ csr_src,
    const float* __restrict__ csr_w, const float* __restrict__ x,
    float* __restrict__ tx1, __nv_bfloat16* __restrict__ Abig, int Fin)
{
    int warp = threadIdx.x >> 5, lane = threadIdx.x & 31;
    int n = blockIdx.x * 4 + warp;
    if (n >= NN) return;
    int f = blockIdx.y * 128 + lane * 4;
    int s = rowptr[n], e = rowptr[n + 1];
    float4 acc = make_float4(0.f, 0.f, 0.f, 0.f);
    for (int j0 = s; j0 < e; j0 += 32) {
        int j = j0 + lane;
        int es = 0; float ew = 0.f;
        if (j < e) { es = csr_src[j]; ew = csr_w[j]; }
        int m = min(32, e - j0);
        for (int t = 0; t < m; t++) {
            int src = __shfl_sync(0xffffffffu, es, t);
            float wt = __shfl_sync(0xffffffffu, ew, t);
            float4 xv = *(const float4*)(x + (size_t)src * Fin + f);
            acc.x += wt * xv.x; acc.y += wt * xv.y;
            acc.z += wt * xv.z; acc.w += wt * xv.w;
        }
    }
    float4 x0 = *(const float4*)(x + (size_t)n * Fin + f);
    __nv_bfloat16* row = Abig + (size_t)n * 9 * Fin;
    split_write4(row, Fin, f, x0);
    split_write4(row, Fin, Fin + f, acc);
    *(float4*)(tx1 + (size_t)n * Fin + f) = acc;
}
// prop2: tx2 = 2*sum w*tx1[src] - x; writes tx2 split. warp-per-node.
__global__ __launch_bounds__(128) void k_gprop2(
    const int* __restrict__ rowptr, const int* __restrict__ csr_src,
    const float* __restrict__ csr_w, const float* __restrict__ x,
    const float* __restrict__ tx1, __nv_bfloat16* __restrict__ Abig, int Fin)
{
    int warp = threadIdx.x >> 5, lane = threadIdx.x & 31;
    int n = blockIdx.x * 4 + warp;
    if (n >= NN) return;
    int f = blockIdx.y * 128 + lane * 4;
    int s = rowptr[n], e = rowptr[n + 1];
    float4 acc = make_float4(0.f, 0.f, 0.f, 0.f);
    for (int j0 = s; j0 < e; j0 += 32) {
        int j = j0 + lane;
        int es = 0; float ew = 0.f;
        if (j < e) { es = csr_src[j]; ew = csr_w[j]; }
        int m = min(32, e - j0);
        for (int t = 0; t < m; t++) {
            int src = __shfl_sync(0xffffffffu, es, t);
            float wt = __shfl_sync(0xffffffffu, ew, t);
            float4 xv = *(const float4*)(tx1 + (size_t)src * Fin + f);
            acc.x += wt * xv.x; acc.y += wt * xv.y;
            acc.z += wt * xv.z; acc.w += wt * xv.w;
        }
    }
    float4 x0 = *(const float4*)(x + (size_t)n * Fin + f);
    float4 t2 = make_float4(2.f * acc.x - x0.x, 2.f * acc.y - x0.y,
                            2.f * acc.z - x0.z, 2.f * acc.w - x0.w);
    __nv_bfloat16* row = Abig + (size_t)n * 9 * Fin;
    split_write4(row, Fin, 2 * Fin + f, t2);
}

// =============== B weight split conversion ===============
// W [K, N] -> rows of 3K per output-col n: [hi | hi | lo]
__global__ void k_wconv(const float* __restrict__ W, __nv_bfloat16* __restrict__ B,
                        int K, int N) {
    int i = blockIdx.x * blockDim.x + threadIdx.x;
    if (i < K * N) {
        int k = i / N;
        int n = i - k * N;
        float x = W[i];
        __nv_bfloat16 hi = __float2bfloat16(x);
        __nv_bfloat16 lo = __float2bfloat16(x - __bfloat162float(hi));
        __nv_bfloat16* row = B + (size_t)n * 3 * K;
        row[k] = hi;
        row[K + k] = hi;
        row[2 * K + k] = lo;
    }
}

// =============== mma.sync bf16 GEMM, 64x128 tile, 4-stage cp.async ===============
#define LDT 40           // padded smem stride (80B rows: 16B-aligned, conflict-free)
#define NSTAGE 4
#define A_ELEMS (64 * LDT)
#define B_ELEMS (128 * LDT)

__device__ __forceinline__ void ldm_x4(uint32_t& r0, uint32_t& r1, uint32_t& r2, uint32_t& r3,
                                       uint32_t a) {
    asm volatile("ldmatrix.sync.aligned.m8n8.x4.shared.b16 {%0,%1,%2,%3}, [%4];"
                 : "=r"(r0), "=r"(r1), "=r"(r2), "=r"(r3) : "r"(a));
}
__device__ __forceinline__ void ldm_x2(uint32_t& r0, uint32_t& r1, uint32_t a) {
    asm volatile("ldmatrix.sync.aligned.m8n8.x2.shared.b16 {%0,%1}, [%2];"
                 : "=r"(r0), "=r"(r1) : "r"(a));
}
__device__ __forceinline__ void mma_bf16(float* c, const uint32_t* a, const uint32_t* b) {
    asm volatile(
        "mma.sync.aligned.m16n8k16.row.col.f32.bf16.bf16.f32 "
        "{%0,%1,%2,%3}, {%4,%5,%6,%7}, {%8,%9}, {%0,%1,%2,%3};"
        : "+f"(c[0]), "+f"(c[1]), "+f"(c[2]), "+f"(c[3])
        : "r"(a[0]), "r"(a[1]), "r"(a[2]), "r"(a[3]), "r"(b[0]), "r"(b[1]));
}
__device__ __forceinline__ void cp16(uint32_t dst, const void* src, int pred16) {
    asm volatile("cp.async.cg.shared.global [%0], [%1], 16, %2;"
                 :: "r"(dst), "l"(src), "r"(pred16) : "memory");
}

// If Asplit != 0: write [hi|lo|hi] bf16 rows (len 3*ldc) instead of fp32 C.
// Else: cols < split -> C0 (+bias0), else C1 (+bias1).
__global__ __launch_bounds__(256) void k_mgemm(
    const __nv_bfloat16* __restrict__ A, const __nv_bfloat16* __restrict__ B,
    const float* __restrict__ bias0, const float* __restrict__ bias1,
    float* __restrict__ C0, float* __restrict__ C1,
    __nv_bfloat16* __restrict__ Asplit,
    int M, int Kbig, int ldc, int relu, int split)
{
    extern __shared__ __align__(16) __nv_bfloat16 smp[];
    __nv_bfloat16* sAp = smp;
    __nv_bfloat16* sBp = smp + NSTAGE * A_ELEMS;

    const int tid = threadIdx.x;
    const int wid = tid >> 5;
    const int lane = tid & 31;
    const int bm = blockIdx.y * 64;
    const int bn = blockIdx.x * 128;
    const int warp_m = (wid & 1) * 32;
    const int warp_n = (wid >> 1) * 32;

    float acc[2][4][4];
#pragma unroll
    for (int i = 0; i < 2; i++)
#pragma unroll
        for (int j = 0; j < 4; j++)
#pragma unroll
            for (int q = 0; q < 4; q++) acc[i][j][q] = 0.f;

    uint32_t sA_u[NSTAGE], sB_u[NSTAGE];
#pragma unroll
    for (int s = 0; s < NSTAGE; s++) {
        sA_u[s] = smem_u32(sAp + s * A_ELEMS);
        sB_u[s] = smem_u32(sBp + s * B_ELEMS);
    }
    const int niter = Kbig >> 5;

    const int ar = tid >> 2, ac = tid & 3;

    auto issue = [&](int stage, int k0) {
        cp16(sA_u[stage] + (ar * LDT + ac * 8) * 2,
             A + (size_t)(bm + ar) * Kbig + k0 + ac * 8, (bm + ar) < M ? 16 : 0);
#pragma unroll
        for (int h = 0; h < 2; h++) {
            int idx = tid + h * 256;
            int br = idx >> 2, bc = idx & 3;
            cp16(sB_u[stage] + (br * LDT + bc * 8) * 2,
                 B + (size_t)(bn + br) * Kbig + k0 + bc * 8, 16);
        }
        asm volatile("cp.async.commit_group;" ::: "memory");
    };

    issue(0, 0);
    issue(1, 32);
    issue(2, 64);

    for (int it = 0; it < niter; it++) {
        const int stage = it & (NSTAGE - 1);
        const int ahead = niter - 1 - it;
        if (ahead >= 2)      asm volatile("cp.async.wait_group 2;" ::: "memory");
        else if (ahead == 1) asm volatile("cp.async.wait_group 1;" ::: "memory");
        else                 asm volatile("cp.async.wait_group 0;" ::: "memory");
        __syncthreads();

        if (it + 3 < niter) issue((it + 3) & (NSTAGE - 1), (it + 3) << 5);

#pragma unroll
        for (int ks = 0; ks < 2; ks++) {
            uint32_t af[2][4];
            uint32_t bf[4][2];
#pragma unroll
            for (int mf = 0; mf < 2; mf++) {
                uint32_t addr = sA_u[stage] +
                    ((warp_m + mf * 16 + (lane & 15)) * LDT + ks * 16 + (lane >> 4) * 8) * 2;
                ldm_x4(af[mf][0], af[mf][1], af[mf][2], af[mf][3], addr);
            }
#pragma unroll
            for (int nf = 0; nf < 4; nf++) {
                uint32_t addr = sB_u[stage] +
                    ((warp_n + nf * 8 + (lane & 7)) * LDT + ks * 16 + ((lane >> 3) & 1) * 8) * 2;
                ldm_x2(bf[nf][0], bf[nf][1], addr);
            }
#pragma unroll
            for (int mf = 0; mf < 2; mf++)
#pragma unroll
                for (int nf = 0; nf < 4; nf++)
                    mma_bf16(acc[mf][nf], af[mf], bf[nf]);
        }
    }

    // epilogue
#pragma unroll
    for (int mf = 0; mf < 2; mf++) {
#pragma unroll
        for (int nf = 0; nf < 4; nf++) {
            int row0 = bm + warp_m + mf * 16 + (lane >> 2);
            int col0 = bn + warp_n + nf * 8 + (lane & 3) * 2;
#pragma unroll
            for (int h = 0; h < 2; h++) {
                int row = row0 + h * 8;
                if (row >= M) continue;
                float v0 = acc[mf][nf][h * 2 + 0];
                float v1 = acc[mf][nf][h * 2 + 1];
                if (Asplit) {
                    v0 += bias0[col0]; v1 += bias0[col0 + 1];
                    if (relu) { v0 = fmaxf(v0, 0.f); v1 = fmaxf(v1, 0.f); }
                    float h0 = __bfloat162float(__float2bfloat16(v0));
                    float h1 = __bfloat162float(__float2bfloat16(v1));
                    uint32_t hi = pack_bf16x2(v0, v1);
                    uint32_t lo = pack_bf16x2(v0 - h0, v1 - h1);
                    __nv_bfloat16* arow = Asplit + (size_t)row * 3 * ldc;
                    *(uint32_t*)(arow + col0) = hi;
                    *(uint32_t*)(arow + ldc + col0) = lo;
                    *(uint32_t*)(arow + 2 * ldc + col0) = hi;
                } else {
                    bool second = col0 >= split;
                    const float* bs = second ? bias1 : bias0;
                    float* dst = second ? C1 : C0;
                    int cc = second ? col0 - split : col0;
                    v0 += bs[cc]; v1 += bs[cc + 1];
                    if (relu) { v0 = fmaxf(v0, 0.f); v1 = fmaxf(v1, 0.f); }
                    *(float2*)(dst + (size_t)row * ldc + cc) = make_float2(v0, v1);
                }
            }
        }
    }
}

// =============== host orchestration ===============
#define SMEM_BYTES (NSTAGE * (A_ELEMS + B_ELEMS) * 2)

static void launch_gemm(const __nv_bfloat16* A, const __nv_bfloat16* B,
                        const float* bias0, const float* bias1,
                        float* C0, float* C1, __nv_bfloat16* Asplit,
                        int Kbig, int N, int ldc, int relu, int split) {
    dim3 grid(N / 128, (NN + 63) / 64);
    k_mgemm<<<grid, 256, SMEM_BYTES>>>(A, B, bias0, bias1, C0, C1, Asplit,
                                       NN, Kbig, ldc, relu, split);
}

static void run_layer(const int* rowptr, const int* csr_src, const float* csr_w,
                      float* tx1, __nv_bfloat16* Abig, __nv_bfloat16* Bbig,
                      const float* x, int Fin, int Fout,
                      const float* W, const float* b, float* y,
                      __nv_bfloat16* Asplit) {
    dim3 pg((NN + 3) / 4, Fin / 128);
    k_gprop1<<<pg, 128>>>(rowptr, csr_src, csr_w, x, tx1, Abig, Fin);
    k_gprop2<<<pg, 128>>>(rowptr, csr_src, csr_w, x, tx1, Abig, Fin);
    k_wconv<<<(3 * Fin * Fout + 255) / 256, 256>>>(W, Bbig, 3 * Fin, Fout);
    launch_gemm(Abig, Bbig, b, b, y, y, Asplit, 9 * Fin, Fout, Fout, 1, Fout);
}

extern "C" void kernel_launch(void* const* d_in, const int* in_sizes, int n_in,
                              void* d_out, int out_size) {
    const float* v    = (const float*)d_in[0];
    const int* ei     = (const int*)d_in[1];
    const float* W1   = (const float*)d_in[2];
    const float* b1   = (const float*)d_in[3];
    const float* W2   = (const float*)d_in[4];
    const float* b2   = (const float*)d_in[5];
    const float* W3   = (const float*)d_in[6];
    const float* b3   = (const float*)d_in[7];
    const float* Wmu  = (const float*)d_in[8];
    const float* bmu  = (const float*)d_in[9];
    const float* Wstd = (const float*)d_in[10];
    const float* bstd = (const float*)d_in[11];
    float* out = (float*)d_out;

    static bool attr_done = false;
    if (!attr_done) {
        cudaFuncSetAttribute(k_mgemm, cudaFuncAttributeMaxDynamicSharedMemorySize, SMEM_BYTES);
        attr_done = true;
    }

    float *deg, *dis, *wbuf, *tx1, *actA, *actB, *csr_w;
    int *cnt, *rowptr, *cursor, *csr_src;
    __nv_bfloat16 *Abig, *Bbig;
    cudaGetSymbolAddress((void**)&deg,     g_deg);
    cudaGetSymbolAddress((void**)&dis,     g_dis);
    cudaGetSymbolAddress((void**)&wbuf,    g_w);
    cudaGetSymbolAddress((void**)&cnt,     g_cnt);
    cudaGetSymbolAddress((void**)&rowptr,  g_rowptr);
    cudaGetSymbolAddress((void**)&cursor,  g_cursor);
    cudaGetSymbolAddress((void**)&csr_src, g_csr_src);
    cudaGetSymbolAddress((void**)&csr_w,   g_csr_w);
    cudaGetSymbolAddress((void**)&tx1,     g_tx1);
    cudaGetSymbolAddress((void**)&actA,    g_actA);
    cudaGetSymbolAddress((void**)&actB,    g_actB);
    cudaGetSymbolAddress((void**)&Abig,    g_Abig);
    cudaGetSymbolAddress((void**)&Bbig,    g_Bbig);

    // graph preprocessing
    k_zero2<<<(NN + 255) / 256, 256>>>(deg, cnt, NN);
    k_counts<<<(NE + 255) / 256, 256>>>(ei, deg, cnt);
    k_dis<<<(NN + 255) / 256, 256>>>(deg, dis);
    k_w<<<(NE + 255) / 256, 256>>>(ei, dis, wbuf);
    k_scan<<<1, 1024>>>(cnt, rowptr, cursor);
    k_scatter<<<(NE + 255) / 256, 256>>>(ei, wbuf, cursor, csr_src, csr_w);

    // 3 ChebConv(K=3) + ReLU layers; L3 writes bf16 split rows directly
    run_layer(rowptr, csr_src, csr_w, tx1, Abig, Bbig, v,    128, 128, W1, b1, actA, nullptr);
    run_layer(rowptr, csr_src, csr_w, tx1, Abig, Bbig, actA, 128, 256, W2, b2, actB, nullptr);
    run_layer(rowptr, csr_src, csr_w, tx1, Abig, Bbig, actB, 256, 512, W3, b3, nullptr, Abig);

    // fused heads: one N=512 GEMM on split A (K''=1536), split output mu|std
    k_wconv<<<(512 * 256 + 255) / 256, 256>>>(Wmu,  Bbig, 512, 256);
    k_wconv<<<(512 * 256 + 255) / 256, 256>>>(Wstd, Bbig + (size_t)256 * 1536, 512, 256);
    launch_gemm(Abig, Bbig, bmu, bstd, out, out + (size_t)NN * 256, nullptr,
                1536, 512, 256, 0, 256);

    (void)in_sizes; (void)n_in; (void)out_size;
}

// round 9
// speedup vs baseline: 2.5840x; 1.0877x over previous
#include <cuda_runtime.h>
#include <cuda_bf16.h>
#include <math.h>
#include <stdint.h>

#define NN 10000
#define NE 160000

// ---- scratch (static device globals; no allocation) ----
__device__ float g_deg[NN];
__device__ float g_dis[NN];
__device__ int   g_cnt[NN];
__device__ int   g_rowptr[NN + 1];
__device__ int   g_cursor[NN];
__device__ int   g_csr_src[NE];
__device__ float g_csr_w[NE];
__device__ float g_tx1[NN * 256];             // fp32 tx1 (prop2 input), max Fin=256
__device__ float g_actA[NN * 512];
__device__ float g_actB[NN * 512];
__device__ __nv_bfloat16 g_Abig[NN * 2304];   // split rows, K''max = 9*256 = 2304
// per-layer split weight buffers [N, 3K]
__device__ __nv_bfloat16 g_B1[128 * 1152];
__device__ __nv_bfloat16 g_B2[256 * 1152];
__device__ __nv_bfloat16 g_B3[512 * 2304];
__device__ __nv_bfloat16 g_Bh[512 * 1536];    // [mu(256 rows) | std(256 rows)]

__device__ __forceinline__ uint32_t smem_u32(const void* p) {
    uint32_t a;
    asm("{ .reg .u64 t; cvta.to.shared.u64 t, %1; cvt.u32.u64 %0, t; }" : "=r"(a) : "l"(p));
    return a;
}
__device__ __forceinline__ uint32_t pack_bf16x2(float a, float b) {
    __nv_bfloat162 t = __floats2bfloat162_rn(a, b);
    return *(uint32_t*)&t;
}

// =============== graph preprocessing (4 launches) ===============
__global__ void k_zero2(float* deg, int* cnt, int n) {
    int i = blockIdx.x * blockDim.x + threadIdx.x;
    if (i < n) { deg[i] = 0.f; cnt[i] = 0; }
}
__global__ void k_counts(const int* __restrict__ ei, float* __restrict__ deg,
                         int* __restrict__ cnt) {
    int e = blockIdx.x * blockDim.x + threadIdx.x;
    if (e < NE) {
        atomicAdd(&deg[ei[e]], 1.f);
        atomicAdd(&cnt[ei[NE + e]], 1);
    }
}
// scan over cnt -> rowptr/cursor; also computes dis from deg (elementwise)
__global__ void k_scan(const int* __restrict__ cnt, int* __restrict__ rowptr,
                       int* __restrict__ cursor, const float* __restrict__ deg,
                       float* __restrict__ dis) {
    __shared__ int sh[1024];
    __shared__ int carry;
    int tid = threadIdx.x;
    if (tid == 0) { carry = 0; rowptr[0] = 0; }
    __syncthreads();
    for (int base = 0; base < NN; base += 1024) {
        int i = base + tid;
        if (i < NN) {
            float d = deg[i];
            dis[i] = (d > 0.f) ? rsqrtf(d) : 0.f;
        }
        int v = (i < NN) ? cnt[i] : 0;
        sh[tid] = v;
        __syncthreads();
        for (int off = 1; off < 1024; off <<= 1) {
            int t = (tid >= off) ? sh[tid - off] : 0;
            __syncthreads();
            sh[tid] += t;
            __syncthreads();
        }
        if (i < NN) {
            int inc = carry + sh[tid];
            rowptr[i + 1] = inc;
            cursor[i] = inc - v;
        }
        __syncthreads();
        if (tid == 1023) carry += sh[1023];
        __syncthreads();
    }
}
// scatter with inline edge-weight computation
__global__ void k_scatter(const int* __restrict__ ei, const float* __restrict__ dis,
                          int* __restrict__ cursor, int* __restrict__ csr_src,
                          float* __restrict__ csr_w) {
    int e = blockIdx.x * blockDim.x + threadIdx.x;
    if (e < NE) {
        int r = ei[e];
        int c = ei[NE + e];
        int p = atomicAdd(&cursor[c], 1);
        csr_src[p] = r;
        csr_w[p] = -dis[r] * dis[c];
    }
}

// =============== warp-per-node CSR gather props, fused bf16-split writes ===============
__device__ __forceinline__ void split_write4(__nv_bfloat16* row, int Fin, int pos, float4 v) {
    float hx = __bfloat162float(__float2bfloat16(v.x));
    float hy = __bfloat162float(__float2bfloat16(v.y));
    float hz = __bfloat162float(__float2bfloat16(v.z));
    float hw = __bfloat162float(__float2bfloat16(v.w));
    uint2 hi = make_uint2(pack_bf16x2(v.x, v.y), pack_bf16x2(v.z, v.w));
    uint2 lo = make_uint2(pack_bf16x2(v.x - hx, v.y - hy), pack_bf16x2(v.z - hz, v.w - hw));
    *(uint2*)(row + pos) = hi;
    *(uint2*)(row + 3 * Fin + pos) = lo;
    *(uint2*)(row + 6 * Fin + pos) = hi;
}

__global__ __launch_bounds__(128) void k_gprop1(
    const int* __restrict__ rowptr, const int* __restrict__ csr_src,
    const float* __restrict__ csr_w, const float* __restrict__ x,
    float* __restrict__ tx1, __nv_bfloat16* __restrict__ Abig, int Fin)
{
    int warp = threadIdx.x >> 5, lane = threadIdx.x & 31;
    int n = blockIdx.x * 4 + warp;
    if (n >= NN) return;
    int f = blockIdx.y * 128 + lane * 4;
    int s = rowptr[n], e = rowptr[n + 1];
    float4 acc = make_float4(0.f, 0.f, 0.f, 0.f);
    for (int j0 = s; j0 < e; j0 += 32) {
        int j = j0 + lane;
        int es = 0; float ew = 0.f;
        if (j < e) { es = csr_src[j]; ew = csr_w[j]; }
        int m = min(32, e - j0);
        for (int t = 0; t < m; t++) {
            int src = __shfl_sync(0xffffffffu, es, t);
            float wt = __shfl_sync(0xffffffffu, ew, t);
            float4 xv = *(const float4*)(x + (size_t)src * Fin + f);
            acc.x += wt * xv.x; acc.y += wt * xv.y;
            acc.z += wt * xv.z; acc.w += wt * xv.w;
        }
    }
    float4 x0 = *(const float4*)(x + (size_t)n * Fin + f);
    __nv_bfloat16* row = Abig + (size_t)n * 9 * Fin;
    split_write4(row, Fin, f, x0);
    split_write4(row, Fin, Fin + f, acc);
    *(float4*)(tx1 + (size_t)n * Fin + f) = acc;
}
__global__ __launch_bounds__(128) void k_gprop2(
    const int* __restrict__ rowptr, const int* __restrict__ csr_src,
    const float* __restrict__ csr_w, const float* __restrict__ x,
    const float* __restrict__ tx1, __nv_bfloat16* __restrict__ Abig, int Fin)
{
    int warp = threadIdx.x >> 5, lane = threadIdx.x & 31;
    int n = blockIdx.x * 4 + warp;
    if (n >= NN) return;
    int f = blockIdx.y * 128 + lane * 4;
    int s = rowptr[n], e = rowptr[n + 1];
    float4 acc = make_float4(0.f, 0.f, 0.f, 0.f);
    for (int j0 = s; j0 < e; j0 += 32) {
        int j = j0 + lane;
        int es = 0; float ew = 0.f;
        if (j < e) { es = csr_src[j]; ew = csr_w[j]; }
        int m = min(32, e - j0);
        for (int t = 0; t < m; t++) {
            int src = __shfl_sync(0xffffffffu, es, t);
            float wt = __shfl_sync(0xffffffffu, ew, t);
            float4 xv = *(const float4*)(tx1 + (size_t)src * Fin + f);
            acc.x += wt * xv.x; acc.y += wt * xv.y;
            acc.z += wt * xv.z; acc.w += wt * xv.w;
        }
    }
    float4 x0 = *(const float4*)(x + (size_t)n * Fin + f);
    float4 t2 = make_float4(2.f * acc.x - x0.x, 2.f * acc.y - x0.y,
                            2.f * acc.z - x0.z, 2.f * acc.w - x0.w);
    __nv_bfloat16* row = Abig + (size_t)n * 9 * Fin;
    split_write4(row, Fin, 2 * Fin + f, t2);
}

// =============== B weight split conversion ===============
__global__ void k_wconv(const float* __restrict__ W, __nv_bfloat16* __restrict__ B,
                        int K, int N) {
    int i = blockIdx.x * blockDim.x + threadIdx.x;
    if (i < K * N) {
        int k = i / N;
        int n = i - k * N;
        float x = W[i];
        __nv_bfloat16 hi = __float2bfloat16(x);
        __nv_bfloat16 lo = __float2bfloat16(x - __bfloat162float(hi));
        __nv_bfloat16* row = B + (size_t)n * 3 * K;
        row[k] = hi;
        row[K + k] = hi;
        row[2 * K + k] = lo;
    }
}

// =============== mma.sync bf16 GEMM, 64x128 tile, 4-stage cp.async ===============
#define LDT 40
#define NSTAGE 4
#define A_ELEMS (64 * LDT)
#define B_ELEMS (128 * LDT)

__device__ __forceinline__ void ldm_x4(uint32_t& r0, uint32_t& r1, uint32_t& r2, uint32_t& r3,
                                       uint32_t a) {
    asm volatile("ldmatrix.sync.aligned.m8n8.x4.shared.b16 {%0,%1,%2,%3}, [%4];"
                 : "=r"(r0), "=r"(r1), "=r"(r2), "=r"(r3) : "r"(a));
}
__device__ __forceinline__ void mma_bf16(float* c, const uint32_t* a, const uint32_t* b) {
    asm volatile(
        "mma.sync.aligned.m16n8k16.row.col.f32.bf16.bf16.f32 "
        "{%0,%1,%2,%3}, {%4,%5,%6,%7}, {%8,%9}, {%0,%1,%2,%3};"
        : "+f"(c[0]), "+f"(c[1]), "+f"(c[2]), "+f"(c[3])
        : "r"(a[0]), "r"(a[1]), "r"(a[2]), "r"(a[3]), "r"(b[0]), "r"(b[1]));
}
__device__ __forceinline__ void cp16(uint32_t dst, const void* src, int pred16) {
    asm volatile("cp.async.cg.shared.global [%0], [%1], 16, %2;"
                 :: "r"(dst), "l"(src), "r"(pred16) : "memory");
}

__global__ __launch_bounds__(256) void k_mgemm(
    const __nv_bfloat16* __restrict__ A, const __nv_bfloat16* __restrict__ B,
    const float* __restrict__ bias0, const float* __restrict__ bias1,
    float* __restrict__ C0, float* __restrict__ C1,
    __nv_bfloat16* __restrict__ Asplit,
    int M, int Kbig, int ldc, int relu, int split)
{
    extern __shared__ __align__(16) __nv_bfloat16 smp[];
    __nv_bfloat16* sAp = smp;
    __nv_bfloat16* sBp = smp + NSTAGE * A_ELEMS;

    const int tid = threadIdx.x;
    const int wid = tid >> 5;
    const int lane = tid & 31;
    const int bm = blockIdx.y * 64;
    const int bn = blockIdx.x * 128;
    const int warp_m = (wid & 1) * 32;
    const int warp_n = (wid >> 1) * 32;

    float acc[2][4][4];
#pragma unroll
    for (int i = 0; i < 2; i++)
#pragma unroll
        for (int j = 0; j < 4; j++)
#pragma unroll
            for (int q = 0; q < 4; q++) acc[i][j][q] = 0.f;

    uint32_t sA_u[NSTAGE], sB_u[NSTAGE];
#pragma unroll
    for (int s = 0; s < NSTAGE; s++) {
        sA_u[s] = smem_u32(sAp + s * A_ELEMS);
        sB_u[s] = smem_u32(sBp + s * B_ELEMS);
    }
    const int niter = Kbig >> 5;

    const int ar = tid >> 2, ac = tid & 3;

    auto issue = [&](int stage, int k0) {
        cp16(sA_u[stage] + (ar * LDT + ac * 8) * 2,
             A + (size_t)(bm + ar) * Kbig + k0 + ac * 8, (bm + ar) < M ? 16 : 0);
#pragma unroll
        for (int h = 0; h < 2; h++) {
            int idx = tid + h * 256;
            int br = idx >> 2, bc = idx & 3;
            cp16(sB_u[stage] + (br * LDT + bc * 8) * 2,
                 B + (size_t)(bn + br) * Kbig + k0 + bc * 8, 16);
        }
        asm volatile("cp.async.commit_group;" ::: "memory");
    };

    issue(0, 0);
    issue(1, 32);
    issue(2, 64);

    for (int it = 0; it < niter; it++) {
        const int stage = it & (NSTAGE - 1);
        const int ahead = niter - 1 - it;
        if (ahead >= 2)      asm volatile("cp.async.wait_group 2;" ::: "memory");
        else if (ahead == 1) asm volatile("cp.async.wait_group 1;" ::: "memory");
        else                 asm volatile("cp.async.wait_group 0;" ::: "memory");
        __syncthreads();

        if (it + 3 < niter) issue((it + 3) & (NSTAGE - 1), (it + 3) << 5);

#pragma unroll
        for (int ks = 0; ks < 2; ks++) {
            uint32_t af[2][4];
            uint32_t bf[4][2];
#pragma unroll
            for (int mf = 0; mf < 2; mf++) {
                uint32_t addr = sA_u[stage] +
                    ((warp_m + mf * 16 + (lane & 15)) * LDT + ks * 16 + (lane >> 4) * 8) * 2;
                ldm_x4(af[mf][0], af[mf][1], af[mf][2], af[mf][3], addr);
            }
            // B frags via x4: one instr covers two n8 frags (16 rows x 16 cols)
#pragma unroll
            for (int nfp = 0; nfp < 2; nfp++) {
                uint32_t addr = sB_u[stage] +
                    ((warp_n + nfp * 16 + (lane & 15)) * LDT + ks * 16 + (lane >> 4) * 8) * 2;
                uint32_t r0, r1, r2, r3;
                ldm_x4(r0, r1, r2, r3, addr);
                bf[nfp * 2 + 0][0] = r0; bf[nfp * 2 + 1][0] = r1;
                bf[nfp * 2 + 0][1] = r2; bf[nfp * 2 + 1][1] = r3;
            }
#pragma unroll
            for (int mf = 0; mf < 2; mf++)
#pragma unroll
                for (int nf = 0; nf < 4; nf++)
                    mma_bf16(acc[mf][nf], af[mf], bf[nf]);
        }
    }

    // epilogue
#pragma unroll
    for (int mf = 0; mf < 2; mf++) {
#pragma unroll
        for (int nf = 0; nf < 4; nf++) {
            int row0 = bm + warp_m + mf * 16 + (lane >> 2);
            int col0 = bn + warp_n + nf * 8 + (lane & 3) * 2;
#pragma unroll
            for (int h = 0; h < 2; h++) {
                int row = row0 + h * 8;
                if (row >= M) continue;
                float v0 = acc[mf][nf][h * 2 + 0];
                float v1 = acc[mf][nf][h * 2 + 1];
                if (Asplit) {
                    v0 += bias0[col0]; v1 += bias0[col0 + 1];
                    if (relu) { v0 = fmaxf(v0, 0.f); v1 = fmaxf(v1, 0.f); }
                    float h0 = __bfloat162float(__float2bfloat16(v0));
                    float h1 = __bfloat162float(__float2bfloat16(v1));
                    uint32_t hi = pack_bf16x2(v0, v1);
                    uint32_t lo = pack_bf16x2(v0 - h0, v1 - h1);
                    __nv_bfloat16* arow = Asplit + (size_t)row * 3 * ldc;
                    *(uint32_t*)(arow + col0) = hi;
                    *(uint32_t*)(arow + ldc + col0) = lo;
                    *(uint32_t*)(arow + 2 * ldc + col0) = hi;
                } else {
                    bool second = col0 >= split;
                    const float* bs = second ? bias1 : bias0;
                    float* dst = second ? C1 : C0;
                    int cc = second ? col0 - split : col0;
                    v0 += bs[cc]; v1 += bs[cc + 1];
                    if (relu) { v0 = fmaxf(v0, 0.f); v1 = fmaxf(v1, 0.f); }
                    *(float2*)(dst + (size_t)row * ldc + cc) = make_float2(v0, v1);
                }
            }
        }
    }
}

// =============== host orchestration ===============
#define SMEM_BYTES (NSTAGE * (A_ELEMS + B_ELEMS) * 2)

static void launch_gemm(const __nv_bfloat16* A, const __nv_bfloat16* B,
                        const float* bias0, const float* bias1,
                        float* C0, float* C1, __nv_bfloat16* Asplit,
                        int Kbig, int N, int ldc, int relu, int split) {
    dim3 grid(N / 128, (NN + 63) / 64);
    k_mgemm<<<grid, 256, SMEM_BYTES>>>(A, B, bias0, bias1, C0, C1, Asplit,
                                       NN, Kbig, ldc, relu, split);
}

static void run_layer(const int* rowptr, const int* csr_src, const float* csr_w,
                      float* tx1, __nv_bfloat16* Abig, const __nv_bfloat16* Bbig,
                      const float* x, int Fin, int Fout,
                      const float* b, float* y, __nv_bfloat16* Asplit) {
    dim3 pg((NN + 3) / 4, Fin / 128);
    k_gprop1<<<pg, 128>>>(rowptr, csr_src, csr_w, x, tx1, Abig, Fin);
    k_gprop2<<<pg, 128>>>(rowptr, csr_src, csr_w, x, tx1, Abig, Fin);
    launch_gemm(Abig, Bbig, b, b, y, y, Asplit, 9 * Fin, Fout, Fout, 1, Fout);
}

extern "C" void kernel_launch(void* const* d_in, const int* in_sizes, int n_in,
                              void* d_out, int out_size) {
    const float* v    = (const float*)d_in[0];
    const int* ei     = (const int*)d_in[1];
    const float* W1   = (const float*)d_in[2];
    const float* b1   = (const float*)d_in[3];
    const float* W2   = (const float*)d_in[4];
    const float* b2   = (const float*)d_in[5];
    const float* W3   = (const float*)d_in[6];
    const float* b3   = (const float*)d_in[7];
    const float* Wmu  = (const float*)d_in[8];
    const float* bmu  = (const float*)d_in[9];
    const float* Wstd = (const float*)d_in[10];
    const float* bstd = (const float*)d_in[11];
    float* out = (float*)d_out;

    static bool init_done = false;
    static cudaStream_t s2;
    static cudaEvent_t evFork, evDone;
    if (!init_done) {
        cudaFuncSetAttribute(k_mgemm, cudaFuncAttributeMaxDynamicSharedMemorySize, SMEM_BYTES);
        cudaStreamCreateWithFlags(&s2, cudaStreamNonBlocking);
        cudaEventCreateWithFlags(&evFork, cudaEventDisableTiming);
        cudaEventCreateWithFlags(&evDone, cudaEventDisableTiming);
        init_done = true;
    }

    float *deg, *dis, *tx1, *actA, *actB, *csr_w;
    int *cnt, *rowptr, *cursor, *csr_src;
    __nv_bfloat16 *Abig, *B1, *B2, *B3, *Bh;
    cudaGetSymbolAddress((void**)&deg,     g_deg);
    cudaGetSymbolAddress((void**)&dis,     g_dis);
    cudaGetSymbolAddress((void**)&cnt,     g_cnt);
    cudaGetSymbolAddress((void**)&rowptr,  g_rowptr);
    cudaGetSymbolAddress((void**)&cursor,  g_cursor);
    cudaGetSymbolAddress((void**)&csr_src, g_csr_src);
    cudaGetSymbolAddress((void**)&csr_w,   g_csr_w);
    cudaGetSymbolAddress((void**)&tx1,     g_tx1);
    cudaGetSymbolAddress((void**)&actA,    g_actA);
    cudaGetSymbolAddress((void**)&actB,    g_actB);
    cudaGetSymbolAddress((void**)&Abig,    g_Abig);
    cudaGetSymbolAddress((void**)&B1,      g_B1);
    cudaGetSymbolAddress((void**)&B2,      g_B2);
    cudaGetSymbolAddress((void**)&B3,      g_B3);
    cudaGetSymbolAddress((void**)&Bh,      g_Bh);

    // fork side stream: all 5 weight conversions off the critical path
    cudaEventRecord(evFork, 0);
    cudaStreamWaitEvent(s2, evFork, 0);
    k_wconv<<<(128 * 384 + 255) / 256, 256, 0, s2>>>(W1, B1, 384, 128);
    k_wconv<<<(256 * 384 + 255) / 256, 256, 0, s2>>>(W2, B2, 384, 256);
    k_wconv<<<(512 * 768 + 255) / 256, 256, 0, s2>>>(W3, B3, 768, 512);
    k_wconv<<<(256 * 512 + 255) / 256, 256, 0, s2>>>(Wmu,  Bh, 512, 256);
    k_wconv<<<(256 * 512 + 255) / 256, 256, 0, s2>>>(Wstd, Bh + (size_t)256 * 1536, 512, 256);
    cudaEventRecord(evDone, s2);

    // graph preprocessing (main stream)
    k_zero2<<<(NN + 255) / 256, 256>>>(deg, cnt, NN);
    k_counts<<<(NE + 255) / 256, 256>>>(ei, deg, cnt);
    k_scan<<<1, 1024>>>(cnt, rowptr, cursor, deg, dis);
    k_scatter<<<(NE + 255) / 256, 256>>>(ei, dis, cursor, csr_src, csr_w);

    // L1 props, then join side stream before first GEMM
    dim3 pg1((NN + 3) / 4, 1);
    k_gprop1<<<pg1, 128>>>(rowptr, csr_src, csr_w, v, tx1, Abig, 128);
    k_gprop2<<<pg1, 128>>>(rowptr, csr_src, csr_w, v, tx1, Abig, 128);
    cudaStreamWaitEvent(0, evDone, 0);
    launch_gemm(Abig, B1, b1, b1, actA, actA, nullptr, 1152, 128, 128, 1, 128);

    // L2, L3 (L3 writes bf16 split rows directly into Abig)
    run_layer(rowptr, csr_src, csr_w, tx1, Abig, B2, actA, 128, 256, b2, actB, nullptr);
    run_layer(rowptr, csr_src, csr_w, tx1, Abig, B3, actB, 256, 512, b3, nullptr, Abig);

    // fused heads: one N=512 GEMM on split A (K''=1536), split output mu|std
    launch_gemm(Abig, Bh, bmu, bstd, out, out + (size_t)NN * 256, nullptr,
                1536, 512, 256, 0, 256);

    (void)in_sizes; (void)n_in; (void)out_size;
}

// round 10
// speedup vs baseline: 3.4100x; 1.3197x over previous
#include <cuda_runtime.h>
#include <cuda_fp16.h>
#include <math.h>
#include <stdint.h>

#define NN 10000
#define NE 160000

// ---- scratch (static device globals; no allocation) ----
__device__ float g_deg[NN];
__device__ float g_dis[NN];
__device__ int   g_cnt[NN];
__device__ int   g_rowptr[NN + 1];
__device__ int   g_cursor[NN];
__device__ int   g_csr_src[NE];
__device__ float g_csr_w[NE];
__device__ float g_tx1[NN * 256];            // fp32 tx1 (prop2 input), max Fin=256
__device__ float g_actA[NN * 512];
__device__ float g_actB[NN * 512];
__device__ __half g_Abig[NN * 1536];         // [hi|lo] split rows, K''max = 6*256 = 1536
// per-layer split weight buffers [N, 2*(3K)] = [hi|hi]
__device__ __half g_B1[128 * 768];
__device__ __half g_B2[256 * 768];
__device__ __half g_B3[512 * 1536];
__device__ __half g_Bh[512 * 1024];          // [mu(256 rows) | std(256 rows)]

__device__ __forceinline__ uint32_t smem_u32(const void* p) {
    uint32_t a;
    asm("{ .reg .u64 t; cvta.to.shared.u64 t, %1; cvt.u32.u64 %0, t; }" : "=r"(a) : "l"(p));
    return a;
}
__device__ __forceinline__ uint32_t pack_h2(float a, float b) {
    __half2 t = __floats2half2_rn(a, b);     // .x=a (low addr), .y=b
    return *(uint32_t*)&t;
}

// =============== graph preprocessing (4 launches) ===============
__global__ void k_zero2(float* deg, int* cnt, int n) {
    int i = blockIdx.x * blockDim.x + threadIdx.x;
    if (i < n) { deg[i] = 0.f; cnt[i] = 0; }
}
__global__ void k_counts(const int* __restrict__ ei, float* __restrict__ deg,
                         int* __restrict__ cnt) {
    int e = blockIdx.x * blockDim.x + threadIdx.x;
    if (e < NE) {
        atomicAdd(&deg[ei[e]], 1.f);
        atomicAdd(&cnt[ei[NE + e]], 1);
    }
}
__global__ void k_scan(const int* __restrict__ cnt, int* __restrict__ rowptr,
                       int* __restrict__ cursor, const float* __restrict__ deg,
                       float* __restrict__ dis) {
    __shared__ int sh[1024];
    __shared__ int carry;
    int tid = threadIdx.x;
    if (tid == 0) { carry = 0; rowptr[0] = 0; }
    __syncthreads();
    for (int base = 0; base < NN; base += 1024) {
        int i = base + tid;
        if (i < NN) {
            float d = deg[i];
            dis[i] = (d > 0.f) ? rsqrtf(d) : 0.f;
        }
        int v = (i < NN) ? cnt[i] : 0;
        sh[tid] = v;
        __syncthreads();
        for (int off = 1; off < 1024; off <<= 1) {
            int t = (tid >= off) ? sh[tid - off] : 0;
            __syncthreads();
            sh[tid] += t;
            __syncthreads();
        }
        if (i < NN) {
            int inc = carry + sh[tid];
            rowptr[i + 1] = inc;
            cursor[i] = inc - v;
        }
        __syncthreads();
        if (tid == 1023) carry += sh[1023];
        __syncthreads();
    }
}
__global__ void k_scatter(const int* __restrict__ ei, const float* __restrict__ dis,
                          int* __restrict__ cursor, int* __restrict__ csr_src,
                          float* __restrict__ csr_w) {
    int e = blockIdx.x * blockDim.x + threadIdx.x;
    if (e < NE) {
        int r = ei[e];
        int c = ei[NE + e];
        int p = atomicAdd(&cursor[c], 1);
        csr_src[p] = r;
        csr_w[p] = -dis[r] * dis[c];
    }
}

// =============== warp-per-node CSR gather props, fused fp16-split writes ===============
// Abig row layout (len 6*Fin): [hi(tx0)|hi(tx1)|hi(tx2) | lo(tx0)|lo(tx1)|lo(tx2)]
__device__ __forceinline__ void split_write4(__half* row, int Fin, int pos, float4 v) {
    float hx = __half2float(__float2half_rn(v.x));
    float hy = __half2float(__float2half_rn(v.y));
    float hz = __half2float(__float2half_rn(v.z));
    float hw = __half2float(__float2half_rn(v.w));
    uint2 hi = make_uint2(pack_h2(v.x, v.y), pack_h2(v.z, v.w));
    uint2 lo = make_uint2(pack_h2(v.x - hx, v.y - hy), pack_h2(v.z - hz, v.w - hw));
    *(uint2*)(row + pos) = hi;
    *(uint2*)(row + 3 * Fin + pos) = lo;
}

__global__ __launch_bounds__(128) void k_gprop1(
    const int* __restrict__ rowptr, const int* __restrict__ csr_src,
    const float* __restrict__ csr_w, const float* __restrict__ x,
    float* __restrict__ tx1, __half* __restrict__ Abig, int Fin)
{
    int warp = threadIdx.x >> 5, lane = threadIdx.x & 31;
    int n = blockIdx.x * 4 + warp;
    if (n >= NN) return;
    int f = blockIdx.y * 128 + lane * 4;
    int s = rowptr[n], e = rowptr[n + 1];
    float4 acc = make_float4(0.f, 0.f, 0.f, 0.f);
    for (int j0 = s; j0 < e; j0 += 32) {
        int j = j0 + lane;
        int es = 0; float ew = 0.f;
        if (j < e) { es = csr_src[j]; ew = csr_w[j]; }
        int m = min(32, e - j0);
        for (int t = 0; t < m; t++) {
            int src = __shfl_sync(0xffffffffu, es, t);
            float wt = __shfl_sync(0xffffffffu, ew, t);
            float4 xv = *(const float4*)(x + (size_t)src * Fin + f);
            acc.x += wt * xv.x; acc.y += wt * xv.y;
            acc.z += wt * xv.z; acc.w += wt * xv.w;
        }
    }
    float4 x0 = *(const float4*)(x + (size_t)n * Fin + f);
    __half* row = Abig + (size_t)n * 6 * Fin;
    split_write4(row, Fin, f, x0);
    split_write4(row, Fin, Fin + f, acc);
    *(float4*)(tx1 + (size_t)n * Fin + f) = acc;
}
__global__ __launch_bounds__(128) void k_gprop2(
    const int* __restrict__ rowptr, const int* __restrict__ csr_src,
    const float* __restrict__ csr_w, const float* __restrict__ x,
    const float* __restrict__ tx1, __half* __restrict__ Abig, int Fin)
{
    int warp = threadIdx.x >> 5, lane = threadIdx.x & 31;
    int n = blockIdx.x * 4 + warp;
    if (n >= NN) return;
    int f = blockIdx.y * 128 + lane * 4;
    int s = rowptr[n], e = rowptr[n + 1];
    float4 acc = make_float4(0.f, 0.f, 0.f, 0.f);
    for (int j0 = s; j0 < e; j0 += 32) {
        int j = j0 + lane;
        int es = 0; float ew = 0.f;
        if (j < e) { es = csr_src[j]; ew = csr_w[j]; }
        int m = min(32, e - j0);
        for (int t = 0; t < m; t++) {
            int src = __shfl_sync(0xffffffffu, es, t);
            float wt = __shfl_sync(0xffffffffu, ew, t);
            float4 xv = *(const float4*)(tx1 + (size_t)src * Fin + f);
            acc.x += wt * xv.x; acc.y += wt * xv.y;
            acc.z += wt * xv.z; acc.w += wt * xv.w;
        }
    }
    float4 x0 = *(const float4*)(x + (size_t)n * Fin + f);
    float4 t2 = make_float4(2.f * acc.x - x0.x, 2.f * acc.y - x0.y,
                            2.f * acc.z - x0.z, 2.f * acc.w - x0.w);
    __half* row = Abig + (size_t)n * 6 * Fin;
    split_write4(row, Fin, 2 * Fin + f, t2);
}

// =============== B weight conversion: W[K,N] -> rows of 2K: [hi|hi] ===============
__global__ void k_wconv(const float* __restrict__ W, __half* __restrict__ B,
                        int K, int N) {
    int i = blockIdx.x * blockDim.x + threadIdx.x;
    if (i < K * N) {
        int k = i / N;
        int n = i - k * N;
        __half hi = __float2half_rn(W[i]);
        __half* row = B + (size_t)n * 2 * K;
        row[k] = hi;
        row[K + k] = hi;
    }
}

// =============== mma.sync fp16 GEMM, 64x128 tile, 4-stage cp.async ===============
#define LDT 40
#define NSTAGE 4
#define A_ELEMS (64 * LDT)
#define B_ELEMS (128 * LDT)

__device__ __forceinline__ void ldm_x4(uint32_t& r0, uint32_t& r1, uint32_t& r2, uint32_t& r3,
                                       uint32_t a) {
    asm volatile("ldmatrix.sync.aligned.m8n8.x4.shared.b16 {%0,%1,%2,%3}, [%4];"
                 : "=r"(r0), "=r"(r1), "=r"(r2), "=r"(r3) : "r"(a));
}
__device__ __forceinline__ void mma_f16(float* c, const uint32_t* a, const uint32_t* b) {
    asm volatile(
        "mma.sync.aligned.m16n8k16.row.col.f32.f16.f16.f32 "
        "{%0,%1,%2,%3}, {%4,%5,%6,%7}, {%8,%9}, {%0,%1,%2,%3};"
        : "+f"(c[0]), "+f"(c[1]), "+f"(c[2]), "+f"(c[3])
        : "r"(a[0]), "r"(a[1]), "r"(a[2]), "r"(a[3]), "r"(b[0]), "r"(b[1]));
}
__device__ __forceinline__ void cp16(uint32_t dst, const void* src, int pred16) {
    asm volatile("cp.async.cg.shared.global [%0], [%1], 16, %2;"
                 :: "r"(dst), "l"(src), "r"(pred16) : "memory");
}

// If Asplit != 0: write [hi|lo] fp16 rows (len 2*ldc) instead of fp32 C.
// Else: cols < split -> C0 (+bias0), else C1 (+bias1).
__global__ __launch_bounds__(256) void k_mgemm(
    const __half* __restrict__ A, const __half* __restrict__ B,
    const float* __restrict__ bias0, const float* __restrict__ bias1,
    float* __restrict__ C0, float* __restrict__ C1,
    __half* __restrict__ Asplit,
    int M, int Kbig, int ldc, int relu, int split)
{
    extern __shared__ __align__(16) __half smp[];
    __half* sAp = smp;
    __half* sBp = smp + NSTAGE * A_ELEMS;

    const int tid = threadIdx.x;
    const int wid = tid >> 5;
    const int lane = tid & 31;
    const int bm = blockIdx.y * 64;
    const int bn = blockIdx.x * 128;
    const int warp_m = (wid & 1) * 32;
    const int warp_n = (wid >> 1) * 32;

    float acc[2][4][4];
#pragma unroll
    for (int i = 0; i < 2; i++)
#pragma unroll
        for (int j = 0; j < 4; j++)
#pragma unroll
            for (int q = 0; q < 4; q++) acc[i][j][q] = 0.f;

    uint32_t sA_u[NSTAGE], sB_u[NSTAGE];
#pragma unroll
    for (int s = 0; s < NSTAGE; s++) {
        sA_u[s] = smem_u32(sAp + s * A_ELEMS);
        sB_u[s] = smem_u32(sBp + s * B_ELEMS);
    }
    const int niter = Kbig >> 5;

    const int ar = tid >> 2, ac = tid & 3;

    auto issue = [&](int stage, int k0) {
        cp16(sA_u[stage] + (ar * LDT + ac * 8) * 2,
             A + (size_t)(bm + ar) * Kbig + k0 + ac * 8, (bm + ar) < M ? 16 : 0);
#pragma unroll
        for (int h = 0; h < 2; h++) {
            int idx = tid + h * 256;
            int br = idx >> 2, bc = idx & 3;
            cp16(sB_u[stage] + (br * LDT + bc * 8) * 2,
                 B + (size_t)(bn + br) * Kbig + k0 + bc * 8, 16);
        }
        asm volatile("cp.async.commit_group;" ::: "memory");
    };

    issue(0, 0);
    issue(1, 32);
    issue(2, 64);

    for (int it = 0; it < niter; it++) {
        const int stage = it & (NSTAGE - 1);
        const int ahead = niter - 1 - it;
        if (ahead >= 2)      asm volatile("cp.async.wait_group 2;" ::: "memory");
        else if (ahead == 1) asm volatile("cp.async.wait_group 1;" ::: "memory");
        else                 asm volatile("cp.async.wait_group 0;" ::: "memory");
        __syncthreads();

        if (it + 3 < niter) issue((it + 3) & (NSTAGE - 1), (it + 3) << 5);

#pragma unroll
        for (int ks = 0; ks < 2; ks++) {
            uint32_t af[2][4];
            uint32_t bf[4][2];
#pragma unroll
            for (int mf = 0; mf < 2; mf++) {
                uint32_t addr = sA_u[stage] +
                    ((warp_m + mf * 16 + (lane & 15)) * LDT + ks * 16 + (lane >> 4) * 8) * 2;
                ldm_x4(af[mf][0], af[mf][1], af[mf][2], af[mf][3], addr);
            }
#pragma unroll
            for (int nfp = 0; nfp < 2; nfp++) {
                uint32_t addr = sB_u[stage] +
                    ((warp_n + nfp * 16 + (lane & 15)) * LDT + ks * 16 + (lane >> 4) * 8) * 2;
                uint32_t r0, r1, r2, r3;
                ldm_x4(r0, r1, r2, r3, addr);
                bf[nfp * 2 + 0][0] = r0; bf[nfp * 2 + 1][0] = r1;
                bf[nfp * 2 + 0][1] = r2; bf[nfp * 2 + 1][1] = r3;
            }
#pragma unroll
            for (int mf = 0; mf < 2; mf++)
#pragma unroll
                for (int nf = 0; nf < 4; nf++)
                    mma_f16(acc[mf][nf], af[mf], bf[nf]);
        }
    }

    // epilogue
#pragma unroll
    for (int mf = 0; mf < 2; mf++) {
#pragma unroll
        for (int nf = 0; nf < 4; nf++) {
            int row0 = bm + warp_m + mf * 16 + (lane >> 2);
            int col0 = bn + warp_n + nf * 8 + (lane & 3) * 2;
#pragma unroll
            for (int h = 0; h < 2; h++) {
                int row = row0 + h * 8;
                if (row >= M) continue;
                float v0 = acc[mf][nf][h * 2 + 0];
                float v1 = acc[mf][nf][h * 2 + 1];
                if (Asplit) {
                    v0 += bias0[col0]; v1 += bias0[col0 + 1];
                    if (relu) { v0 = fmaxf(v0, 0.f); v1 = fmaxf(v1, 0.f); }
                    float h0 = __half2float(__float2half_rn(v0));
                    float h1 = __half2float(__float2half_rn(v1));
                    uint32_t hi = pack_h2(v0, v1);
                    uint32_t lo = pack_h2(v0 - h0, v1 - h1);
                    __half* arow = Asplit + (size_t)row * 2 * ldc;
                    *(uint32_t*)(arow + col0) = hi;
                    *(uint32_t*)(arow + ldc + col0) = lo;
                } else {
                    bool second = col0 >= split;
                    const float* bs = second ? bias1 : bias0;
                    float* dst = second ? C1 : C0;
                    int cc = second ? col0 - split : col0;
                    v0 += bs[cc]; v1 += bs[cc + 1];
                    if (relu) { v0 = fmaxf(v0, 0.f); v1 = fmaxf(v1, 0.f); }
                    *(float2*)(dst + (size_t)row * ldc + cc) = make_float2(v0, v1);
                }
            }
        }
    }
}

// =============== host orchestration ===============
#define SMEM_BYTES (NSTAGE * (A_ELEMS + B_ELEMS) * 2)

static void launch_gemm(const __half* A, const __half* B,
                        const float* bias0, const float* bias1,
                        float* C0, float* C1, __half* Asplit,
                        int Kbig, int N, int ldc, int relu, int split) {
    dim3 grid(N / 128, (NN + 63) / 64);
    k_mgemm<<<grid, 256, SMEM_BYTES>>>(A, B, bias0, bias1, C0, C1, Asplit,
                                       NN, Kbig, ldc, relu, split);
}

static void run_layer(const int* rowptr, const int* csr_src, const float* csr_w,
                      float* tx1, __half* Abig, const __half* Bbig,
                      const float* x, int Fin, int Fout,
                      const float* b, float* y, __half* Asplit) {
    dim3 pg((NN + 3) / 4, Fin / 128);
    k_gprop1<<<pg, 128>>>(rowptr, csr_src, csr_w, x, tx1, Abig, Fin);
    k_gprop2<<<pg, 128>>>(rowptr, csr_src, csr_w, x, tx1, Abig, Fin);
    launch_gemm(Abig, Bbig, b, b, y, y, Asplit, 6 * Fin, Fout, Fout, 1, Fout);
}

extern "C" void kernel_launch(void* const* d_in, const int* in_sizes, int n_in,
                              void* d_out, int out_size) {
    const float* v    = (const float*)d_in[0];
    const int* ei     = (const int*)d_in[1];
    const float* W1   = (const float*)d_in[2];
    const float* b1   = (const float*)d_in[3];
    const float* W2   = (const float*)d_in[4];
    const float* b2   = (const float*)d_in[5];
    const float* W3   = (const float*)d_in[6];
    const float* b3   = (const float*)d_in[7];
    const float* Wmu  = (const float*)d_in[8];
    const float* bmu  = (const float*)d_in[9];
    const float* Wstd = (const float*)d_in[10];
    const float* bstd = (const float*)d_in[11];
    float* out = (float*)d_out;

    static bool init_done = false;
    static cudaStream_t s2;
    static cudaEvent_t evFork, evDone;
    if (!init_done) {
        cudaFuncSetAttribute(k_mgemm, cudaFuncAttributeMaxDynamicSharedMemorySize, SMEM_BYTES);
        cudaStreamCreateWithFlags(&s2, cudaStreamNonBlocking);
        cudaEventCreateWithFlags(&evFork, cudaEventDisableTiming);
        cudaEventCreateWithFlags(&evDone, cudaEventDisableTiming);
        init_done = true;
    }

    float *deg, *dis, *tx1, *actA, *actB, *csr_w;
    int *cnt, *rowptr, *cursor, *csr_src;
    __half *Abig, *B1, *B2, *B3, *Bh;
    cudaGetSymbolAddress((void**)&deg,     g_deg);
    cudaGetSymbolAddress((void**)&dis,     g_dis);
    cudaGetSymbolAddress((void**)&cnt,     g_cnt);
    cudaGetSymbolAddress((void**)&rowptr,  g_rowptr);
    cudaGetSymbolAddress((void**)&cursor,  g_cursor);
    cudaGetSymbolAddress((void**)&csr_src, g_csr_src);
    cudaGetSymbolAddress((void**)&csr_w,   g_csr_w);
    cudaGetSymbolAddress((void**)&tx1,     g_tx1);
    cudaGetSymbolAddress((void**)&actA,    g_actA);
    cudaGetSymbolAddress((void**)&actB,    g_actB);
    cudaGetSymbolAddress((void**)&Abig,    g_Abig);
    cudaGetSymbolAddress((void**)&B1,      g_B1);
    cudaGetSymbolAddress((void**)&B2,      g_B2);
    cudaGetSymbolAddress((void**)&B3,      g_B3);
    cudaGetSymbolAddress((void**)&Bh,      g_Bh);

    // fork side stream: weight conversions off the critical path
    cudaEventRecord(evFork, 0);
    cudaStreamWaitEvent(s2, evFork, 0);
    k_wconv<<<(128 * 384 + 255) / 256, 256, 0, s2>>>(W1, B1, 384, 128);
    k_wconv<<<(256 * 384 + 255) / 256, 256, 0, s2>>>(W2, B2, 384, 256);
    k_wconv<<<(512 * 768 + 255) / 256, 256, 0, s2>>>(W3, B3, 768, 512);
    k_wconv<<<(256 * 512 + 255) / 256, 256, 0, s2>>>(Wmu,  Bh, 512, 256);
    k_wconv<<<(256 * 512 + 255) / 256, 256, 0, s2>>>(Wstd, Bh + (size_t)256 * 1024, 512, 256);
    cudaEventRecord(evDone, s2);

    // graph preprocessing (main stream)
    k_zero2<<<(NN + 255) / 256, 256>>>(deg, cnt, NN);
    k_counts<<<(NE + 255) / 256, 256>>>(ei, deg, cnt);
    k_scan<<<1, 1024>>>(cnt, rowptr, cursor, deg, dis);
    k_scatter<<<(NE + 255) / 256, 256>>>(ei, dis, cursor, csr_src, csr_w);

    // L1 props, then join side stream before first GEMM
    dim3 pg1((NN + 3) / 4, 1);
    k_gprop1<<<pg1, 128>>>(rowptr, csr_src, csr_w, v, tx1, Abig, 128);
    k_gprop2<<<pg1, 128>>>(rowptr, csr_src, csr_w, v, tx1, Abig, 128);
    cudaStreamWaitEvent(0, evDone, 0);
    launch_gemm(Abig, B1, b1, b1, actA, actA, nullptr, 768, 128, 128, 1, 128);

    // L2, L3 (L3 writes fp16 split rows directly into Abig)
    run_layer(rowptr, csr_src, csr_w, tx1, Abig, B2, actA, 128, 256, b2, actB, nullptr);
    run_layer(rowptr, csr_src, csr_w, tx1, Abig, B3, actB, 256, 512, b3, nullptr, Abig);

    // fused heads: one N=512 GEMM on split A (K''=1024), split output mu|std
    launch_gemm(Abig, Bh, bmu, bstd, out, out + (size_t)NN * 256, nullptr,
                1024, 512, 256, 0, 256);

    (void)in_sizes; (void)n_in; (void)out_size;
}

// round 11
// speedup vs baseline: 3.6125x; 1.0594x over previous
#include <cuda_runtime.h>
#include <cuda_fp16.h>
#include <math.h>
#include <stdint.h>

#define NN 10000
#define NE 160000

// ---- scratch (static device globals; zero-initialized at module load) ----
__device__ float g_deg[NN];
__device__ float g_dis[NN];
__device__ int   g_cnt[NN];
__device__ int   g_rowptr[NN + 1];
__device__ int   g_cursor[NN];
__device__ int   g_csr_src[NE];
__device__ float g_csr_w[NE];
__device__ float g_tx1[NN * 256];
__device__ float g_actA[NN * 512];
__device__ float g_actB[NN * 512];
__device__ __half g_Abig[NN * 1536];         // [hi|lo] split rows, K''max = 6*256
__device__ __half g_B1[128 * 768];
__device__ __half g_B2[256 * 768];
__device__ __half g_B3[512 * 1536];
__device__ __half g_Bh[512 * 1024];          // [mu(256 rows) | std(256 rows)]

__device__ __forceinline__ uint32_t smem_u32(const void* p) {
    uint32_t a;
    asm("{ .reg .u64 t; cvta.to.shared.u64 t, %1; cvt.u32.u64 %0, t; }" : "=r"(a) : "l"(p));
    return a;
}
__device__ __forceinline__ uint32_t pack_h2(float a, float b) {
    __half2 t = __floats2half2_rn(a, b);
    return *(uint32_t*)&t;
}

// =============== graph preprocessing ===============
__global__ void k_zero2(float* deg, int* cnt, int n) {
    int i = blockIdx.x * blockDim.x + threadIdx.x;
    if (i < n) { deg[i] = 0.f; cnt[i] = 0; }
}
__global__ void k_counts(const int* __restrict__ ei, float* __restrict__ deg,
                         int* __restrict__ cnt) {
    int e = blockIdx.x * blockDim.x + threadIdx.x;
    if (e < NE) {
        atomicAdd(&deg[ei[e]], 1.f);
        atomicAdd(&cnt[ei[NE + e]], 1);
    }
}
// warp-shuffle scan: 3 barriers per 1024-chunk; also computes dis from deg
__global__ void k_scan(const int* __restrict__ cnt, int* __restrict__ rowptr,
                       int* __restrict__ cursor, const float* __restrict__ deg,
                       float* __restrict__ dis) {
    __shared__ int wsum[32];
    __shared__ int carry_s;
    int tid = threadIdx.x, lane = tid & 31, wid = tid >> 5;
    if (tid == 0) { carry_s = 0; rowptr[0] = 0; }
    __syncthreads();
    for (int base = 0; base < NN; base += 1024) {
        int i = base + tid;
        if (i < NN) {
            float d = deg[i];
            dis[i] = (d > 0.f) ? rsqrtf(d) : 0.f;
        }
        int v = (i < NN) ? cnt[i] : 0;
        int x = v;
#pragma unroll
        for (int o = 1; o < 32; o <<= 1) {
            int t = __shfl_up_sync(0xffffffffu, x, o);
            if (lane >= o) x += t;
        }
        if (lane == 31) wsum[wid] = x;
        __syncthreads();
        if (wid == 0) {
            int s = wsum[lane];
#pragma unroll
            for (int o = 1; o < 32; o <<= 1) {
                int t = __shfl_up_sync(0xffffffffu, s, o);
                if (lane >= o) s += t;
            }
            wsum[lane] = s;
        }
        __syncthreads();
        int inc = carry_s + ((wid > 0) ? wsum[wid - 1] : 0) + x;
        if (i < NN) { rowptr[i + 1] = inc; cursor[i] = inc - v; }
        __syncthreads();
        if (tid == 1023) carry_s = inc;
        __syncthreads();
    }
}
__global__ void k_scatter(const int* __restrict__ ei, const float* __restrict__ dis,
                          int* __restrict__ cursor, int* __restrict__ csr_src,
                          float* __restrict__ csr_w) {
    int e = blockIdx.x * blockDim.x + threadIdx.x;
    if (e < NE) {
        int r = ei[e];
        int c = ei[NE + e];
        int p = atomicAdd(&cursor[c], 1);
        csr_src[p] = r;
        csr_w[p] = -dis[r] * dis[c];
    }
}

// =============== warp-per-node CSR gather props, fused fp16-split writes ===============
__device__ __forceinline__ void split_write4(__half* row, int Fin, int pos, float4 v) {
    float hx = __half2float(__float2half_rn(v.x));
    float hy = __half2float(__float2half_rn(v.y));
    float hz = __half2float(__float2half_rn(v.z));
    float hw = __half2float(__float2half_rn(v.w));
    uint2 hi = make_uint2(pack_h2(v.x, v.y), pack_h2(v.z, v.w));
    uint2 lo = make_uint2(pack_h2(v.x - hx, v.y - hy), pack_h2(v.z - hz, v.w - hw));
    *(uint2*)(row + pos) = hi;
    *(uint2*)(row + 3 * Fin + pos) = lo;
}
// 4-way unrolled weighted gather: y = sum w[t]*src_rows[t]
__device__ __forceinline__ float4 gather_acc(
    const int* __restrict__ csr_src, const float* __restrict__ csr_w,
    const float* __restrict__ base, int Fin, int f, int s, int e, int lane)
{
    float4 a0 = make_float4(0.f, 0.f, 0.f, 0.f);
    float4 a1 = a0, a2 = a0, a3 = a0;
    for (int j0 = s; j0 < e; j0 += 32) {
        int j = j0 + lane;
        int es = 0; float ew = 0.f;
        if (j < e) { es = csr_src[j]; ew = csr_w[j]; }
        int m = min(32, e - j0);
        int t = 0;
        for (; t + 4 <= m; t += 4) {
            int s0 = __shfl_sync(0xffffffffu, es, t + 0);
            int s1 = __shfl_sync(0xffffffffu, es, t + 1);
            int s2 = __shfl_sync(0xffffffffu, es, t + 2);
            int s3 = __shfl_sync(0xffffffffu, es, t + 3);
            float w0 = __shfl_sync(0xffffffffu, ew, t + 0);
            float w1 = __shfl_sync(0xffffffffu, ew, t + 1);
            float w2 = __shfl_sync(0xffffffffu, ew, t + 2);
            float w3 = __shfl_sync(0xffffffffu, ew, t + 3);
            float4 v0 = *(const float4*)(base + (size_t)s0 * Fin + f);
            float4 v1 = *(const float4*)(base + (size_t)s1 * Fin + f);
            float4 v2 = *(const float4*)(base + (size_t)s2 * Fin + f);
            float4 v3 = *(const float4*)(base + (size_t)s3 * Fin + f);
            a0.x += w0 * v0.x; a0.y += w0 * v0.y; a0.z += w0 * v0.z; a0.w += w0 * v0.w;
            a1.x += w1 * v1.x; a1.y += w1 * v1.y; a1.z += w1 * v1.z; a1.w += w1 * v1.w;
            a2.x += w2 * v2.x; a2.y += w2 * v2.y; a2.z += w2 * v2.z; a2.w += w2 * v2.w;
            a3.x += w3 * v3.x; a3.y += w3 * v3.y; a3.z += w3 * v3.z; a3.w += w3 * v3.w;
        }
        for (; t < m; t++) {
            int s0 = __shfl_sync(0xffffffffu, es, t);
            float w0 = __shfl_sync(0xffffffffu, ew, t);
            float4 v0 = *(const float4*)(base + (size_t)s0 * Fin + f);
            a0.x += w0 * v0.x; a0.y += w0 * v0.y; a0.z += w0 * v0.z; a0.w += w0 * v0.w;
        }
    }
    a0.x += a1.x + a2.x + a3.x;
    a0.y += a1.y + a2.y + a3.y;
    a0.z += a1.z + a2.z + a3.z;
    a0.w += a1.w + a2.w + a3.w;
    return a0;
}

__global__ __launch_bounds__(128) void k_gprop1(
    const int* __restrict__ rowptr, const int* __restrict__ csr_src,
    const float* __restrict__ csr_w, const float* __restrict__ x,
    float* __restrict__ tx1, __half* __restrict__ Abig, int Fin)
{
    int warp = threadIdx.x >> 5, lane = threadIdx.x & 31;
    int n = blockIdx.x * 4 + warp;
    if (n >= NN) return;
    int f = blockIdx.y * 128 + lane * 4;
    float4 acc = gather_acc(csr_src, csr_w, x, Fin, f, rowptr[n], rowptr[n + 1], lane);
    float4 x0 = *(const float4*)(x + (size_t)n * Fin + f);
    __half* row = Abig + (size_t)n * 6 * Fin;
    split_write4(row, Fin, f, x0);
    split_write4(row, Fin, Fin + f, acc);
    *(float4*)(tx1 + (size_t)n * Fin + f) = acc;
}
__global__ __launch_bounds__(128) void k_gprop2(
    const int* __restrict__ rowptr, const int* __restrict__ csr_src,
    const float* __restrict__ csr_w, const float* __restrict__ x,
    const float* __restrict__ tx1, __half* __restrict__ Abig, int Fin)
{
    int warp = threadIdx.x >> 5, lane = threadIdx.x & 31;
    int n = blockIdx.x * 4 + warp;
    if (n >= NN) return;
    int f = blockIdx.y * 128 + lane * 4;
    float4 acc = gather_acc(csr_src, csr_w, tx1, Fin, f, rowptr[n], rowptr[n + 1], lane);
    float4 x0 = *(const float4*)(x + (size_t)n * Fin + f);
    float4 t2 = make_float4(2.f * acc.x - x0.x, 2.f * acc.y - x0.y,
                            2.f * acc.z - x0.z, 2.f * acc.w - x0.w);
    __half* row = Abig + (size_t)n * 6 * Fin;
    split_write4(row, Fin, 2 * Fin + f, t2);
}

// =============== B weight conversion: W[K,N] -> rows of 2K: [hi|hi] ===============
__global__ void k_wconv(const float* __restrict__ W, __half* __restrict__ B,
                        int K, int N) {
    int i = blockIdx.x * blockDim.x + threadIdx.x;
    if (i < K * N) {
        int k = i / N;
        int n = i - k * N;
        __half hi = __float2half_rn(W[i]);
        __half* row = B + (size_t)n * 2 * K;
        row[k] = hi;
        row[K + k] = hi;
    }
}

// =============== mma.sync fp16 GEMM, 64x128 tile, BK=64, 3-stage cp.async ===============
#define LDT 72            // 64 + 8 pad (144B rows; ldsm rows hit distinct bank-groups)
#define NSTAGE 3
#define A_ELEMS (64 * LDT)
#define B_ELEMS (128 * LDT)

__device__ __forceinline__ void ldm_x4(uint32_t& r0, uint32_t& r1, uint32_t& r2, uint32_t& r3,
                                       uint32_t a) {
    asm volatile("ldmatrix.sync.aligned.m8n8.x4.shared.b16 {%0,%1,%2,%3}, [%4];"
                 : "=r"(r0), "=r"(r1), "=r"(r2), "=r"(r3) : "r"(a));
}
__device__ __forceinline__ void mma_f16(float* c, const uint32_t* a, const uint32_t* b) {
    asm volatile(
        "mma.sync.aligned.m16n8k16.row.col.f32.f16.f16.f32 "
        "{%0,%1,%2,%3}, {%4,%5,%6,%7}, {%8,%9}, {%0,%1,%2,%3};"
        : "+f"(c[0]), "+f"(c[1]), "+f"(c[2]), "+f"(c[3])
        : "r"(a[0]), "r"(a[1]), "r"(a[2]), "r"(a[3]), "r"(b[0]), "r"(b[1]));
}
__device__ __forceinline__ void cp16(uint32_t dst, const void* src, int pred16) {
    asm volatile("cp.async.cg.shared.global [%0], [%1], 16, %2;"
                 :: "r"(dst), "l"(src), "r"(pred16) : "memory");
}

__global__ __launch_bounds__(256) void k_mgemm(
    const __half* __restrict__ A, const __half* __restrict__ B,
    const float* __restrict__ bias0, const float* __restrict__ bias1,
    float* __restrict__ C0, float* __restrict__ C1,
    __half* __restrict__ Asplit,
    int M, int Kbig, int ldc, int relu, int split)
{
    extern __shared__ __align__(16) __half smp[];
    __half* sAp = smp;
    __half* sBp = smp + NSTAGE * A_ELEMS;

    const int tid = threadIdx.x;
    const int wid = tid >> 5;
    const int lane = tid & 31;
    const int bm = blockIdx.y * 64;
    const int bn = blockIdx.x * 128;
    const int warp_m = (wid & 1) * 32;
    const int warp_n = (wid >> 1) * 32;

    float acc[2][4][4];
#pragma unroll
    for (int i = 0; i < 2; i++)
#pragma unroll
        for (int j = 0; j < 4; j++)
#pragma unroll
            for (int q = 0; q < 4; q++) acc[i][j][q] = 0.f;

    uint32_t sA_u[NSTAGE], sB_u[NSTAGE];
#pragma unroll
    for (int s = 0; s < NSTAGE; s++) {
        sA_u[s] = smem_u32(sAp + s * A_ELEMS);
        sB_u[s] = smem_u32(sBp + s * B_ELEMS);
    }
    const int niter = Kbig >> 6;   // BK=64

    auto issue = [&](int stage, int k0) {
        // A: 64 rows x 8 chunks(16B) = 512; 2 per thread
#pragma unroll
        for (int h = 0; h < 2; h++) {
            int c = tid + h * 256;
            int r = c >> 3, col = c & 7;
            cp16(sA_u[stage] + (r * LDT + col * 8) * 2,
                 A + (size_t)(bm + r) * Kbig + k0 + col * 8, (bm + r) < M ? 16 : 0);
        }
        // B: 128 rows x 8 chunks = 1024; 4 per thread
#pragma unroll
        for (int h = 0; h < 4; h++) {
            int c = tid + h * 256;
            int r = c >> 3, col = c & 7;
            cp16(sB_u[stage] + (r * LDT + col * 8) * 2,
                 B + (size_t)(bn + r) * Kbig + k0 + col * 8, 16);
        }
        asm volatile("cp.async.commit_group;" ::: "memory");
    };

    issue(0, 0);
    issue(1, 64);

    int stage = 0;
    for (int it = 0; it < niter; it++) {
        if (it + 1 < niter) asm volatile("cp.async.wait_group 1;" ::: "memory");
        else                asm volatile("cp.async.wait_group 0;" ::: "memory");
        __syncthreads();

        if (it + 2 < niter) {
            int ns = stage + 2; if (ns >= NSTAGE) ns -= NSTAGE;
            issue(ns, (it + 2) << 6);
        }

#pragma unroll
        for (int ks = 0; ks < 4; ks++) {
            uint32_t af[2][4];
            uint32_t bf[4][2];
#pragma unroll
            for (int mf = 0; mf < 2; mf++) {
                uint32_t addr = sA_u[stage] +
                    ((warp_m + mf * 16 + (lane & 15)) * LDT + ks * 16 + (lane >> 4) * 8) * 2;
                ldm_x4(af[mf][0], af[mf][1], af[mf][2], af[mf][3], addr);
            }
#pragma unroll
            for (int nfp = 0; nfp < 2; nfp++) {
                uint32_t addr = sB_u[stage] +
                    ((warp_n + nfp * 16 + (lane & 15)) * LDT + ks * 16 + (lane >> 4) * 8) * 2;
                uint32_t r0, r1, r2, r3;
                ldm_x4(r0, r1, r2, r3, addr);
                bf[nfp * 2 + 0][0] = r0; bf[nfp * 2 + 1][0] = r1;
                bf[nfp * 2 + 0][1] = r2; bf[nfp * 2 + 1][1] = r3;
            }
#pragma unroll
            for (int mf = 0; mf < 2; mf++)
#pragma unroll
                for (int nf = 0; nf < 4; nf++)
                    mma_f16(acc[mf][nf], af[mf], bf[nf]);
        }
        if (++stage == NSTAGE) stage = 0;
    }

    // epilogue
#pragma unroll
    for (int mf = 0; mf < 2; mf++) {
#pragma unroll
        for (int nf = 0; nf < 4; nf++) {
            int row0 = bm + warp_m + mf * 16 + (lane >> 2);
            int col0 = bn + warp_n + nf * 8 + (lane & 3) * 2;
#pragma unroll
            for (int h = 0; h < 2; h++) {
                int row = row0 + h * 8;
                if (row >= M) continue;
                float v0 = acc[mf][nf][h * 2 + 0];
                float v1 = acc[mf][nf][h * 2 + 1];
                if (Asplit) {
                    v0 += bias0[col0]; v1 += bias0[col0 + 1];
                    if (relu) { v0 = fmaxf(v0, 0.f); v1 = fmaxf(v1, 0.f); }
                    float h0 = __half2float(__float2half_rn(v0));
                    float h1 = __half2float(__float2half_rn(v1));
                    uint32_t hi = pack_h2(v0, v1);
                    uint32_t lo = pack_h2(v0 - h0, v1 - h1);
                    __half* arow = Asplit + (size_t)row * 2 * ldc;
                    *(uint32_t*)(arow + col0) = hi;
                    *(uint32_t*)(arow + ldc + col0) = lo;
                } else {
                    bool second = col0 >= split;
                    const float* bs = second ? bias1 : bias0;
                    float* dst = second ? C1 : C0;
                    int cc = second ? col0 - split : col0;
                    v0 += bs[cc]; v1 += bs[cc + 1];
                    if (relu) { v0 = fmaxf(v0, 0.f); v1 = fmaxf(v1, 0.f); }
                    *(float2*)(dst + (size_t)row * ldc + cc) = make_float2(v0, v1);
                }
            }
        }
    }
}

// =============== host orchestration ===============
#define SMEM_BYTES (NSTAGE * (A_ELEMS + B_ELEMS) * 2)

static void launch_gemm(const __half* A, const __half* B,
                        const float* bias0, const float* bias1,
                        float* C0, float* C1, __half* Asplit,
                        int Kbig, int N, int ldc, int relu, int split) {
    dim3 grid(N / 128, (NN + 63) / 64);
    k_mgemm<<<grid, 256, SMEM_BYTES>>>(A, B, bias0, bias1, C0, C1, Asplit,
                                       NN, Kbig, ldc, relu, split);
}

static void run_layer(const int* rowptr, const int* csr_src, const float* csr_w,
                      float* tx1, __half* Abig, const __half* Bbig,
                      const float* x, int Fin, int Fout,
                      const float* b, float* y, __half* Asplit) {
    dim3 pg((NN + 3) / 4, Fin / 128);
    k_gprop1<<<pg, 128>>>(rowptr, csr_src, csr_w, x, tx1, Abig, Fin);
    k_gprop2<<<pg, 128>>>(rowptr, csr_src, csr_w, x, tx1, Abig, Fin);
    launch_gemm(Abig, Bbig, b, b, y, y, Asplit, 6 * Fin, Fout, Fout, 1, Fout);
}

extern "C" void kernel_launch(void* const* d_in, const int* in_sizes, int n_in,
                              void* d_out, int out_size) {
    const float* v    = (const float*)d_in[0];
    const int* ei     = (const int*)d_in[1];
    const float* W1   = (const float*)d_in[2];
    const float* b1   = (const float*)d_in[3];
    const float* W2   = (const float*)d_in[4];
    const float* b2   = (const float*)d_in[5];
    const float* W3   = (const float*)d_in[6];
    const float* b3   = (const float*)d_in[7];
    const float* Wmu  = (const float*)d_in[8];
    const float* bmu  = (const float*)d_in[9];
    const float* Wstd = (const float*)d_in[10];
    const float* bstd = (const float*)d_in[11];
    float* out = (float*)d_out;

    static bool init_done = false;
    static cudaStream_t s2;
    static cudaEvent_t evFork, evDone, evScan, evZero;
    if (!init_done) {
        cudaFuncSetAttribute(k_mgemm, cudaFuncAttributeMaxDynamicSharedMemorySize, SMEM_BYTES);
        cudaStreamCreateWithFlags(&s2, cudaStreamNonBlocking);
        cudaEventCreateWithFlags(&evFork, cudaEventDisableTiming);
        cudaEventCreateWithFlags(&evDone, cudaEventDisableTiming);
        cudaEventCreateWithFlags(&evScan, cudaEventDisableTiming);
        cudaEventCreateWithFlags(&evZero, cudaEventDisableTiming);
        init_done = true;
    }

    float *deg, *dis, *tx1, *actA, *actB, *csr_w;
    int *cnt, *rowptr, *cursor, *csr_src;
    __half *Abig, *B1, *B2, *B3, *Bh;
    cudaGetSymbolAddress((void**)&deg,     g_deg);
    cudaGetSymbolAddress((void**)&dis,     g_dis);
    cudaGetSymbolAddress((void**)&cnt,     g_cnt);
    cudaGetSymbolAddress((void**)&rowptr,  g_rowptr);
    cudaGetSymbolAddress((void**)&cursor,  g_cursor);
    cudaGetSymbolAddress((void**)&csr_src, g_csr_src);
    cudaGetSymbolAddress((void**)&csr_w,   g_csr_w);
    cudaGetSymbolAddress((void**)&tx1,     g_tx1);
    cudaGetSymbolAddress((void**)&actA,    g_actA);
    cudaGetSymbolAddress((void**)&actB,    g_actB);
    cudaGetSymbolAddress((void**)&Abig,    g_Abig);
    cudaGetSymbolAddress((void**)&B1,      g_B1);
    cudaGetSymbolAddress((void**)&B2,      g_B2);
    cudaGetSymbolAddress((void**)&B3,      g_B3);
    cudaGetSymbolAddress((void**)&Bh,      g_Bh);

    // fork side stream: weight conversions off the critical path
    cudaEventRecord(evFork, 0);
    cudaStreamWaitEvent(s2, evFork, 0);
    k_wconv<<<(128 * 384 + 255) / 256, 256, 0, s2>>>(W1, B1, 384, 128);
    k_wconv<<<(256 * 384 + 255) / 256, 256, 0, s2>>>(W2, B2, 384, 256);
    k_wconv<<<(512 * 768 + 255) / 256, 256, 0, s2>>>(W3, B3, 768, 512);
    k_wconv<<<(256 * 512 + 255) / 256, 256, 0, s2>>>(Wmu,  Bh, 512, 256);
    k_wconv<<<(256 * 512 + 255) / 256, 256, 0, s2>>>(Wstd, Bh + (size_t)256 * 1024, 512, 256);
    cudaEventRecord(evDone, s2);

    // preprocessing (deg/cnt are zero at entry: zero-init at load, re-zeroed below)
    k_counts<<<(NE + 255) / 256, 256>>>(ei, deg, cnt);
    k_scan<<<1, 1024>>>(cnt, rowptr, cursor, deg, dis);
    cudaEventRecord(evScan, 0);
    k_scatter<<<(NE + 255) / 256, 256>>>(ei, dis, cursor, csr_src, csr_w);

    // side stream: re-zero deg/cnt for the NEXT call (after scan has consumed them)
    cudaStreamWaitEvent(s2, evScan, 0);
    k_zero2<<<(NN + 255) / 256, 256, 0, s2>>>(deg, cnt, NN);
    cudaEventRecord(evZero, s2);

    // L1 props, then join side stream before first GEMM
    dim3 pg1((NN + 3) / 4, 1);
    k_gprop1<<<pg1, 128>>>(rowptr, csr_src, csr_w, v, tx1, Abig, 128);
    k_gprop2<<<pg1, 128>>>(rowptr, csr_src, csr_w, v, tx1, Abig, 128);
    cudaStreamWaitEvent(0, evDone, 0);
    launch_gemm(Abig, B1, b1, b1, actA, actA, nullptr, 768, 128, 128, 1, 128);

    // L2, L3 (L3 writes fp16 split rows directly into Abig)
    run_layer(rowptr, csr_src, csr_w, tx1, Abig, B2, actA, 128, 256, b2, actB, nullptr);
    run_layer(rowptr, csr_src, csr_w, tx1, Abig, B3, actB, 256, 512, b3, nullptr, Abig);

    // fused heads: one N=512 GEMM on split A (K''=1024), split output mu|std
    launch_gemm(Abig, Bh, bmu, bstd, out, out + (size_t)NN * 256, nullptr,
                1024, 512, 256, 0, 256);

    // join zeroing into main stream so graph end covers it
    cudaStreamWaitEvent(0, evZero, 0);

    (void)in_sizes; (void)n_in; (void)out_size;
}

// round 12
// speedup vs baseline: 3.6934x; 1.0224x over previous
#include <cuda_runtime.h>
#include <cuda_fp16.h>
#include <math.h>
#include <stdint.h>

#define NN 10000
#define NE 160000

// ---- scratch (static device globals; zero-initialized at module load) ----
__device__ float g_deg[NN];
__device__ float g_dis[NN];
__device__ int   g_cnt[NN];
__device__ int   g_rowptr[NN + 1];
__device__ int   g_cursor[NN];
__device__ int   g_csr_src[NE];
__device__ float g_csr_w[NE];
__device__ float g_tx1[NN * 256];
__device__ float g_actA[NN * 512];
__device__ float g_actB[NN * 512];
__device__ __half g_Abig[NN * 1536];         // [hi|lo] split rows, K''max = 6*256
// B stored deduplicated: single hi copy of length K per output row
__device__ __half g_B1[128 * 384];
__device__ __half g_B2[256 * 384];
__device__ __half g_B3[512 * 768];
__device__ __half g_Bh[512 * 512];           // [mu(256 rows) | std(256 rows)]

__device__ __forceinline__ uint32_t smem_u32(const void* p) {
    uint32_t a;
    asm("{ .reg .u64 t; cvta.to.shared.u64 t, %1; cvt.u32.u64 %0, t; }" : "=r"(a) : "l"(p));
    return a;
}
__device__ __forceinline__ uint32_t pack_h2(float a, float b) {
    __half2 t = __floats2half2_rn(a, b);
    return *(uint32_t*)&t;
}

// =============== graph preprocessing ===============
__global__ void k_zero2(float* deg, int* cnt, int n) {
    int i = blockIdx.x * blockDim.x + threadIdx.x;
    if (i < n) { deg[i] = 0.f; cnt[i] = 0; }
}
__global__ void k_counts(const int* __restrict__ ei, float* __restrict__ deg,
                         int* __restrict__ cnt) {
    int e = blockIdx.x * blockDim.x + threadIdx.x;
    if (e < NE) {
        atomicAdd(&deg[ei[e]], 1.f);
        atomicAdd(&cnt[ei[NE + e]], 1);
    }
}
__global__ void k_scan(const int* __restrict__ cnt, int* __restrict__ rowptr,
                       int* __restrict__ cursor, const float* __restrict__ deg,
                       float* __restrict__ dis) {
    __shared__ int wsum[32];
    __shared__ int carry_s;
    int tid = threadIdx.x, lane = tid & 31, wid = tid >> 5;
    if (tid == 0) { carry_s = 0; rowptr[0] = 0; }
    __syncthreads();
    for (int base = 0; base < NN; base += 1024) {
        int i = base + tid;
        if (i < NN) {
            float d = deg[i];
            dis[i] = (d > 0.f) ? rsqrtf(d) : 0.f;
        }
        int v = (i < NN) ? cnt[i] : 0;
        int x = v;
#pragma unroll
        for (int o = 1; o < 32; o <<= 1) {
            int t = __shfl_up_sync(0xffffffffu, x, o);
            if (lane >= o) x += t;
        }
        if (lane == 31) wsum[wid] = x;
        __syncthreads();
        if (wid == 0) {
            int s = wsum[lane];
#pragma unroll
            for (int o = 1; o < 32; o <<= 1) {
                int t = __shfl_up_sync(0xffffffffu, s, o);
                if (lane >= o) s += t;
            }
            wsum[lane] = s;
        }
        __syncthreads();
        int inc = carry_s + ((wid > 0) ? wsum[wid - 1] : 0) + x;
        if (i < NN) { rowptr[i + 1] = inc; cursor[i] = inc - v; }
        __syncthreads();
        if (tid == 1023) carry_s = inc;
        __syncthreads();
    }
}
__global__ void k_scatter(const int* __restrict__ ei, const float* __restrict__ dis,
                          int* __restrict__ cursor, int* __restrict__ csr_src,
                          float* __restrict__ csr_w) {
    int e = blockIdx.x * blockDim.x + threadIdx.x;
    if (e < NE) {
        int r = ei[e];
        int c = ei[NE + e];
        int p = atomicAdd(&cursor[c], 1);
        csr_src[p] = r;
        csr_w[p] = -dis[r] * dis[c];
    }
}

// =============== warp-per-node CSR gather props, fused fp16-split writes ===============
__device__ __forceinline__ void split_write4(__half* row, int Fin, int pos, float4 v) {
    float hx = __half2float(__float2half_rn(v.x));
    float hy = __half2float(__float2half_rn(v.y));
    float hz = __half2float(__float2half_rn(v.z));
    float hw = __half2float(__float2half_rn(v.w));
    uint2 hi = make_uint2(pack_h2(v.x, v.y), pack_h2(v.z, v.w));
    uint2 lo = make_uint2(pack_h2(v.x - hx, v.y - hy), pack_h2(v.z - hz, v.w - hw));
    *(uint2*)(row + pos) = hi;
    *(uint2*)(row + 3 * Fin + pos) = lo;
}
__device__ __forceinline__ float4 gather_acc(
    const int* __restrict__ csr_src, const float* __restrict__ csr_w,
    const float* __restrict__ base, int Fin, int f, int s, int e, int lane)
{
    float4 a0 = make_float4(0.f, 0.f, 0.f, 0.f);
    float4 a1 = a0, a2 = a0, a3 = a0;
    for (int j0 = s; j0 < e; j0 += 32) {
        int j = j0 + lane;
        int es = 0; float ew = 0.f;
        if (j < e) { es = csr_src[j]; ew = csr_w[j]; }
        int m = min(32, e - j0);
        int t = 0;
        for (; t + 4 <= m; t += 4) {
            int s0 = __shfl_sync(0xffffffffu, es, t + 0);
            int s1 = __shfl_sync(0xffffffffu, es, t + 1);
            int s2 = __shfl_sync(0xffffffffu, es, t + 2);
            int s3 = __shfl_sync(0xffffffffu, es, t + 3);
            float w0 = __shfl_sync(0xffffffffu, ew, t + 0);
            float w1 = __shfl_sync(0xffffffffu, ew, t + 1);
            float w2 = __shfl_sync(0xffffffffu, ew, t + 2);
            float w3 = __shfl_sync(0xffffffffu, ew, t + 3);
            float4 v0 = *(const float4*)(base + (size_t)s0 * Fin + f);
            float4 v1 = *(const float4*)(base + (size_t)s1 * Fin + f);
            float4 v2 = *(const float4*)(base + (size_t)s2 * Fin + f);
            float4 v3 = *(const float4*)(base + (size_t)s3 * Fin + f);
            a0.x += w0 * v0.x; a0.y += w0 * v0.y; a0.z += w0 * v0.z; a0.w += w0 * v0.w;
            a1.x += w1 * v1.x; a1.y += w1 * v1.y; a1.z += w1 * v1.z; a1.w += w1 * v1.w;
            a2.x += w2 * v2.x; a2.y += w2 * v2.y; a2.z += w2 * v2.z; a2.w += w2 * v2.w;
            a3.x += w3 * v3.x; a3.y += w3 * v3.y; a3.z += w3 * v3.z; a3.w += w3 * v3.w;
        }
        for (; t < m; t++) {
            int s0 = __shfl_sync(0xffffffffu, es, t);
            float w0 = __shfl_sync(0xffffffffu, ew, t);
            float4 v0 = *(const float4*)(base + (size_t)s0 * Fin + f);
            a0.x += w0 * v0.x; a0.y += w0 * v0.y; a0.z += w0 * v0.z; a0.w += w0 * v0.w;
        }
    }
    a0.x += a1.x + a2.x + a3.x;
    a0.y += a1.y + a2.y + a3.y;
    a0.z += a1.z + a2.z + a3.z;
    a0.w += a1.w + a2.w + a3.w;
    return a0;
}

__global__ __launch_bounds__(128) void k_gprop1(
    const int* __restrict__ rowptr, const int* __restrict__ csr_src,
    const float* __restrict__ csr_w, const float* __restrict__ x,
    float* __restrict__ tx1, __half* __restrict__ Abig, int Fin)
{
    int warp = threadIdx.x >> 5, lane = threadIdx.x & 31;
    int n = blockIdx.x * 4 + warp;
    if (n >= NN) return;
    int f = blockIdx.y * 128 + lane * 4;
    float4 acc = gather_acc(csr_src, csr_w, x, Fin, f, rowptr[n], rowptr[n + 1], lane);
    float4 x0 = *(const float4*)(x + (size_t)n * Fin + f);
    __half* row = Abig + (size_t)n * 6 * Fin;
    split_write4(row, Fin, f, x0);
    split_write4(row, Fin, Fin + f, acc);
    *(float4*)(tx1 + (size_t)n * Fin + f) = acc;
}
__global__ __launch_bounds__(128) void k_gprop2(
    const int* __restrict__ rowptr, const int* __restrict__ csr_src,
    const float* __restrict__ csr_w, const float* __restrict__ x,
    const float* __restrict__ tx1, __half* __restrict__ Abig, int Fin)
{
    int warp = threadIdx.x >> 5, lane = threadIdx.x & 31;
    int n = blockIdx.x * 4 + warp;
    if (n >= NN) return;
    int f = blockIdx.y * 128 + lane * 4;
    float4 acc = gather_acc(csr_src, csr_w, tx1, Fin, f, rowptr[n], rowptr[n + 1], lane);
    float4 x0 = *(const float4*)(x + (size_t)n * Fin + f);
    float4 t2 = make_float4(2.f * acc.x - x0.x, 2.f * acc.y - x0.y,
                            2.f * acc.z - x0.z, 2.f * acc.w - x0.w);
    __half* row = Abig + (size_t)n * 6 * Fin;
    split_write4(row, Fin, 2 * Fin + f, t2);
}

// =============== B weight conversion: W[K,N] -> single hi copy [N rows, K] ===============
__global__ void k_wconv(const float* __restrict__ W, __half* __restrict__ B,
                        int K, int N) {
    int i = blockIdx.x * blockDim.x + threadIdx.x;
    if (i < K * N) {
        int k = i / N;
        int n = i - k * N;
        B[(size_t)n * K + k] = __float2half_rn(W[i]);
    }
}

// =============== mma.sync fp16 GEMM, 64x128 tile, BK=64, 3-stage cp.async ===============
// B operand is deduplicated: logical k in [0,2*Kb) maps to k mod Kb in memory.
#define LDT 72
#define NSTAGE 3
#define A_ELEMS (64 * LDT)
#define B_ELEMS (128 * LDT)

__device__ __forceinline__ void ldm_x4(uint32_t& r0, uint32_t& r1, uint32_t& r2, uint32_t& r3,
                                       uint32_t a) {
    asm volatile("ldmatrix.sync.aligned.m8n8.x4.shared.b16 {%0,%1,%2,%3}, [%4];"
                 : "=r"(r0), "=r"(r1), "=r"(r2), "=r"(r3) : "r"(a));
}
__device__ __forceinline__ void mma_f16(float* c, const uint32_t* a, const uint32_t* b) {
    asm volatile(
        "mma.sync.aligned.m16n8k16.row.col.f32.f16.f16.f32 "
        "{%0,%1,%2,%3}, {%4,%5,%6,%7}, {%8,%9}, {%0,%1,%2,%3};"
        : "+f"(c[0]), "+f"(c[1]), "+f"(c[2]), "+f"(c[3])
        : "r"(a[0]), "r"(a[1]), "r"(a[2]), "r"(a[3]), "r"(b[0]), "r"(b[1]));
}
__device__ __forceinline__ void cp16(uint32_t dst, const void* src, int pred16) {
    asm volatile("cp.async.cg.shared.global [%0], [%1], 16, %2;"
                 :: "r"(dst), "l"(src), "r"(pred16) : "memory");
}

__global__ __launch_bounds__(256) void k_mgemm(
    const __half* __restrict__ A, const __half* __restrict__ B,
    const float* __restrict__ bias0, const float* __restrict__ bias1,
    float* __restrict__ C0, float* __restrict__ C1,
    __half* __restrict__ Asplit,
    int M, int Kbig, int Kb, int ldc, int relu, int split)
{
    extern __shared__ __align__(16) __half smp[];
    __half* sAp = smp;
    __half* sBp = smp + NSTAGE * A_ELEMS;

    const int tid = threadIdx.x;
    const int wid = tid >> 5;
    const int lane = tid & 31;
    const int bm = blockIdx.y * 64;
    const int bn = blockIdx.x * 128;
    const int warp_m = (wid & 1) * 32;
    const int warp_n = (wid >> 1) * 32;

    float acc[2][4][4];
#pragma unroll
    for (int i = 0; i < 2; i++)
#pragma unroll
        for (int j = 0; j < 4; j++)
#pragma unroll
            for (int q = 0; q < 4; q++) acc[i][j][q] = 0.f;

    uint32_t sA_u[NSTAGE], sB_u[NSTAGE];
#pragma unroll
    for (int s = 0; s < NSTAGE; s++) {
        sA_u[s] = smem_u32(sAp + s * A_ELEMS);
        sB_u[s] = smem_u32(sBp + s * B_ELEMS);
    }
    const int niter = Kbig >> 6;   // BK=64

    auto issue = [&](int stage, int k0) {
        // A: 64 rows x 8 chunks(16B); 2 per thread
#pragma unroll
        for (int h = 0; h < 2; h++) {
            int c = tid + h * 256;
            int r = c >> 3, col = c & 7;
            cp16(sA_u[stage] + (r * LDT + col * 8) * 2,
                 A + (size_t)(bm + r) * Kbig + k0 + col * 8, (bm + r) < M ? 16 : 0);
        }
        // B: dedup mapping — whole BK=64 tile lives in one half (Kb % 64 == 0)
        int kb = (k0 < Kb) ? k0 : k0 - Kb;
#pragma unroll
        for (int h = 0; h < 4; h++) {
            int c = tid + h * 256;
            int r = c >> 3, col = c & 7;
            cp16(sB_u[stage] + (r * LDT + col * 8) * 2,
                 B + (size_t)(bn + r) * Kb + kb + col * 8, 16);
        }
        asm volatile("cp.async.commit_group;" ::: "memory");
    };

    issue(0, 0);
    issue(1, 64);

    int stage = 0;
    for (int it = 0; it < niter; it++) {
        if (it + 1 < niter) asm volatile("cp.async.wait_group 1;" ::: "memory");
        else                asm volatile("cp.async.wait_group 0;" ::: "memory");
        __syncthreads();

        if (it + 2 < niter) {
            int ns = stage + 2; if (ns >= NSTAGE) ns -= NSTAGE;
            issue(ns, (it + 2) << 6);
        }

#pragma unroll
        for (int ks = 0; ks < 4; ks++) {
            uint32_t af[2][4];
            uint32_t bf[4][2];
#pragma unroll
            for (int mf = 0; mf < 2; mf++) {
                uint32_t addr = sA_u[stage] +
                    ((warp_m + mf * 16 + (lane & 15)) * LDT + ks * 16 + (lane >> 4) * 8) * 2;
                ldm_x4(af[mf][0], af[mf][1], af[mf][2], af[mf][3], addr);
            }
#pragma unroll
            for (int nfp = 0; nfp < 2; nfp++) {
                uint32_t addr = sB_u[stage] +
                    ((warp_n + nfp * 16 + (lane & 15)) * LDT + ks * 16 + (lane >> 4) * 8) * 2;
                uint32_t r0, r1, r2, r3;
                ldm_x4(r0, r1, r2, r3, addr);
                bf[nfp * 2 + 0][0] = r0; bf[nfp * 2 + 1][0] = r1;
                bf[nfp * 2 + 0][1] = r2; bf[nfp * 2 + 1][1] = r3;
            }
#pragma unroll
            for (int mf = 0; mf < 2; mf++)
#pragma unroll
                for (int nf = 0; nf < 4; nf++)
                    mma_f16(acc[mf][nf], af[mf], bf[nf]);
        }
        if (++stage == NSTAGE) stage = 0;
    }

    // epilogue
#pragma unroll
    for (int mf = 0; mf < 2; mf++) {
#pragma unroll
        for (int nf = 0; nf < 4; nf++) {
            int row0 = bm + warp_m + mf * 16 + (lane >> 2);
            int col0 = bn + warp_n + nf * 8 + (lane & 3) * 2;
#pragma unroll
            for (int h = 0; h < 2; h++) {
                int row = row0 + h * 8;
                if (row >= M) continue;
                float v0 = acc[mf][nf][h * 2 + 0];
                float v1 = acc[mf][nf][h * 2 + 1];
                if (Asplit) {
                    v0 += bias0[col0]; v1 += bias0[col0 + 1];
                    if (relu) { v0 = fmaxf(v0, 0.f); v1 = fmaxf(v1, 0.f); }
                    float h0 = __half2float(__float2half_rn(v0));
                    float h1 = __half2float(__float2half_rn(v1));
                    uint32_t hi = pack_h2(v0, v1);
                    uint32_t lo = pack_h2(v0 - h0, v1 - h1);
                    __half* arow = Asplit + (size_t)row * 2 * ldc;
                    *(uint32_t*)(arow + col0) = hi;
                    *(uint32_t*)(arow + ldc + col0) = lo;
                } else {
                    bool second = col0 >= split;
                    const float* bs = second ? bias1 : bias0;
                    float* dst = second ? C1 : C0;
                    int cc = second ? col0 - split : col0;
                    v0 += bs[cc]; v1 += bs[cc + 1];
                    if (relu) { v0 = fmaxf(v0, 0.f); v1 = fmaxf(v1, 0.f); }
                    *(float2*)(dst + (size_t)row * ldc + cc) = make_float2(v0, v1);
                }
            }
        }
    }
}

// =============== host orchestration ===============
#define SMEM_BYTES (NSTAGE * (A_ELEMS + B_ELEMS) * 2)

static void launch_gemm(const __half* A, const __half* B,
                        const float* bias0, const float* bias1,
                        float* C0, float* C1, __half* Asplit,
                        int Kbig, int N, int ldc, int relu, int split) {
    dim3 grid(N / 128, (NN + 63) / 64);
    k_mgemm<<<grid, 256, SMEM_BYTES>>>(A, B, bias0, bias1, C0, C1, Asplit,
                                       NN, Kbig, Kbig / 2, ldc, relu, split);
}

static void run_layer(const int* rowptr, const int* csr_src, const float* csr_w,
                      float* tx1, __half* Abig, const __half* Bbig,
                      const float* x, int Fin, int Fout,
                      const float* b, float* y, __half* Asplit) {
    dim3 pg((NN + 3) / 4, Fin / 128);
    k_gprop1<<<pg, 128>>>(rowptr, csr_src, csr_w, x, tx1, Abig, Fin);
    k_gprop2<<<pg, 128>>>(rowptr, csr_src, csr_w, x, tx1, Abig, Fin);
    launch_gemm(Abig, Bbig, b, b, y, y, Asplit, 6 * Fin, Fout, Fout, 1, Fout);
}

extern "C" void kernel_launch(void* const* d_in, const int* in_sizes, int n_in,
                              void* d_out, int out_size) {
    const float* v    = (const float*)d_in[0];
    const int* ei     = (const int*)d_in[1];
    const float* W1   = (const float*)d_in[2];
    const float* b1   = (const float*)d_in[3];
    const float* W2   = (const float*)d_in[4];
    const float* b2   = (const float*)d_in[5];
    const float* W3   = (const float*)d_in[6];
    const float* b3   = (const float*)d_in[7];
    const float* Wmu  = (const float*)d_in[8];
    const float* bmu  = (const float*)d_in[9];
    const float* Wstd = (const float*)d_in[10];
    const float* bstd = (const float*)d_in[11];
    float* out = (float*)d_out;

    static bool init_done = false;
    static cudaStream_t s2;
    static cudaEvent_t evFork, evDone, evScan, evZero;
    if (!init_done) {
        cudaFuncSetAttribute(k_mgemm, cudaFuncAttributeMaxDynamicSharedMemorySize, SMEM_BYTES);
        cudaStreamCreateWithFlags(&s2, cudaStreamNonBlocking);
        cudaEventCreateWithFlags(&evFork, cudaEventDisableTiming);
        cudaEventCreateWithFlags(&evDone, cudaEventDisableTiming);
        cudaEventCreateWithFlags(&evScan, cudaEventDisableTiming);
        cudaEventCreateWithFlags(&evZero, cudaEventDisableTiming);
        init_done = true;
    }

    float *deg, *dis, *tx1, *actA, *actB, *csr_w;
    int *cnt, *rowptr, *cursor, *csr_src;
    __half *Abig, *B1, *B2, *B3, *Bh;
    cudaGetSymbolAddress((void**)&deg,     g_deg);
    cudaGetSymbolAddress((void**)&dis,     g_dis);
    cudaGetSymbolAddress((void**)&cnt,     g_cnt);
    cudaGetSymbolAddress((void**)&rowptr,  g_rowptr);
    cudaGetSymbolAddress((void**)&cursor,  g_cursor);
    cudaGetSymbolAddress((void**)&csr_src, g_csr_src);
    cudaGetSymbolAddress((void**)&csr_w,   g_csr_w);
    cudaGetSymbolAddress((void**)&tx1,     g_tx1);
    cudaGetSymbolAddress((void**)&actA,    g_actA);
    cudaGetSymbolAddress((void**)&actB,    g_actB);
    cudaGetSymbolAddress((void**)&Abig,    g_Abig);
    cudaGetSymbolAddress((void**)&B1,      g_B1);
    cudaGetSymbolAddress((void**)&B2,      g_B2);
    cudaGetSymbolAddress((void**)&B3,      g_B3);
    cudaGetSymbolAddress((void**)&Bh,      g_Bh);

    // fork side stream: weight conversions off the critical path
    cudaEventRecord(evFork, 0);
    cudaStreamWaitEvent(s2, evFork, 0);
    k_wconv<<<(128 * 384 + 255) / 256, 256, 0, s2>>>(W1, B1, 384, 128);
    k_wconv<<<(256 * 384 + 255) / 256, 256, 0, s2>>>(W2, B2, 384, 256);
    k_wconv<<<(512 * 768 + 255) / 256, 256, 0, s2>>>(W3, B3, 768, 512);
    k_wconv<<<(256 * 512 + 255) / 256, 256, 0, s2>>>(Wmu,  Bh, 512, 256);
    k_wconv<<<(256 * 512 + 255) / 256, 256, 0, s2>>>(Wstd, Bh + (size_t)256 * 512, 512, 256);
    cudaEventRecord(evDone, s2);

    // preprocessing (deg/cnt are zero at entry)
    k_counts<<<(NE + 255) / 256, 256>>>(ei, deg, cnt);
    k_scan<<<1, 1024>>>(cnt, rowptr, cursor, deg, dis);
    cudaEventRecord(evScan, 0);
    k_scatter<<<(NE + 255) / 256, 256>>>(ei, dis, cursor, csr_src, csr_w);

    // side stream: re-zero deg/cnt for the NEXT call
    cudaStreamWaitEvent(s2, evScan, 0);
    k_zero2<<<(NN + 255) / 256, 256, 0, s2>>>(deg, cnt, NN);
    cudaEventRecord(evZero, s2);

    // L1 props, then join side stream before first GEMM
    dim3 pg1((NN + 3) / 4, 1);
    k_gprop1<<<pg1, 128>>>(rowptr, csr_src, csr_w, v, tx1, Abig, 128);
    k_gprop2<<<pg1, 128>>>(rowptr, csr_src, csr_w, v, tx1, Abig, 128);
    cudaStreamWaitEvent(0, evDone, 0);
    launch_gemm(Abig, B1, b1, b1, actA, actA, nullptr, 768, 128, 128, 1, 128);

    // L2, L3 (L3 writes fp16 split rows directly into Abig)
    run_layer(rowptr, csr_src, csr_w, tx1, Abig, B2, actA, 128, 256, b2, actB, nullptr);
    run_layer(rowptr, csr_src, csr_w, tx1, Abig, B3, actB, 256, 512, b3, nullptr, Abig);

    // fused heads: one N=512 GEMM on split A (K''=1024, Kb=512), split output mu|std
    launch_gemm(Abig, Bh, bmu, bstd, out, out + (size_t)NN * 256, nullptr,
                1024, 512, 256, 0, 256);

    cudaStreamWaitEvent(0, evZero, 0);

    (void)in_sizes; (void)n_in; (void)out_size;
}

// round 13
// speedup vs baseline: 4.1236x; 1.1165x over previous
#include <cuda_runtime.h>
#include <cuda_fp16.h>
#include <math.h>
#include <stdint.h>

#define NN 10000
#define NE 160000

// ---- scratch (static device globals; zero-initialized at module load) ----
__device__ float g_deg[NN];
__device__ float g_dis[NN];
__device__ int   g_cnt[NN];
__device__ int   g_rowptr[NN + 1];
__device__ int   g_cursor[NN];
__device__ int   g_csr_src[NE];
__device__ float g_csr_w[NE];
__device__ float g_tx1[NN * 256];
__device__ float g_actA[NN * 512];
__device__ float g_actB[NN * 512];
__device__ __half g_Abig[NN * 1536];         // [hi|lo] split rows, K''max = 6*256
// B stored deduplicated: single hi copy of length K per output row
__device__ __half g_B1[128 * 384];
__device__ __half g_B2[256 * 384];
__device__ __half g_B3[512 * 768];
__device__ __half g_Bh[512 * 512];           // [mu(256 rows) | std(256 rows)], K=512

__device__ __forceinline__ uint32_t smem_u32(const void* p) {
    uint32_t a;
    asm("{ .reg .u64 t; cvta.to.shared.u64 t, %1; cvt.u32.u64 %0, t; }" : "=r"(a) : "l"(p));
    return a;
}
__device__ __forceinline__ uint32_t pack_h2(float a, float b) {
    __half2 t = __floats2half2_rn(a, b);
    return *(uint32_t*)&t;
}

// =============== graph preprocessing ===============
__global__ void k_zero2(float* deg, int* cnt, int n) {
    int i = blockIdx.x * blockDim.x + threadIdx.x;
    if (i < n) { deg[i] = 0.f; cnt[i] = 0; }
}
__global__ void k_counts(const int* __restrict__ ei, float* __restrict__ deg,
                         int* __restrict__ cnt) {
    int e = blockIdx.x * blockDim.x + threadIdx.x;
    if (e < NE) {
        atomicAdd(&deg[ei[e]], 1.f);
        atomicAdd(&cnt[ei[NE + e]], 1);
    }
}
__global__ void k_scan(const int* __restrict__ cnt, int* __restrict__ rowptr,
                       int* __restrict__ cursor, const float* __restrict__ deg,
                       float* __restrict__ dis) {
    __shared__ int wsum[32];
    __shared__ int carry_s;
    int tid = threadIdx.x, lane = tid & 31, wid = tid >> 5;
    if (tid == 0) { carry_s = 0; rowptr[0] = 0; }
    __syncthreads();
    for (int base = 0; base < NN; base += 1024) {
        int i = base + tid;
        if (i < NN) {
            float d = deg[i];
            dis[i] = (d > 0.f) ? rsqrtf(d) : 0.f;
        }
        int v = (i < NN) ? cnt[i] : 0;
        int x = v;
#pragma unroll
        for (int o = 1; o < 32; o <<= 1) {
            int t = __shfl_up_sync(0xffffffffu, x, o);
            if (lane >= o) x += t;
        }
        if (lane == 31) wsum[wid] = x;
        __syncthreads();
        if (wid == 0) {
            int s = wsum[lane];
#pragma unroll
            for (int o = 1; o < 32; o <<= 1) {
                int t = __shfl_up_sync(0xffffffffu, s, o);
                if (lane >= o) s += t;
            }
            wsum[lane] = s;
        }
        __syncthreads();
        int inc = carry_s + ((wid > 0) ? wsum[wid - 1] : 0) + x;
        if (i < NN) { rowptr[i + 1] = inc; cursor[i] = inc - v; }
        __syncthreads();
        if (tid == 1023) carry_s = inc;
        __syncthreads();
    }
}
__global__ void k_scatter(const int* __restrict__ ei, const float* __restrict__ dis,
                          int* __restrict__ cursor, int* __restrict__ csr_src,
                          float* __restrict__ csr_w) {
    int e = blockIdx.x * blockDim.x + threadIdx.x;
    if (e < NE) {
        int r = ei[e];
        int c = ei[NE + e];
        int p = atomicAdd(&cursor[c], 1);
        csr_src[p] = r;
        csr_w[p] = -dis[r] * dis[c];
    }
}

// =============== warp-per-node CSR gather props, fused fp16-split writes ===============
__device__ __forceinline__ void split_write4(__half* row, int Fin, int pos, float4 v) {
    float hx = __half2float(__float2half_rn(v.x));
    float hy = __half2float(__float2half_rn(v.y));
    float hz = __half2float(__float2half_rn(v.z));
    float hw = __half2float(__float2half_rn(v.w));
    uint2 hi = make_uint2(pack_h2(v.x, v.y), pack_h2(v.z, v.w));
    uint2 lo = make_uint2(pack_h2(v.x - hx, v.y - hy), pack_h2(v.z - hz, v.w - hw));
    *(uint2*)(row + pos) = hi;
    *(uint2*)(row + 3 * Fin + pos) = lo;
}
__device__ __forceinline__ float4 gather_acc(
    const int* __restrict__ csr_src, const float* __restrict__ csr_w,
    const float* __restrict__ base, int Fin, int f, int s, int e, int lane)
{
    float4 a0 = make_float4(0.f, 0.f, 0.f, 0.f);
    float4 a1 = a0, a2 = a0, a3 = a0;
    for (int j0 = s; j0 < e; j0 += 32) {
        int j = j0 + lane;
        int es = 0; float ew = 0.f;
        if (j < e) { es = csr_src[j]; ew = csr_w[j]; }
        int m = min(32, e - j0);
        int t = 0;
        for (; t + 4 <= m; t += 4) {
            int s0 = __shfl_sync(0xffffffffu, es, t + 0);
            int s1 = __shfl_sync(0xffffffffu, es, t + 1);
            int s2 = __shfl_sync(0xffffffffu, es, t + 2);
            int s3 = __shfl_sync(0xffffffffu, es, t + 3);
            float w0 = __shfl_sync(0xffffffffu, ew, t + 0);
            float w1 = __shfl_sync(0xffffffffu, ew, t + 1);
            float w2 = __shfl_sync(0xffffffffu, ew, t + 2);
            float w3 = __shfl_sync(0xffffffffu, ew, t + 3);
            float4 v0 = *(const float4*)(base + (size_t)s0 * Fin + f);
            float4 v1 = *(const float4*)(base + (size_t)s1 * Fin + f);
            float4 v2 = *(const float4*)(base + (size_t)s2 * Fin + f);
            float4 v3 = *(const float4*)(base + (size_t)s3 * Fin + f);
            a0.x += w0 * v0.x; a0.y += w0 * v0.y; a0.z += w0 * v0.z; a0.w += w0 * v0.w;
            a1.x += w1 * v1.x; a1.y += w1 * v1.y; a1.z += w1 * v1.z; a1.w += w1 * v1.w;
            a2.x += w2 * v2.x; a2.y += w2 * v2.y; a2.z += w2 * v2.z; a2.w += w2 * v2.w;
            a3.x += w3 * v3.x; a3.y += w3 * v3.y; a3.z += w3 * v3.z; a3.w += w3 * v3.w;
        }
        for (; t < m; t++) {
            int s0 = __shfl_sync(0xffffffffu, es, t);
            float w0 = __shfl_sync(0xffffffffu, ew, t);
            float4 v0 = *(const float4*)(base + (size_t)s0 * Fin + f);
            a0.x += w0 * v0.x; a0.y += w0 * v0.y; a0.z += w0 * v0.z; a0.w += w0 * v0.w;
        }
    }
    a0.x += a1.x + a2.x + a3.x;
    a0.y += a1.y + a2.y + a3.y;
    a0.z += a1.z + a2.z + a3.z;
    a0.w += a1.w + a2.w + a3.w;
    return a0;
}

__global__ __launch_bounds__(128) void k_gprop1(
    const int* __restrict__ rowptr, const int* __restrict__ csr_src,
    const float* __restrict__ csr_w, const float* __restrict__ x,
    float* __restrict__ tx1, __half* __restrict__ Abig, int Fin)
{
    int warp = threadIdx.x >> 5, lane = threadIdx.x & 31;
    int n = blockIdx.x * 4 + warp;
    if (n >= NN) return;
    int f = blockIdx.y * 128 + lane * 4;
    float4 acc = gather_acc(csr_src, csr_w, x, Fin, f, rowptr[n], rowptr[n + 1], lane);
    float4 x0 = *(const float4*)(x + (size_t)n * Fin + f);
    __half* row = Abig + (size_t)n * 6 * Fin;
    split_write4(row, Fin, f, x0);
    split_write4(row, Fin, Fin + f, acc);
    *(float4*)(tx1 + (size_t)n * Fin + f) = acc;
}
__global__ __launch_bounds__(128) void k_gprop2(
    const int* __restrict__ rowptr, const int* __restrict__ csr_src,
    const float* __restrict__ csr_w, const float* __restrict__ x,
    const float* __restrict__ tx1, __half* __restrict__ Abig, int Fin)
{
    int warp = threadIdx.x >> 5, lane = threadIdx.x & 31;
    int n = blockIdx.x * 4 + warp;
    if (n >= NN) return;
    int f = blockIdx.y * 128 + lane * 4;
    float4 acc = gather_acc(csr_src, csr_w, tx1, Fin, f, rowptr[n], rowptr[n + 1], lane);
    float4 x0 = *(const float4*)(x + (size_t)n * Fin + f);
    float4 t2 = make_float4(2.f * acc.x - x0.x, 2.f * acc.y - x0.y,
                            2.f * acc.z - x0.z, 2.f * acc.w - x0.w);
    __half* row = Abig + (size_t)n * 6 * Fin;
    split_write4(row, Fin, 2 * Fin + f, t2);
}

// =============== B weight conversion: W[K,N] -> single hi copy [N rows, K] ===============
__global__ void k_wconv(const float* __restrict__ W, __half* __restrict__ B,
                        int K, int N) {
    int i = blockIdx.x * blockDim.x + threadIdx.x;
    if (i < K * N) {
        int k = i / N;
        int n = i - k * N;
        B[(size_t)n * K + k] = __float2half_rn(W[i]);
    }
}

// =============== mma.sync fp16 GEMM, 64x128 tile, BK=64, 3-stage cp.async ===============
// B dedup: logical k in [0,Kbig) maps to k mod Kb in memory (Kb % 64 == 0).
#define LDT 72
#define NSTAGE 3
#define A_ELEMS (64 * LDT)
#define B_ELEMS (128 * LDT)

__device__ __forceinline__ void ldm_x4(uint32_t& r0, uint32_t& r1, uint32_t& r2, uint32_t& r3,
                                       uint32_t a) {
    asm volatile("ldmatrix.sync.aligned.m8n8.x4.shared.b16 {%0,%1,%2,%3}, [%4];"
                 : "=r"(r0), "=r"(r1), "=r"(r2), "=r"(r3) : "r"(a));
}
__device__ __forceinline__ void mma_f16(float* c, const uint32_t* a, const uint32_t* b) {
    asm volatile(
        "mma.sync.aligned.m16n8k16.row.col.f32.f16.f16.f32 "
        "{%0,%1,%2,%3}, {%4,%5,%6,%7}, {%8,%9}, {%0,%1,%2,%3};"
        : "+f"(c[0]), "+f"(c[1]), "+f"(c[2]), "+f"(c[3])
        : "r"(a[0]), "r"(a[1]), "r"(a[2]), "r"(a[3]), "r"(b[0]), "r"(b[1]));
}
__device__ __forceinline__ void cp16(uint32_t dst, const void* src, int pred16) {
    asm volatile("cp.async.cg.shared.global [%0], [%1], 16, %2;"
                 :: "r"(dst), "l"(src), "r"(pred16) : "memory");
}

// Asplit != 0: write single hi fp16 row (len ldc) instead of fp32 C.
__global__ __launch_bounds__(256) void k_mgemm(
    const __half* __restrict__ A, const __half* __restrict__ B,
    const float* __restrict__ bias0, const float* __restrict__ bias1,
    float* __restrict__ C0, float* __restrict__ C1,
    __half* __restrict__ Asplit,
    int M, int Kbig, int Kb, int ldc, int relu, int split)
{
    extern __shared__ __align__(16) __half smp[];
    __half* sAp = smp;
    __half* sBp = smp + NSTAGE * A_ELEMS;

    const int tid = threadIdx.x;
    const int wid = tid >> 5;
    const int lane = tid & 31;
    const int bm = blockIdx.y * 64;
    const int bn = blockIdx.x * 128;
    const int warp_m = (wid & 1) * 32;
    const int warp_n = (wid >> 1) * 32;

    float acc[2][4][4];
#pragma unroll
    for (int i = 0; i < 2; i++)
#pragma unroll
        for (int j = 0; j < 4; j++)
#pragma unroll
            for (int q = 0; q < 4; q++) acc[i][j][q] = 0.f;

    uint32_t sA_u[NSTAGE], sB_u[NSTAGE];
#pragma unroll
    for (int s = 0; s < NSTAGE; s++) {
        sA_u[s] = smem_u32(sAp + s * A_ELEMS);
        sB_u[s] = smem_u32(sBp + s * B_ELEMS);
    }
    const int niter = Kbig >> 6;   // BK=64

    auto issue = [&](int stage, int k0) {
#pragma unroll
        for (int h = 0; h < 2; h++) {
            int c = tid + h * 256;
            int r = c >> 3, col = c & 7;
            cp16(sA_u[stage] + (r * LDT + col * 8) * 2,
                 A + (size_t)(bm + r) * Kbig + k0 + col * 8, (bm + r) < M ? 16 : 0);
        }
        int kb = (k0 < Kb) ? k0 : k0 - Kb;
#pragma unroll
        for (int h = 0; h < 4; h++) {
            int c = tid + h * 256;
            int r = c >> 3, col = c & 7;
            cp16(sB_u[stage] + (r * LDT + col * 8) * 2,
                 B + (size_t)(bn + r) * Kb + kb + col * 8, 16);
        }
        asm volatile("cp.async.commit_group;" ::: "memory");
    };

    issue(0, 0);
    issue(1, 64);

    int stage = 0;
    for (int it = 0; it < niter; it++) {
        if (it + 1 < niter) asm volatile("cp.async.wait_group 1;" ::: "memory");
        else                asm volatile("cp.async.wait_group 0;" ::: "memory");
        __syncthreads();

        if (it + 2 < niter) {
            int ns = stage + 2; if (ns >= NSTAGE) ns -= NSTAGE;
            issue(ns, (it + 2) << 6);
        }

#pragma unroll
        for (int ks = 0; ks < 4; ks++) {
            uint32_t af[2][4];
            uint32_t bf[4][2];
#pragma unroll
            for (int mf = 0; mf < 2; mf++) {
                uint32_t addr = sA_u[stage] +
                    ((warp_m + mf * 16 + (lane & 15)) * LDT + ks * 16 + (lane >> 4) * 8) * 2;
                ldm_x4(af[mf][0], af[mf][1], af[mf][2], af[mf][3], addr);
            }
#pragma unroll
            for (int nfp = 0; nfp < 2; nfp++) {
                uint32_t addr = sB_u[stage] +
                    ((warp_n + nfp * 16 + (lane & 15)) * LDT + ks * 16 + (lane >> 4) * 8) * 2;
                uint32_t r0, r1, r2, r3;
                ldm_x4(r0, r1, r2, r3, addr);
                bf[nfp * 2 + 0][0] = r0; bf[nfp * 2 + 1][0] = r1;
                bf[nfp * 2 + 0][1] = r2; bf[nfp * 2 + 1][1] = r3;
            }
#pragma unroll
            for (int mf = 0; mf < 2; mf++)
#pragma unroll
                for (int nf = 0; nf < 4; nf++)
                    mma_f16(acc[mf][nf], af[mf], bf[nf]);
        }
        if (++stage == NSTAGE) stage = 0;
    }

    // epilogue
#pragma unroll
    for (int mf = 0; mf < 2; mf++) {
#pragma unroll
        for (int nf = 0; nf < 4; nf++) {
            int row0 = bm + warp_m + mf * 16 + (lane >> 2);
            int col0 = bn + warp_n + nf * 8 + (lane & 3) * 2;
#pragma unroll
            for (int h = 0; h < 2; h++) {
                int row = row0 + h * 8;
                if (row >= M) continue;
                float v0 = acc[mf][nf][h * 2 + 0];
                float v1 = acc[mf][nf][h * 2 + 1];
                if (Asplit) {
                    v0 += bias0[col0]; v1 += bias0[col0 + 1];
                    if (relu) { v0 = fmaxf(v0, 0.f); v1 = fmaxf(v1, 0.f); }
                    // single hi copy (head consumes 1-term A)
                    *(uint32_t*)(Asplit + (size_t)row * ldc + col0) = pack_h2(v0, v1);
                } else {
                    bool second = col0 >= split;
                    const float* bs = second ? bias1 : bias0;
                    float* dst = second ? C1 : C0;
                    int cc = second ? col0 - split : col0;
                    v0 += bs[cc]; v1 += bs[cc + 1];
                    if (relu) { v0 = fmaxf(v0, 0.f); v1 = fmaxf(v1, 0.f); }
                    *(float2*)(dst + (size_t)row * ldc + cc) = make_float2(v0, v1);
                }
            }
        }
    }
}

// =============== host orchestration ===============
#define SMEM_BYTES (NSTAGE * (A_ELEMS + B_ELEMS) * 2)

static void launch_gemm(const __half* A, const __half* B,
                        const float* bias0, const float* bias1,
                        float* C0, float* C1, __half* Asplit,
                        int Kbig, int Kb, int N, int ldc, int relu, int split) {
    dim3 grid(N / 128, (NN + 63) / 64);
    k_mgemm<<<grid, 256, SMEM_BYTES>>>(A, B, bias0, bias1, C0, C1, Asplit,
                                       NN, Kbig, Kb, ldc, relu, split);
}

static void run_layer(const int* rowptr, const int* csr_src, const float* csr_w,
                      float* tx1, __half* Abig, const __half* Bbig,
                      const float* x, int Fin, int Fout,
                      const float* b, float* y, __half* Asplit) {
    dim3 pg((NN + 3) / 4, Fin / 128);
    k_gprop1<<<pg, 128>>>(rowptr, csr_src, csr_w, x, tx1, Abig, Fin);
    k_gprop2<<<pg, 128>>>(rowptr, csr_src, csr_w, x, tx1, Abig, Fin);
    launch_gemm(Abig, Bbig, b, b, y, y, Asplit, 6 * Fin, 3 * Fin, Fout, Fout, 1, Fout);
}

extern "C" void kernel_launch(void* const* d_in, const int* in_sizes, int n_in,
                              void* d_out, int out_size) {
    const float* v    = (const float*)d_in[0];
    const int* ei     = (const int*)d_in[1];
    const float* W1   = (const float*)d_in[2];
    const float* b1   = (const float*)d_in[3];
    const float* W2   = (const float*)d_in[4];
    const float* b2   = (const float*)d_in[5];
    const float* W3   = (const float*)d_in[6];
    const float* b3   = (const float*)d_in[7];
    const float* Wmu  = (const float*)d_in[8];
    const float* bmu  = (const float*)d_in[9];
    const float* Wstd = (const float*)d_in[10];
    const float* bstd = (const float*)d_in[11];
    float* out = (float*)d_out;

    static bool init_done = false;
    static cudaStream_t s2;
    static cudaEvent_t evFork, evDone, evScan, evZero;
    if (!init_done) {
        cudaFuncSetAttribute(k_mgemm, cudaFuncAttributeMaxDynamicSharedMemorySize, SMEM_BYTES);
        cudaStreamCreateWithFlags(&s2, cudaStreamNonBlocking);
        cudaEventCreateWithFlags(&evFork, cudaEventDisableTiming);
        cudaEventCreateWithFlags(&evDone, cudaEventDisableTiming);
        cudaEventCreateWithFlags(&evScan, cudaEventDisableTiming);
        cudaEventCreateWithFlags(&evZero, cudaEventDisableTiming);
        init_done = true;
    }

    float *deg, *dis, *tx1, *actA, *actB, *csr_w;
    int *cnt, *rowptr, *cursor, *csr_src;
    __half *Abig, *B1, *B2, *B3, *Bh;
    cudaGetSymbolAddress((void**)&deg,     g_deg);
    cudaGetSymbolAddress((void**)&dis,     g_dis);
    cudaGetSymbolAddress((void**)&cnt,     g_cnt);
    cudaGetSymbolAddress((void**)&rowptr,  g_rowptr);
    cudaGetSymbolAddress((void**)&cursor,  g_cursor);
    cudaGetSymbolAddress((void**)&csr_src, g_csr_src);
    cudaGetSymbolAddress((void**)&csr_w,   g_csr_w);
    cudaGetSymbolAddress((void**)&tx1,     g_tx1);
    cudaGetSymbolAddress((void**)&actA,    g_actA);
    cudaGetSymbolAddress((void**)&actB,    g_actB);
    cudaGetSymbolAddress((void**)&Abig,    g_Abig);
    cudaGetSymbolAddress((void**)&B1,      g_B1);
    cudaGetSymbolAddress((void**)&B2,      g_B2);
    cudaGetSymbolAddress((void**)&B3,      g_B3);
    cudaGetSymbolAddress((void**)&Bh,      g_Bh);

    // fork side stream: weight conversions off the critical path
    cudaEventRecord(evFork, 0);
    cudaStreamWaitEvent(s2, evFork, 0);
    k_wconv<<<(128 * 384 + 255) / 256, 256, 0, s2>>>(W1, B1, 384, 128);
    k_wconv<<<(256 * 384 + 255) / 256, 256, 0, s2>>>(W2, B2, 384, 256);
    k_wconv<<<(512 * 768 + 255) / 256, 256, 0, s2>>>(W3, B3, 768, 512);
    k_wconv<<<(256 * 512 + 255) / 256, 256, 0, s2>>>(Wmu,  Bh, 512, 256);
    k_wconv<<<(256 * 512 + 255) / 256, 256, 0, s2>>>(Wstd, Bh + (size_t)256 * 512, 512, 256);
    cudaEventRecord(evDone, s2);

    // preprocessing (deg/cnt are zero at entry)
    k_counts<<<(NE + 255) / 256, 256>>>(ei, deg, cnt);
    k_scan<<<1, 1024>>>(cnt, rowptr, cursor, deg, dis);
    cudaEventRecord(evScan, 0);
    k_scatter<<<(NE + 255) / 256, 256>>>(ei, dis, cursor, csr_src, csr_w);

    // side stream: re-zero deg/cnt for the NEXT call
    cudaStreamWaitEvent(s2, evScan, 0);
    k_zero2<<<(NN + 255) / 256, 256, 0, s2>>>(deg, cnt, NN);
    cudaEventRecord(evZero, s2);

    // L1 props, then join side stream before first GEMM
    dim3 pg1((NN + 3) / 4, 1);
    k_gprop1<<<pg1, 128>>>(rowptr, csr_src, csr_w, v, tx1, Abig, 128);
    k_gprop2<<<pg1, 128>>>(rowptr, csr_src, csr_w, v, tx1, Abig, 128);
    cudaStreamWaitEvent(0, evDone, 0);
    launch_gemm(Abig, B1, b1, b1, actA, actA, nullptr, 768, 384, 128, 128, 1, 128);

    // L2, L3 (L3 writes single-hi fp16 rows directly into Abig, ldc=512)
    run_layer(rowptr, csr_src, csr_w, tx1, Abig, B2, actA, 128, 256, b2, actB, nullptr);
    run_layer(rowptr, csr_src, csr_w, tx1, Abig, B3, actB, 256, 512, b3, nullptr, Abig);

    // fused heads: one N=512 GEMM on 1-term A (K=512, no dedup wrap), split mu|std
    launch_gemm(Abig, Bh, bmu, bstd, out, out + (size_t)NN * 256, nullptr,
                512, 512, 512, 256, 0, 256);

    cudaStreamWaitEvent(0, evZero, 0);

    (void)in_sizes; (void)n_in; (void)out_size;
}

// round 14
// speedup vs baseline: 4.7188x; 1.1443x over previous
#include <cuda_runtime.h>
#include <cuda_fp16.h>
#include <math.h>
#include <stdint.h>

#define NN 10000
#define NE 160000

// ---- scratch (static device globals; zero-initialized at module load) ----
__device__ float g_deg[NN];
__device__ float g_dis[NN];
__device__ int   g_cnt[NN];
__device__ int   g_rowptr[NN + 1];
__device__ int   g_cursor[NN];
__device__ int   g_csr_src[NE];
__device__ float g_csr_w[NE];
__device__ float g_tx1[NN * 256];
__device__ float g_actA[NN * 512];
__device__ float g_actB[NN * 512];
__device__ __half g_Abig[NN * 1536];         // L1/L2: [hi|lo] 6*Fin rows; L3: hi-only 3*Fin
// B stored deduplicated: single hi copy of length K per output row
__device__ __half g_B1[128 * 384];
__device__ __half g_B2[256 * 384];
__device__ __half g_B3[512 * 768];
__device__ __half g_Bh[512 * 512];           // [mu(256 rows) | std(256 rows)], K=512

__device__ __forceinline__ uint32_t smem_u32(const void* p) {
    uint32_t a;
    asm("{ .reg .u64 t; cvta.to.shared.u64 t, %1; cvt.u32.u64 %0, t; }" : "=r"(a) : "l"(p));
    return a;
}
__device__ __forceinline__ uint32_t pack_h2(float a, float b) {
    __half2 t = __floats2half2_rn(a, b);
    return *(uint32_t*)&t;
}

// =============== graph preprocessing ===============
__global__ void k_zero2(float* deg, int* cnt, int n) {
    int i = blockIdx.x * blockDim.x + threadIdx.x;
    if (i < n) { deg[i] = 0.f; cnt[i] = 0; }
}
__global__ void k_counts(const int* __restrict__ ei, float* __restrict__ deg,
                         int* __restrict__ cnt) {
    int e = blockIdx.x * blockDim.x + threadIdx.x;
    if (e < NE) {
        atomicAdd(&deg[ei[e]], 1.f);
        atomicAdd(&cnt[ei[NE + e]], 1);
    }
}
__global__ void k_scan(const int* __restrict__ cnt, int* __restrict__ rowptr,
                       int* __restrict__ cursor, const float* __restrict__ deg,
                       float* __restrict__ dis) {
    __shared__ int wsum[32];
    __shared__ int carry_s;
    int tid = threadIdx.x, lane = tid & 31, wid = tid >> 5;
    if (tid == 0) { carry_s = 0; rowptr[0] = 0; }
    __syncthreads();
    for (int base = 0; base < NN; base += 1024) {
        int i = base + tid;
        if (i < NN) {
            float d = deg[i];
            dis[i] = (d > 0.f) ? rsqrtf(d) : 0.f;
        }
        int v = (i < NN) ? cnt[i] : 0;
        int x = v;
#pragma unroll
        for (int o = 1; o < 32; o <<= 1) {
            int t = __shfl_up_sync(0xffffffffu, x, o);
            if (lane >= o) x += t;
        }
        if (lane == 31) wsum[wid] = x;
        __syncthreads();
        if (wid == 0) {
            int s = wsum[lane];
#pragma unroll
            for (int o = 1; o < 32; o <<= 1) {
                int t = __shfl_up_sync(0xffffffffu, s, o);
                if (lane >= o) s += t;
            }
            wsum[lane] = s;
        }
        __syncthreads();
        int inc = carry_s + ((wid > 0) ? wsum[wid - 1] : 0) + x;
        if (i < NN) { rowptr[i + 1] = inc; cursor[i] = inc - v; }
        __syncthreads();
        if (tid == 1023) carry_s = inc;
        __syncthreads();
    }
}
__global__ void k_scatter(const int* __restrict__ ei, const float* __restrict__ dis,
                          int* __restrict__ cursor, int* __restrict__ csr_src,
                          float* __restrict__ csr_w) {
    int e = blockIdx.x * blockDim.x + threadIdx.x;
    if (e < NE) {
        int r = ei[e];
        int c = ei[NE + e];
        int p = atomicAdd(&cursor[c], 1);
        csr_src[p] = r;
        csr_w[p] = -dis[r] * dis[c];
    }
}

// =============== warp-per-node CSR gather props, fused fp16 writes ===============
// two=1: row stride 6*Fin, write [hi at pos, lo at 3*Fin+pos]
// two=0: row stride 3*Fin, write hi only
__device__ __forceinline__ void split_write4(__half* row, int Fin, int pos, float4 v, int two) {
    uint2 hi = make_uint2(pack_h2(v.x, v.y), pack_h2(v.z, v.w));
    *(uint2*)(row + pos) = hi;
    if (two) {
        float hx = __half2float(__float2half_rn(v.x));
        float hy = __half2float(__float2half_rn(v.y));
        float hz = __half2float(__float2half_rn(v.z));
        float hw = __half2float(__float2half_rn(v.w));
        uint2 lo = make_uint2(pack_h2(v.x - hx, v.y - hy), pack_h2(v.z - hz, v.w - hw));
        *(uint2*)(row + 3 * Fin + pos) = lo;
    }
}
__device__ __forceinline__ float4 gather_acc(
    const int* __restrict__ csr_src, const float* __restrict__ csr_w,
    const float* __restrict__ base, int Fin, int f, int s, int e, int lane)
{
    float4 a0 = make_float4(0.f, 0.f, 0.f, 0.f);
    float4 a1 = a0, a2 = a0, a3 = a0;
    for (int j0 = s; j0 < e; j0 += 32) {
        int j = j0 + lane;
        int es = 0; float ew = 0.f;
        if (j < e) { es = csr_src[j]; ew = csr_w[j]; }
        int m = min(32, e - j0);
        int t = 0;
        for (; t + 4 <= m; t += 4) {
            int s0 = __shfl_sync(0xffffffffu, es, t + 0);
            int s1 = __shfl_sync(0xffffffffu, es, t + 1);
            int s2 = __shfl_sync(0xffffffffu, es, t + 2);
            int s3 = __shfl_sync(0xffffffffu, es, t + 3);
            float w0 = __shfl_sync(0xffffffffu, ew, t + 0);
            float w1 = __shfl_sync(0xffffffffu, ew, t + 1);
            float w2 = __shfl_sync(0xffffffffu, ew, t + 2);
            float w3 = __shfl_sync(0xffffffffu, ew, t + 3);
            float4 v0 = *(const float4*)(base + (size_t)s0 * Fin + f);
            float4 v1 = *(const float4*)(base + (size_t)s1 * Fin + f);
            float4 v2 = *(const float4*)(base + (size_t)s2 * Fin + f);
            float4 v3 = *(const float4*)(base + (size_t)s3 * Fin + f);
            a0.x += w0 * v0.x; a0.y += w0 * v0.y; a0.z += w0 * v0.z; a0.w += w0 * v0.w;
            a1.x += w1 * v1.x; a1.y += w1 * v1.y; a1.z += w1 * v1.z; a1.w += w1 * v1.w;
            a2.x += w2 * v2.x; a2.y += w2 * v2.y; a2.z += w2 * v2.z; a2.w += w2 * v2.w;
            a3.x += w3 * v3.x; a3.y += w3 * v3.y; a3.z += w3 * v3.z; a3.w += w3 * v3.w;
        }
        for (; t < m; t++) {
            int s0 = __shfl_sync(0xffffffffu, es, t);
            float w0 = __shfl_sync(0xffffffffu, ew, t);
            float4 v0 = *(const float4*)(base + (size_t)s0 * Fin + f);
            a0.x += w0 * v0.x; a0.y += w0 * v0.y; a0.z += w0 * v0.z; a0.w += w0 * v0.w;
        }
    }
    a0.x += a1.x + a2.x + a3.x;
    a0.y += a1.y + a2.y + a3.y;
    a0.z += a1.z + a2.z + a3.z;
    a0.w += a1.w + a2.w + a3.w;
    return a0;
}

__global__ __launch_bounds__(128) void k_gprop1(
    const int* __restrict__ rowptr, const int* __restrict__ csr_src,
    const float* __restrict__ csr_w, const float* __restrict__ x,
    float* __restrict__ tx1, __half* __restrict__ Abig, int Fin, int two)
{
    int warp = threadIdx.x >> 5, lane = threadIdx.x & 31;
    int n = blockIdx.x * 4 + warp;
    if (n >= NN) return;
    int f = blockIdx.y * 128 + lane * 4;
    float4 acc = gather_acc(csr_src, csr_w, x, Fin, f, rowptr[n], rowptr[n + 1], lane);
    float4 x0 = *(const float4*)(x + (size_t)n * Fin + f);
    __half* row = Abig + (size_t)n * (two ? 6 : 3) * Fin;
    split_write4(row, Fin, f, x0, two);
    split_write4(row, Fin, Fin + f, acc, two);
    *(float4*)(tx1 + (size_t)n * Fin + f) = acc;
}
__global__ __launch_bounds__(128) void k_gprop2(
    const int* __restrict__ rowptr, const int* __restrict__ csr_src,
    const float* __restrict__ csr_w, const float* __restrict__ x,
    const float* __restrict__ tx1, __half* __restrict__ Abig, int Fin, int two)
{
    int warp = threadIdx.x >> 5, lane = threadIdx.x & 31;
    int n = blockIdx.x * 4 + warp;
    if (n >= NN) return;
    int f = blockIdx.y * 128 + lane * 4;
    float4 acc = gather_acc(csr_src, csr_w, tx1, Fin, f, rowptr[n], rowptr[n + 1], lane);
    float4 x0 = *(const float4*)(x + (size_t)n * Fin + f);
    float4 t2 = make_float4(2.f * acc.x - x0.x, 2.f * acc.y - x0.y,
                            2.f * acc.z - x0.z, 2.f * acc.w - x0.w);
    __half* row = Abig + (size_t)n * (two ? 6 : 3) * Fin;
    split_write4(row, Fin, 2 * Fin + f, t2, two);
}

// =============== B weight conversion: W[K,N] -> single hi copy [N rows, K] ===============
__global__ void k_wconv(const float* __restrict__ W, __half* __restrict__ B,
                        int K, int N) {
    int i = blockIdx.x * blockDim.x + threadIdx.x;
    if (i < K * N) {
        int k = i / N;
        int n = i - k * N;
        B[(size_t)n * K + k] = __float2half_rn(W[i]);
    }
}

// =============== mma.sync fp16 GEMM, 64x128 tile, BK=64, 4-stage cp.async ===============
// B dedup: logical k in [0,Kbig) maps to k mod Kb in memory (Kb % 64 == 0).
#define LDT 72
#define NSTAGE 4
#define A_ELEMS (64 * LDT)
#define B_ELEMS (128 * LDT)

__device__ __forceinline__ void ldm_x4(uint32_t& r0, uint32_t& r1, uint32_t& r2, uint32_t& r3,
                                       uint32_t a) {
    asm volatile("ldmatrix.sync.aligned.m8n8.x4.shared.b16 {%0,%1,%2,%3}, [%4];"
                 : "=r"(r0), "=r"(r1), "=r"(r2), "=r"(r3) : "r"(a));
}
__device__ __forceinline__ void mma_f16(float* c, const uint32_t* a, const uint32_t* b) {
    asm volatile(
        "mma.sync.aligned.m16n8k16.row.col.f32.f16.f16.f32 "
        "{%0,%1,%2,%3}, {%4,%5,%6,%7}, {%8,%9}, {%0,%1,%2,%3};"
        : "+f"(c[0]), "+f"(c[1]), "+f"(c[2]), "+f"(c[3])
        : "r"(a[0]), "r"(a[1]), "r"(a[2]), "r"(a[3]), "r"(b[0]), "r"(b[1]));
}
__device__ __forceinline__ void cp16(uint32_t dst, const void* src, int pred16) {
    asm volatile("cp.async.cg.shared.global [%0], [%1], 16, %2;"
                 :: "r"(dst), "l"(src), "r"(pred16) : "memory");
}

// Asplit != 0: write single hi fp16 row (len ldc) instead of fp32 C.
__global__ __launch_bounds__(256) void k_mgemm(
    const __half* __restrict__ A, const __half* __restrict__ B,
    const float* __restrict__ bias0, const float* __restrict__ bias1,
    float* __restrict__ C0, float* __restrict__ C1,
    __half* __restrict__ Asplit,
    int M, int Kbig, int Kb, int ldc, int relu, int split)
{
    extern __shared__ __align__(16) __half smp[];
    __half* sAp = smp;
    __half* sBp = smp + NSTAGE * A_ELEMS;

    const int tid = threadIdx.x;
    const int wid = tid >> 5;
    const int lane = tid & 31;
    const int bm = blockIdx.y * 64;
    const int bn = blockIdx.x * 128;
    const int warp_m = (wid & 1) * 32;
    const int warp_n = (wid >> 1) * 32;

    float acc[2][4][4];
#pragma unroll
    for (int i = 0; i < 2; i++)
#pragma unroll
        for (int j = 0; j < 4; j++)
#pragma unroll
            for (int q = 0; q < 4; q++) acc[i][j][q] = 0.f;

    uint32_t sA_u[NSTAGE], sB_u[NSTAGE];
#pragma unroll
    for (int s = 0; s < NSTAGE; s++) {
        sA_u[s] = smem_u32(sAp + s * A_ELEMS);
        sB_u[s] = smem_u32(sBp + s * B_ELEMS);
    }
    const int niter = Kbig >> 6;   // BK=64; min niter = 8 (head)

    auto issue = [&](int stage, int k0) {
#pragma unroll
        for (int h = 0; h < 2; h++) {
            int c = tid + h * 256;
            int r = c >> 3, col = c & 7;
            cp16(sA_u[stage] + (r * LDT + col * 8) * 2,
                 A + (size_t)(bm + r) * Kbig + k0 + col * 8, (bm + r) < M ? 16 : 0);
        }
        int kb = (k0 < Kb) ? k0 : k0 - Kb;
#pragma unroll
        for (int h = 0; h < 4; h++) {
            int c = tid + h * 256;
            int r = c >> 3, col = c & 7;
            cp16(sB_u[stage] + (r * LDT + col * 8) * 2,
                 B + (size_t)(bn + r) * Kb + kb + col * 8, 16);
        }
        asm volatile("cp.async.commit_group;" ::: "memory");
    };

    issue(0, 0);
    issue(1, 64);
    issue(2, 128);

    int stage = 0;
    for (int it = 0; it < niter; it++) {
        const int ahead = niter - 1 - it;
        if (ahead >= 2)      asm volatile("cp.async.wait_group 2;" ::: "memory");
        else if (ahead == 1) asm volatile("cp.async.wait_group 1;" ::: "memory");
        else                 asm volatile("cp.async.wait_group 0;" ::: "memory");
        __syncthreads();

        if (it + 3 < niter) {
            int ns = stage + 3; if (ns >= NSTAGE) ns -= NSTAGE;
            issue(ns, (it + 3) << 6);
        }

#pragma unroll
        for (int ks = 0; ks < 4; ks++) {
            uint32_t af[2][4];
            uint32_t bf[4][2];
#pragma unroll
            for (int mf = 0; mf < 2; mf++) {
                uint32_t addr = sA_u[stage] +
                    ((warp_m + mf * 16 + (lane & 15)) * LDT + ks * 16 + (lane >> 4) * 8) * 2;
                ldm_x4(af[mf][0], af[mf][1], af[mf][2], af[mf][3], addr);
            }
#pragma unroll
            for (int nfp = 0; nfp < 2; nfp++) {
                uint32_t addr = sB_u[stage] +
                    ((warp_n + nfp * 16 + (lane & 15)) * LDT + ks * 16 + (lane >> 4) * 8) * 2;
                uint32_t r0, r1, r2, r3;
                ldm_x4(r0, r1, r2, r3, addr);
                bf[nfp * 2 + 0][0] = r0; bf[nfp * 2 + 1][0] = r1;
                bf[nfp * 2 + 0][1] = r2; bf[nfp * 2 + 1][1] = r3;
            }
#pragma unroll
            for (int mf = 0; mf < 2; mf++)
#pragma unroll
                for (int nf = 0; nf < 4; nf++)
                    mma_f16(acc[mf][nf], af[mf], bf[nf]);
        }
        if (++stage == NSTAGE) stage = 0;
    }

    // epilogue
#pragma unroll
    for (int mf = 0; mf < 2; mf++) {
#pragma unroll
        for (int nf = 0; nf < 4; nf++) {
            int row0 = bm + warp_m + mf * 16 + (lane >> 2);
            int col0 = bn + warp_n + nf * 8 + (lane & 3) * 2;
#pragma unroll
            for (int h = 0; h < 2; h++) {
                int row = row0 + h * 8;
                if (row >= M) continue;
                float v0 = acc[mf][nf][h * 2 + 0];
                float v1 = acc[mf][nf][h * 2 + 1];
                if (Asplit) {
                    v0 += bias0[col0]; v1 += bias0[col0 + 1];
                    if (relu) { v0 = fmaxf(v0, 0.f); v1 = fmaxf(v1, 0.f); }
                    *(uint32_t*)(Asplit + (size_t)row * ldc + col0) = pack_h2(v0, v1);
                } else {
                    bool second = col0 >= split;
                    const float* bs = second ? bias1 : bias0;
                    float* dst = second ? C1 : C0;
                    int cc = second ? col0 - split : col0;
                    v0 += bs[cc]; v1 += bs[cc + 1];
                    if (relu) { v0 = fmaxf(v0, 0.f); v1 = fmaxf(v1, 0.f); }
                    *(float2*)(dst + (size_t)row * ldc + cc) = make_float2(v0, v1);
                }
            }
        }
    }
}

// =============== host orchestration ===============
#define SMEM_BYTES (NSTAGE * (A_ELEMS + B_ELEMS) * 2)

static void launch_gemm(const __half* A, const __half* B,
                        const float* bias0, const float* bias1,
                        float* C0, float* C1, __half* Asplit,
                        int Kbig, int Kb, int N, int ldc, int relu, int split) {
    dim3 grid(N / 128, (NN + 63) / 64);
    k_mgemm<<<grid, 256, SMEM_BYTES>>>(A, B, bias0, bias1, C0, C1, Asplit,
                                       NN, Kbig, Kb, ldc, relu, split);
}

// two_term: 1 -> A rows [hi|lo] (Kbig=6*Fin, Kb=3*Fin); 0 -> hi only (Kbig=Kb=3*Fin)
static void run_layer(const int* rowptr, const int* csr_src, const float* csr_w,
                      float* tx1, __half* Abig, const __half* Bbig,
                      const float* x, int Fin, int Fout,
                      const float* b, float* y, __half* Asplit, int two_term) {
    dim3 pg((NN + 3) / 4, Fin / 128);
    k_gprop1<<<pg, 128>>>(rowptr, csr_src, csr_w, x, tx1, Abig, Fin, two_term);
    k_gprop2<<<pg, 128>>>(rowptr, csr_src, csr_w, x, tx1, Abig, Fin, two_term);
    int Kbig = (two_term ? 6 : 3) * Fin;
    launch_gemm(Abig, Bbig, b, b, y, y, Asplit, Kbig, 3 * Fin, Fout, Fout, 1, Fout);
}

extern "C" void kernel_launch(void* const* d_in, const int* in_sizes, int n_in,
                              void* d_out, int out_size) {
    const float* v    = (const float*)d_in[0];
    const int* ei     = (const int*)d_in[1];
    const float* W1   = (const float*)d_in[2];
    const float* b1   = (const float*)d_in[3];
    const float* W2   = (const float*)d_in[4];
    const float* b2   = (const float*)d_in[5];
    const float* W3   = (const float*)d_in[6];
    const float* b3   = (const float*)d_in[7];
    const float* Wmu  = (const float*)d_in[8];
    const float* bmu  = (const float*)d_in[9];
    const float* Wstd = (const float*)d_in[10];
    const float* bstd = (const float*)d_in[11];
    float* out = (float*)d_out;

    static bool init_done = false;
    static cudaStream_t s2;
    static cudaEvent_t evFork, evDone, evScan, evZero;
    if (!init_done) {
        cudaFuncSetAttribute(k_mgemm, cudaFuncAttributeMaxDynamicSharedMemorySize, SMEM_BYTES);
        cudaStreamCreateWithFlags(&s2, cudaStreamNonBlocking);
        cudaEventCreateWithFlags(&evFork, cudaEventDisableTiming);
        cudaEventCreateWithFlags(&evDone, cudaEventDisableTiming);
        cudaEventCreateWithFlags(&evScan, cudaEventDisableTiming);
        cudaEventCreateWithFlags(&evZero, cudaEventDisableTiming);
        init_done = true;
    }

    float *deg, *dis, *tx1, *actA, *actB, *csr_w;
    int *cnt, *rowptr, *cursor, *csr_src;
    __half *Abig, *B1, *B2, *B3, *Bh;
    cudaGetSymbolAddress((void**)&deg,     g_deg);
    cudaGetSymbolAddress((void**)&dis,     g_dis);
    cudaGetSymbolAddress((void**)&cnt,     g_cnt);
    cudaGetSymbolAddress((void**)&rowptr,  g_rowptr);
    cudaGetSymbolAddress((void**)&cursor,  g_cursor);
    cudaGetSymbolAddress((void**)&csr_src, g_csr_src);
    cudaGetSymbolAddress((void**)&csr_w,   g_csr_w);
    cudaGetSymbolAddress((void**)&tx1,     g_tx1);
    cudaGetSymbolAddress((void**)&actA,    g_actA);
    cudaGetSymbolAddress((void**)&actB,    g_actB);
    cudaGetSymbolAddress((void**)&Abig,    g_Abig);
    cudaGetSymbolAddress((void**)&B1,      g_B1);
    cudaGetSymbolAddress((void**)&B2,      g_B2);
    cudaGetSymbolAddress((void**)&B3,      g_B3);
    cudaGetSymbolAddress((void**)&Bh,      g_Bh);

    // fork side stream: weight conversions off the critical path
    cudaEventRecord(evFork, 0);
    cudaStreamWaitEvent(s2, evFork, 0);
    k_wconv<<<(128 * 384 + 255) / 256, 256, 0, s2>>>(W1, B1, 384, 128);
    k_wconv<<<(256 * 384 + 255) / 256, 256, 0, s2>>>(W2, B2, 384, 256);
    k_wconv<<<(512 * 768 + 255) / 256, 256, 0, s2>>>(W3, B3, 768, 512);
    k_wconv<<<(256 * 512 + 255) / 256, 256, 0, s2>>>(Wmu,  Bh, 512, 256);
    k_wconv<<<(256 * 512 + 255) / 256, 256, 0, s2>>>(Wstd, Bh + (size_t)256 * 512, 512, 256);
    cudaEventRecord(evDone, s2);

    // preprocessing (deg/cnt are zero at entry)
    k_counts<<<(NE + 255) / 256, 256>>>(ei, deg, cnt);
    k_scan<<<1, 1024>>>(cnt, rowptr, cursor, deg, dis);
    cudaEventRecord(evScan, 0);
    k_scatter<<<(NE + 255) / 256, 256>>>(ei, dis, cursor, csr_src, csr_w);

    // side stream: re-zero deg/cnt for the NEXT call
    cudaStreamWaitEvent(s2, evScan, 0);
    k_zero2<<<(NN + 255) / 256, 256, 0, s2>>>(deg, cnt, NN);
    cudaEventRecord(evZero, s2);

    // L1 props (2-term), then join side stream before first GEMM
    dim3 pg1((NN + 3) / 4, 1);
    k_gprop1<<<pg1, 128>>>(rowptr, csr_src, csr_w, v, tx1, Abig, 128, 1);
    k_gprop2<<<pg1, 128>>>(rowptr, csr_src, csr_w, v, tx1, Abig, 128, 1);
    cudaStreamWaitEvent(0, evDone, 0);
    launch_gemm(Abig, B1, b1, b1, actA, actA, nullptr, 768, 384, 128, 128, 1, 128);

    // L2 (2-term); L3 (1-term A — feeds only the linear head, no recursion amplification)
    run_layer(rowptr, csr_src, csr_w, tx1, Abig, B2, actA, 128, 256, b2, actB, nullptr, 1);
    run_layer(rowptr, csr_src, csr_w, tx1, Abig, B3, actB, 256, 512, b3, nullptr, Abig, 0);

    // fused heads: one N=512 GEMM on 1-term A (K=512), split mu|std
    launch_gemm(Abig, Bh, bmu, bstd, out, out + (size_t)NN * 256, nullptr,
                512, 512, 512, 256, 0, 256);

    cudaStreamWaitEvent(0, evZero, 0);

    (void)in_sizes; (void)n_in; (void)out_size;
}

// round 15
// speedup vs baseline: 4.7800x; 1.0130x over previous
#include <cuda_runtime.h>
#include <cuda_fp16.h>
#include <math.h>
#include <stdint.h>

#define NN 10000
#define NE 160000

// ---- scratch (static device globals; zero-initialized at module load) ----
__device__ float g_deg[NN];
__device__ float g_dis[NN];
__device__ int   g_cnt[NN];
__device__ int   g_rowptr[NN + 1];
__device__ int   g_cursor[NN];
__device__ int   g_csr_src[NE];
__device__ float g_csr_w[NE];
__device__ float g_tx1[NN * 128];            // fp32 tx1 (L1/L2 prop2 input, Fin=128)
__device__ float g_actA[NN * 128];           // L1 output fp32 (L2 props need fp32)
__device__ __half g_xh[NN * 256];            // L2 output fp16 (L3 prop input)
__device__ __half g_tx1h[NN * 256];          // L3 tx1 fp16
__device__ __half g_Abig[NN * 1536];         // GEMM A: L1/L2 [hi|lo] 6*Fin; L3 hi-only 768
__device__ __half g_Ah[NN * 512];            // head A (hi-only, from L3 epilogue)
// B stored deduplicated: single hi copy of length K per output row
__device__ __half g_B1[128 * 384];
__device__ __half g_B2[256 * 384];
__device__ __half g_B3[512 * 768];
__device__ __half g_Bh[512 * 512];           // [mu(256 rows) | std(256 rows)], K=512

__device__ __forceinline__ uint32_t smem_u32(const void* p) {
    uint32_t a;
    asm("{ .reg .u64 t; cvta.to.shared.u64 t, %1; cvt.u32.u64 %0, t; }" : "=r"(a) : "l"(p));
    return a;
}
__device__ __forceinline__ uint32_t pack_h2(float a, float b) {
    __half2 t = __floats2half2_rn(a, b);
    return *(uint32_t*)&t;
}

// =============== graph preprocessing ===============
__global__ void k_zero2(float* deg, int* cnt, int n) {
    int i = blockIdx.x * blockDim.x + threadIdx.x;
    if (i < n) { deg[i] = 0.f; cnt[i] = 0; }
}
__global__ void k_counts(const int* __restrict__ ei, float* __restrict__ deg,
                         int* __restrict__ cnt) {
    int e = blockIdx.x * blockDim.x + threadIdx.x;
    if (e < NE) {
        atomicAdd(&deg[ei[e]], 1.f);
        atomicAdd(&cnt[ei[NE + e]], 1);
    }
}
__global__ void k_scan(const int* __restrict__ cnt, int* __restrict__ rowptr,
                       int* __restrict__ cursor, const float* __restrict__ deg,
                       float* __restrict__ dis) {
    __shared__ int wsum[32];
    __shared__ int carry_s;
    int tid = threadIdx.x, lane = tid & 31, wid = tid >> 5;
    if (tid == 0) { carry_s = 0; rowptr[0] = 0; }
    __syncthreads();
    for (int base = 0; base < NN; base += 1024) {
        int i = base + tid;
        if (i < NN) {
            float d = deg[i];
            dis[i] = (d > 0.f) ? rsqrtf(d) : 0.f;
        }
        int v = (i < NN) ? cnt[i] : 0;
        int x = v;
#pragma unroll
        for (int o = 1; o < 32; o <<= 1) {
            int t = __shfl_up_sync(0xffffffffu, x, o);
            if (lane >= o) x += t;
        }
        if (lane == 31) wsum[wid] = x;
        __syncthreads();
        if (wid == 0) {
            int s = wsum[lane];
#pragma unroll
            for (int o = 1; o < 32; o <<= 1) {
                int t = __shfl_up_sync(0xffffffffu, s, o);
                if (lane >= o) s += t;
            }
            wsum[lane] = s;
        }
        __syncthreads();
        int inc = carry_s + ((wid > 0) ? wsum[wid - 1] : 0) + x;
        if (i < NN) { rowptr[i + 1] = inc; cursor[i] = inc - v; }
        __syncthreads();
        if (tid == 1023) carry_s = inc;
        __syncthreads();
    }
}
__global__ void k_scatter(const int* __restrict__ ei, const float* __restrict__ dis,
                          int* __restrict__ cursor, int* __restrict__ csr_src,
                          float* __restrict__ csr_w) {
    int e = blockIdx.x * blockDim.x + threadIdx.x;
    if (e < NE) {
        int r = ei[e];
        int c = ei[NE + e];
        int p = atomicAdd(&cursor[c], 1);
        csr_src[p] = r;
        csr_w[p] = -dis[r] * dis[c];
    }
}

// =============== fp32-gather props (L1/L2, Fin=128, 2-term writes) ===============
__device__ __forceinline__ void split_write4(__half* row, int Fin, int pos, float4 v) {
    float hx = __half2float(__float2half_rn(v.x));
    float hy = __half2float(__float2half_rn(v.y));
    float hz = __half2float(__float2half_rn(v.z));
    float hw = __half2float(__float2half_rn(v.w));
    uint2 hi = make_uint2(pack_h2(v.x, v.y), pack_h2(v.z, v.w));
    uint2 lo = make_uint2(pack_h2(v.x - hx, v.y - hy), pack_h2(v.z - hz, v.w - hw));
    *(uint2*)(row + pos) = hi;
    *(uint2*)(row + 3 * Fin + pos) = lo;
}
__device__ __forceinline__ float4 gather_acc(
    const int* __restrict__ csr_src, const float* __restrict__ csr_w,
    const float* __restrict__ base, int Fin, int f, int s, int e, int lane)
{
    float4 a0 = make_float4(0.f, 0.f, 0.f, 0.f);
    float4 a1 = a0, a2 = a0, a3 = a0;
    for (int j0 = s; j0 < e; j0 += 32) {
        int j = j0 + lane;
        int es = 0; float ew = 0.f;
        if (j < e) { es = csr_src[j]; ew = csr_w[j]; }
        int m = min(32, e - j0);
        int t = 0;
        for (; t + 4 <= m; t += 4) {
            int s0 = __shfl_sync(0xffffffffu, es, t + 0);
            int s1 = __shfl_sync(0xffffffffu, es, t + 1);
            int s2 = __shfl_sync(0xffffffffu, es, t + 2);
            int s3 = __shfl_sync(0xffffffffu, es, t + 3);
            float w0 = __shfl_sync(0xffffffffu, ew, t + 0);
            float w1 = __shfl_sync(0xffffffffu, ew, t + 1);
            float w2 = __shfl_sync(0xffffffffu, ew, t + 2);
            float w3 = __shfl_sync(0xffffffffu, ew, t + 3);
            float4 v0 = *(const float4*)(base + (size_t)s0 * Fin + f);
            float4 v1 = *(const float4*)(base + (size_t)s1 * Fin + f);
            float4 v2 = *(const float4*)(base + (size_t)s2 * Fin + f);
            float4 v3 = *(const float4*)(base + (size_t)s3 * Fin + f);
            a0.x += w0 * v0.x; a0.y += w0 * v0.y; a0.z += w0 * v0.z; a0.w += w0 * v0.w;
            a1.x += w1 * v1.x; a1.y += w1 * v1.y; a1.z += w1 * v1.z; a1.w += w1 * v1.w;
            a2.x += w2 * v2.x; a2.y += w2 * v2.y; a2.z += w2 * v2.z; a2.w += w2 * v2.w;
            a3.x += w3 * v3.x; a3.y += w3 * v3.y; a3.z += w3 * v3.z; a3.w += w3 * v3.w;
        }
        for (; t < m; t++) {
            int s0 = __shfl_sync(0xffffffffu, es, t);
            float w0 = __shfl_sync(0xffffffffu, ew, t);
            float4 v0 = *(const float4*)(base + (size_t)s0 * Fin + f);
            a0.x += w0 * v0.x; a0.y += w0 * v0.y; a0.z += w0 * v0.z; a0.w += w0 * v0.w;
        }
    }
    a0.x += a1.x + a2.x + a3.x;
    a0.y += a1.y + a2.y + a3.y;
    a0.z += a1.z + a2.z + a3.z;
    a0.w += a1.w + a2.w + a3.w;
    return a0;
}
// Fin=128: one block covers all features (y-grid = 1)
__global__ __launch_bounds__(128) void k_gprop1(
    const int* __restrict__ rowptr, const int* __restrict__ csr_src,
    const float* __restrict__ csr_w, const float* __restrict__ x,
    float* __restrict__ tx1, __half* __restrict__ Abig)
{
    const int Fin = 128;
    int warp = threadIdx.x >> 5, lane = threadIdx.x & 31;
    int n = blockIdx.x * 4 + warp;
    if (n >= NN) return;
    int f = lane * 4;
    float4 acc = gather_acc(csr_src, csr_w, x, Fin, f, rowptr[n], rowptr[n + 1], lane);
    float4 x0 = *(const float4*)(x + (size_t)n * Fin + f);
    __half* row = Abig + (size_t)n * 6 * Fin;
    split_write4(row, Fin, f, x0);
    split_write4(row, Fin, Fin + f, acc);
    *(float4*)(tx1 + (size_t)n * Fin + f) = acc;
}
__global__ __launch_bounds__(128) void k_gprop2(
    const int* __restrict__ rowptr, const int* __restrict__ csr_src,
    const float* __restrict__ csr_w, const float* __restrict__ x,
    const float* __restrict__ tx1, __half* __restrict__ Abig)
{
    const int Fin = 128;
    int warp = threadIdx.x >> 5, lane = threadIdx.x & 31;
    int n = blockIdx.x * 4 + warp;
    if (n >= NN) return;
    int f = lane * 4;
    float4 acc = gather_acc(csr_src, csr_w, tx1, Fin, f, rowptr[n], rowptr[n + 1], lane);
    float4 x0 = *(const float4*)(x + (size_t)n * Fin + f);
    float4 t2 = make_float4(2.f * acc.x - x0.x, 2.f * acc.y - x0.y,
                            2.f * acc.z - x0.z, 2.f * acc.w - x0.w);
    __half* row = Abig + (size_t)n * 6 * Fin;
    split_write4(row, Fin, 2 * Fin + f, t2);
}

// =============== fp16-gather props (L3, Fin=256, hi-only writes) ===============
// lane covers 8 features (uint4 = 8 halves); Abig rows stride 768.
__device__ __forceinline__ void h8_acc(float* acc, uint4 v, float w) {
    const __half2* h = (const __half2*)&v;
#pragma unroll
    for (int q = 0; q < 4; q++) {
        float2 fv = __half22float2(h[q]);
        acc[2 * q]     += w * fv.x;
        acc[2 * q + 1] += w * fv.y;
    }
}
__device__ __forceinline__ void gather_acc_h(
    float* acc, const int* __restrict__ csr_src, const float* __restrict__ csr_w,
    const __half* __restrict__ base, int f, int s, int e, int lane)
{
    for (int j0 = s; j0 < e; j0 += 32) {
        int j = j0 + lane;
        int es = 0; float ew = 0.f;
        if (j < e) { es = csr_src[j]; ew = csr_w[j]; }
        int m = min(32, e - j0);
        int t = 0;
        for (; t + 4 <= m; t += 4) {
            int s0 = __shfl_sync(0xffffffffu, es, t + 0);
            int s1 = __shfl_sync(0xffffffffu, es, t + 1);
            int s2 = __shfl_sync(0xffffffffu, es, t + 2);
            int s3 = __shfl_sync(0xffffffffu, es, t + 3);
            float w0 = __shfl_sync(0xffffffffu, ew, t + 0);
            float w1 = __shfl_sync(0xffffffffu, ew, t + 1);
            float w2 = __shfl_sync(0xffffffffu, ew, t + 2);
            float w3 = __shfl_sync(0xffffffffu, ew, t + 3);
            uint4 v0 = *(const uint4*)(base + (size_t)s0 * 256 + f);
            uint4 v1 = *(const uint4*)(base + (size_t)s1 * 256 + f);
            uint4 v2 = *(const uint4*)(base + (size_t)s2 * 256 + f);
            uint4 v3 = *(const uint4*)(base + (size_t)s3 * 256 + f);
            h8_acc(acc, v0, w0);
            h8_acc(acc, v1, w1);
            h8_acc(acc, v2, w2);
            h8_acc(acc, v3, w3);
        }
        for (; t < m; t++) {
            int s0 = __shfl_sync(0xffffffffu, es, t);
            float w0 = __shfl_sync(0xffffffffu, ew, t);
            uint4 v0 = *(const uint4*)(base + (size_t)s0 * 256 + f);
            h8_acc(acc, v0, w0);
        }
    }
}
__device__ __forceinline__ uint4 pack_h8(const float* a) {
    uint4 r;
    r.x = pack_h2(a[0], a[1]);
    r.y = pack_h2(a[2], a[3]);
    r.z = pack_h2(a[4], a[5]);
    r.w = pack_h2(a[6], a[7]);
    return r;
}
__global__ __launch_bounds__(128) void k_gprop1h(
    const int* __restrict__ rowptr, const int* __restrict__ csr_src,
    const float* __restrict__ csr_w, const __half* __restrict__ xh,
    __half* __restrict__ tx1h, __half* __restrict__ Abig)
{
    int warp = threadIdx.x >> 5, lane = threadIdx.x & 31;
    int n = blockIdx.x * 4 + warp;
    if (n >= NN) return;
    int f = lane * 8;
    float acc[8] = {0.f, 0.f, 0.f, 0.f, 0.f, 0.f, 0.f, 0.f};
    gather_acc_h(acc, csr_src, csr_w, xh, f, rowptr[n], rowptr[n + 1], lane);
    uint4 x0 = *(const uint4*)(xh + (size_t)n * 256 + f);   // already fp16 hi
    __half* row = Abig + (size_t)n * 768;
    *(uint4*)(row + f) = x0;                 // slot0 = x (copy)
    uint4 p = pack_h8(acc);
    *(uint4*)(row + 256 + f) = p;            // slot1 = tx1 hi
    *(uint4*)(tx1h + (size_t)n * 256 + f) = p;
}
__global__ __launch_bounds__(128) void k_gprop2h(
    const int* __restrict__ rowptr, const int* __restrict__ csr_src,
    const float* __restrict__ csr_w, const __half* __restrict__ xh,
    const __half* __restrict__ tx1h, __half* __restrict__ Abig)
{
    int warp = threadIdx.x >> 5, lane = threadIdx.x & 31;
    int n = blockIdx.x * 4 + warp;
    if (n >= NN) return;
    int f = lane * 8;
    float acc[8] = {0.f, 0.f, 0.f, 0.f, 0.f, 0.f, 0.f, 0.f};
    gather_acc_h(acc, csr_src, csr_w, tx1h, f, rowptr[n], rowptr[n + 1], lane);
    uint4 x0 = *(const uint4*)(xh + (size_t)n * 256 + f);
    const __half2* xh2 = (const __half2*)&x0;
    float t2[8];
#pragma unroll
    for (int q = 0; q < 4; q++) {
        float2 fv = __half22float2(xh2[q]);
        t2[2 * q]     = 2.f * acc[2 * q]     - fv.x;
        t2[2 * q + 1] = 2.f * acc[2 * q + 1] - fv.y;
    }
    *(uint4*)(Abig + (size_t)n * 768 + 512 + f) = pack_h8(t2);  // slot2 = tx2 hi
}

// =============== B weight conversion: W[K,N] -> single hi copy [N rows, K] ===============
__global__ void k_wconv(const float* __restrict__ W, __half* __restrict__ B,
                        int K, int N) {
    int i = blockIdx.x * blockDim.x + threadIdx.x;
    if (i < K * N) {
        int k = i / N;
        int n = i - k * N;
        B[(size_t)n * K + k] = __float2half_rn(W[i]);
    }
}

// =============== mma.sync fp16 GEMM, 64x128 tile, BK=64, 4-stage cp.async ===============
#define LDT 72
#define NSTAGE 4
#define A_ELEMS (64 * LDT)
#define B_ELEMS (128 * LDT)

__device__ __forceinline__ void ldm_x4(uint32_t& r0, uint32_t& r1, uint32_t& r2, uint32_t& r3,
                                       uint32_t a) {
    asm volatile("ldmatrix.sync.aligned.m8n8.x4.shared.b16 {%0,%1,%2,%3}, [%4];"
                 : "=r"(r0), "=r"(r1), "=r"(r2), "=r"(r3) : "r"(a));
}
__device__ __forceinline__ void mma_f16(float* c, const uint32_t* a, const uint32_t* b) {
    asm volatile(
        "mma.sync.aligned.m16n8k16.row.col.f32.f16.f16.f32 "
        "{%0,%1,%2,%3}, {%4,%5,%6,%7}, {%8,%9}, {%0,%1,%2,%3};"
        : "+f"(c[0]), "+f"(c[1]), "+f"(c[2]), "+f"(c[3])
        : "r"(a[0]), "r"(a[1]), "r"(a[2]), "r"(a[3]), "r"(b[0]), "r"(b[1]));
}
__device__ __forceinline__ void cp16(uint32_t dst, const void* src, int pred16) {
    asm volatile("cp.async.cg.shared.global [%0], [%1], 16, %2;"
                 :: "r"(dst), "l"(src), "r"(pred16) : "memory");
}

// Asplit != 0: write single hi fp16 row (len ldc) instead of fp32 C.
__global__ __launch_bounds__(256) void k_mgemm(
    const __half* __restrict__ A, const __half* __restrict__ B,
    const float* __restrict__ bias0, const float* __restrict__ bias1,
    float* __restrict__ C0, float* __restrict__ C1,
    __half* __restrict__ Asplit,
    int M, int Kbig, int Kb, int ldc, int relu, int split)
{
    extern __shared__ __align__(16) __half smp[];
    __half* sAp = smp;
    __half* sBp = smp + NSTAGE * A_ELEMS;

    const int tid = threadIdx.x;
    const int wid = tid >> 5;
    const int lane = tid & 31;
    const int bm = blockIdx.y * 64;
    const int bn = blockIdx.x * 128;
    const int warp_m = (wid & 1) * 32;
    const int warp_n = (wid >> 1) * 32;

    float acc[2][4][4];
#pragma unroll
    for (int i = 0; i < 2; i++)
#pragma unroll
        for (int j = 0; j < 4; j++)
#pragma unroll
            for (int q = 0; q < 4; q++) acc[i][j][q] = 0.f;

    uint32_t sA_u[NSTAGE], sB_u[NSTAGE];
#pragma unroll
    for (int s = 0; s < NSTAGE; s++) {
        sA_u[s] = smem_u32(sAp + s * A_ELEMS);
        sB_u[s] = smem_u32(sBp + s * B_ELEMS);
    }
    const int niter = Kbig >> 6;

    auto issue = [&](int stage, int k0) {
#pragma unroll
        for (int h = 0; h < 2; h++) {
            int c = tid + h * 256;
            int r = c >> 3, col = c & 7;
            cp16(sA_u[stage] + (r * LDT + col * 8) * 2,
                 A + (size_t)(bm + r) * Kbig + k0 + col * 8, (bm + r) < M ? 16 : 0);
        }
        int kb = (k0 < Kb) ? k0 : k0 - Kb;
#pragma unroll
        for (int h = 0; h < 4; h++) {
            int c = tid + h * 256;
            int r = c >> 3, col = c & 7;
            cp16(sB_u[stage] + (r * LDT + col * 8) * 2,
                 B + (size_t)(bn + r) * Kb + kb + col * 8, 16);
        }
        asm volatile("cp.async.commit_group;" ::: "memory");
    };

    issue(0, 0);
    issue(1, 64);
    issue(2, 128);

    int stage = 0;
    for (int it = 0; it < niter; it++) {
        const int ahead = niter - 1 - it;
        if (ahead >= 2)      asm volatile("cp.async.wait_group 2;" ::: "memory");
        else if (ahead == 1) asm volatile("cp.async.wait_group 1;" ::: "memory");
        else                 asm volatile("cp.async.wait_group 0;" ::: "memory");
        __syncthreads();

        if (it + 3 < niter) {
            int ns = stage + 3; if (ns >= NSTAGE) ns -= NSTAGE;
            issue(ns, (it + 3) << 6);
        }

#pragma unroll
        for (int ks = 0; ks < 4; ks++) {
            uint32_t af[2][4];
            uint32_t bf[4][2];
#pragma unroll
            for (int mf = 0; mf < 2; mf++) {
                uint32_t addr = sA_u[stage] +
                    ((warp_m + mf * 16 + (lane & 15)) * LDT + ks * 16 + (lane >> 4) * 8) * 2;
                ldm_x4(af[mf][0], af[mf][1], af[mf][2], af[mf][3], addr);
            }
#pragma unroll
            for (int nfp = 0; nfp < 2; nfp++) {
                uint32_t addr = sB_u[stage] +
                    ((warp_n + nfp * 16 + (lane & 15)) * LDT + ks * 16 + (lane >> 4) * 8) * 2;
                uint32_t r0, r1, r2, r3;
                ldm_x4(r0, r1, r2, r3, addr);
                bf[nfp * 2 + 0][0] = r0; bf[nfp * 2 + 1][0] = r1;
                bf[nfp * 2 + 0][1] = r2; bf[nfp * 2 + 1][1] = r3;
            }
#pragma unroll
            for (int mf = 0; mf < 2; mf++)
#pragma unroll
                for (int nf = 0; nf < 4; nf++)
                    mma_f16(acc[mf][nf], af[mf], bf[nf]);
        }
        if (++stage == NSTAGE) stage = 0;
    }

    // epilogue
#pragma unroll
    for (int mf = 0; mf < 2; mf++) {
#pragma unroll
        for (int nf = 0; nf < 4; nf++) {
            int row0 = bm + warp_m + mf * 16 + (lane >> 2);
            int col0 = bn + warp_n + nf * 8 + (lane & 3) * 2;
#pragma unroll
            for (int h = 0; h < 2; h++) {
                int row = row0 + h * 8;
                if (row >= M) continue;
                float v0 = acc[mf][nf][h * 2 + 0];
                float v1 = acc[mf][nf][h * 2 + 1];
                if (Asplit) {
                    v0 += bias0[col0]; v1 += bias0[col0 + 1];
                    if (relu) { v0 = fmaxf(v0, 0.f); v1 = fmaxf(v1, 0.f); }
                    *(uint32_t*)(Asplit + (size_t)row * ldc + col0) = pack_h2(v0, v1);
                } else {
                    bool second = col0 >= split;
                    const float* bs = second ? bias1 : bias0;
                    float* dst = second ? C1 : C0;
                    int cc = second ? col0 - split : col0;
                    v0 += bs[cc]; v1 += bs[cc + 1];
                    if (relu) { v0 = fmaxf(v0, 0.f); v1 = fmaxf(v1, 0.f); }
                    *(float2*)(dst + (size_t)row * ldc + cc) = make_float2(v0, v1);
                }
            }
        }
    }
}

// =============== host orchestration ===============
#define SMEM_BYTES (NSTAGE * (A_ELEMS + B_ELEMS) * 2)

static void launch_gemm(const __half* A, const __half* B,
                        const float* bias0, const float* bias1,
                        float* C0, float* C1, __half* Asplit,
                        int Kbig, int Kb, int N, int ldc, int relu, int split) {
    dim3 grid(N / 128, (NN + 63) / 64);
    k_mgemm<<<grid, 256, SMEM_BYTES>>>(A, B, bias0, bias1, C0, C1, Asplit,
                                       NN, Kbig, Kb, ldc, relu, split);
}

extern "C" void kernel_launch(void* const* d_in, const int* in_sizes, int n_in,
                              void* d_out, int out_size) {
    const float* v    = (const float*)d_in[0];
    const int* ei     = (const int*)d_in[1];
    const float* W1   = (const float*)d_in[2];
    const float* b1   = (const float*)d_in[3];
    const float* W2   = (const float*)d_in[4];
    const float* b2   = (const float*)d_in[5];
    const float* W3   = (const float*)d_in[6];
    const float* b3   = (const float*)d_in[7];
    const float* Wmu  = (const float*)d_in[8];
    const float* bmu  = (const float*)d_in[9];
    const float* Wstd = (const float*)d_in[10];
    const float* bstd = (const float*)d_in[11];
    float* out = (float*)d_out;

    static bool init_done = false;
    static cudaStream_t s2;
    static cudaEvent_t evFork, evDone, evScan, evZero;
    if (!init_done) {
        cudaFuncSetAttribute(k_mgemm, cudaFuncAttributeMaxDynamicSharedMemorySize, SMEM_BYTES);
        cudaStreamCreateWithFlags(&s2, cudaStreamNonBlocking);
        cudaEventCreateWithFlags(&evFork, cudaEventDisableTiming);
        cudaEventCreateWithFlags(&evDone, cudaEventDisableTiming);
        cudaEventCreateWithFlags(&evScan, cudaEventDisableTiming);
        cudaEventCreateWithFlags(&evZero, cudaEventDisableTiming);
        init_done = true;
    }

    float *deg, *dis, *tx1, *actA, *csr_w;
    int *cnt, *rowptr, *cursor, *csr_src;
    __half *xh, *tx1h, *Abig, *Ah, *B1, *B2, *B3, *Bh;
    cudaGetSymbolAddress((void**)&deg,     g_deg);
    cudaGetSymbolAddress((void**)&dis,     g_dis);
    cudaGetSymbolAddress((void**)&cnt,     g_cnt);
    cudaGetSymbolAddress((void**)&rowptr,  g_rowptr);
    cudaGetSymbolAddress((void**)&cursor,  g_cursor);
    cudaGetSymbolAddress((void**)&csr_src, g_csr_src);
    cudaGetSymbolAddress((void**)&csr_w,   g_csr_w);
    cudaGetSymbolAddress((void**)&tx1,     g_tx1);
    cudaGetSymbolAddress((void**)&actA,    g_actA);
    cudaGetSymbolAddress((void**)&xh,      g_xh);
    cudaGetSymbolAddress((void**)&tx1h,    g_tx1h);
    cudaGetSymbolAddress((void**)&Abig,    g_Abig);
    cudaGetSymbolAddress((void**)&Ah,      g_Ah);
    cudaGetSymbolAddress((void**)&B1,      g_B1);
    cudaGetSymbolAddress((void**)&B2,      g_B2);
    cudaGetSymbolAddress((void**)&B3,      g_B3);
    cudaGetSymbolAddress((void**)&Bh,      g_Bh);

    // fork side stream: weight conversions off the critical path
    cudaEventRecord(evFork, 0);
    cudaStreamWaitEvent(s2, evFork, 0);
    k_wconv<<<(128 * 384 + 255) / 256, 256, 0, s2>>>(W1, B1, 384, 128);
    k_wconv<<<(256 * 384 + 255) / 256, 256, 0, s2>>>(W2, B2, 384, 256);
    k_wconv<<<(512 * 768 + 255) / 256, 256, 0, s2>>>(W3, B3, 768, 512);
    k_wconv<<<(256 * 512 + 255) / 256, 256, 0, s2>>>(Wmu,  Bh, 512, 256);
    k_wconv<<<(256 * 512 + 255) / 256, 256, 0, s2>>>(Wstd, Bh + (size_t)256 * 512, 512, 256);
    cudaEventRecord(evDone, s2);

    // preprocessing (deg/cnt are zero at entry)
    k_counts<<<(NE + 255) / 256, 256>>>(ei, deg, cnt);
    k_scan<<<1, 1024>>>(cnt, rowptr, cursor, deg, dis);
    cudaEventRecord(evScan, 0);
    k_scatter<<<(NE + 255) / 256, 256>>>(ei, dis, cursor, csr_src, csr_w);

    // side stream: re-zero deg/cnt for the NEXT call
    cudaStreamWaitEvent(s2, evScan, 0);
    k_zero2<<<(NN + 255) / 256, 256, 0, s2>>>(deg, cnt, NN);
    cudaEventRecord(evZero, s2);

    const int pgn = (NN + 3) / 4;

    // L1: 2-term props on fp32 v, GEMM -> fp32 actA (L2 props need fp32)
    k_gprop1<<<pgn, 128>>>(rowptr, csr_src, csr_w, v, tx1, Abig);
    k_gprop2<<<pgn, 128>>>(rowptr, csr_src, csr_w, v, tx1, Abig);
    cudaStreamWaitEvent(0, evDone, 0);
    launch_gemm(Abig, B1, b1, b1, actA, actA, nullptr, 768, 384, 128, 128, 1, 128);

    // L2: 2-term props on fp32 actA, GEMM -> fp16 hi xh (epilogue split write)
    k_gprop1<<<pgn, 128>>>(rowptr, csr_src, csr_w, actA, tx1, Abig);
    k_gprop2<<<pgn, 128>>>(rowptr, csr_src, csr_w, actA, tx1, Abig);
    launch_gemm(Abig, B2, b2, b2, nullptr, nullptr, xh, 768, 384, 256, 256, 1, 256);

    // L3: fp16 props (hi-only A rows, stride 768), GEMM -> fp16 hi head-A (Ah)
    k_gprop1h<<<pgn, 128>>>(rowptr, csr_src, csr_w, xh, tx1h, Abig);
    k_gprop2h<<<pgn, 128>>>(rowptr, csr_src, csr_w, xh, tx1h, Abig);
    launch_gemm(Abig, B3, b3, b3, nullptr, nullptr, Ah, 768, 768, 512, 512, 1, 512);

    // fused heads: one N=512 GEMM on Ah (K=512), split mu|std
    launch_gemm(Ah, Bh, bmu, bstd, out, out + (size_t)NN * 256, nullptr,
                512, 512, 512, 256, 0, 256);

    cudaStreamWaitEvent(0, evZero, 0);

    (void)in_sizes; (void)n_in; (void)out_size;
}